// round 2
// baseline (speedup 1.0000x reference)
#include <cuda_runtime.h>
#include <cuda_bf16.h>

#define BK 32768
#define Kk 512

// ---------------- scratch offsets (floats) ----------------
constexpr long long O_XROWS = 0,                          SZ_XROWS = (long long)BK*128;
constexpr long long O_LNB   = O_XROWS + SZ_XROWS,         SZ_LNB   = (long long)BK*128;
constexpr long long O_QKV   = O_LNB + SZ_LNB,             SZ_QKV   = (long long)BK*768;
constexpr long long O_R     = O_QKV + SZ_QKV,             SZ_R     = (long long)BK*512;
constexpr long long O_Y     = O_R + SZ_R,                 SZ_Y     = (long long)BK*128;
constexpr long long O_STATE = O_Y + SZ_Y,                 SZ_STATE = (long long)BK*1536;
constexpr long long O_FUS   = O_STATE + SZ_STATE,         SZ_FUS   = (long long)BK*256;
constexpr long long O_RNN   = O_FUS + SZ_FUS,             SZ_RNN   = (long long)BK*256;
constexpr long long O_GATES = O_RNN + SZ_RNN,             SZ_GATES = (long long)BK*1024;
constexpr long long O_P1    = O_GATES + SZ_GATES,         SZ_P1    = (long long)BK*256;
constexpr long long O_P2    = O_P1 + SZ_P1,               SZ_P2    = (long long)BK*128;
constexpr long long O_G     = O_P2 + SZ_P2,               SZ_G     = 64*256;
constexpr long long O_WT    = O_G + SZ_G,                 SZ_WT    = 8LL*9*128*128;
constexpr long long O_WQKV  = O_WT + SZ_WT,               SZ_WQKV  = 8LL*128*768;
constexpr long long O_WC    = O_WQKV + SZ_WQKV,           SZ_WC    = 8LL*512*128;
constexpr long long O_FUSWT = O_WC + SZ_WC,               SZ_FUSWT = 1024LL*256;
constexpr long long O_RSWT  = O_FUSWT + SZ_FUSWT,         SZ_RSWT  = 1280LL*256;
constexpr long long O_WIHT  = O_RSWT + SZ_RSWT,           SZ_WIHT  = 256LL*1024;
constexpr long long O_WHHT  = O_WIHT + SZ_WIHT,           SZ_WHHT  = 256LL*1024;
constexpr long long O_P1WT  = O_WHHT + SZ_WHHT,           SZ_P1WT  = 1536LL*256;
constexpr long long O_P2WT  = O_P1WT + SZ_P1WT,           SZ_P2WT  = 256LL*128;
constexpr long long O_P2B   = O_P2WT + SZ_P2WT,           SZ_P2B   = 128;
constexpr long long SCRATCH_TOTAL = O_P2B + SZ_P2B;

__device__ __align__(16) float d_scratch[SCRATCH_TOTAL];

// ---------------- generic fp32 GEMM: 64x128 tile ----------------
// C(M,N) = A(M,Kd) @ B(Kd,N) [+ C] [+ bias(col)] [relu]
template<bool ACC, bool RELU>
__global__ void __launch_bounds__(256) gemm_k(
    const float* __restrict__ A, int lda, long long sA,
    const float* __restrict__ Bm, int ldb, long long sB,
    float* __restrict__ C, int ldc, long long sC,
    const float* __restrict__ bias, int Kd)
{
    const int bz = blockIdx.z;
    A  += (long long)bz * sA;
    Bm += (long long)bz * sB;
    C  += (long long)bz * sC;

    const int m0 = blockIdx.x * 64;
    const int n0 = blockIdx.y * 128;
    __shared__ __align__(16) float As[16][64];
    __shared__ __align__(16) float Bs[16][128];
    const int tid = threadIdx.x;
    const int tx = tid & 15, ty = tid >> 4;
    const int arow = tid >> 2, ak = (tid & 3) * 4;
    const int brow = tid >> 5, bn = (tid & 31) * 4;

    float acc[4][8];
#pragma unroll
    for (int i = 0; i < 4; i++)
#pragma unroll
        for (int j = 0; j < 8; j++) acc[i][j] = 0.f;

    const float* Aptr  = A + (long long)(m0 + arow) * lda + ak;
    const float* Bptr0 = Bm + (long long)brow * ldb + n0 + bn;

    for (int kb = 0; kb < Kd; kb += 16) {
        float4 av = *(const float4*)(Aptr + kb);
        As[ak+0][arow] = av.x; As[ak+1][arow] = av.y;
        As[ak+2][arow] = av.z; As[ak+3][arow] = av.w;
        const float* bpg = Bptr0 + (long long)kb * ldb;
        float4 b0 = *(const float4*)(bpg);
        float4 b1 = *(const float4*)(bpg + 8LL * ldb);
        *(float4*)&Bs[brow][bn]   = b0;
        *(float4*)&Bs[brow+8][bn] = b1;
        __syncthreads();
#pragma unroll
        for (int kkk = 0; kkk < 16; kkk++) {
            float4 a  = *(const float4*)&As[kkk][ty*4];
            float4 bx = *(const float4*)&Bs[kkk][tx*8];
            float4 by = *(const float4*)&Bs[kkk][tx*8+4];
            float ar[4] = {a.x, a.y, a.z, a.w};
            float br[8] = {bx.x, bx.y, bx.z, bx.w, by.x, by.y, by.z, by.w};
#pragma unroll
            for (int i = 0; i < 4; i++)
#pragma unroll
                for (int j = 0; j < 8; j++) acc[i][j] = fmaf(ar[i], br[j], acc[i][j]);
        }
        __syncthreads();
    }
#pragma unroll
    for (int i = 0; i < 4; i++) {
        int m = m0 + ty*4 + i;
        float* crow = C + (long long)m * ldc + n0 + tx*8;
        float4 c0, c1;
        if (ACC) { c0 = *(float4*)crow; c1 = *(float4*)(crow + 4); }
        float o[8];
#pragma unroll
        for (int j = 0; j < 8; j++) {
            float v = acc[i][j];
            if (bias) v += bias[n0 + tx*8 + j];
            if (ACC) v += (j < 4 ? (&c0.x)[j] : (&c1.x)[j-4]);
            if (RELU) v = fmaxf(v, 0.f);
            o[j] = v;
        }
        *(float4*)crow     = make_float4(o[0], o[1], o[2], o[3]);
        *(float4*)(crow+4) = make_float4(o[4], o[5], o[6], o[7]);
    }
}

// ---------------- transpose x (B,128,K) -> xrows (B*K,128) ----------------
__global__ void __launch_bounds__(256) xtrans_k(const float* __restrict__ x, float* __restrict__ xr)
{
    __shared__ float t[32][33];
    const int c0 = blockIdx.x * 32, k0 = blockIdx.y * 32, b = blockIdx.z;
    const int tx = threadIdx.x & 31, ty = threadIdx.x >> 5;  // 32x8
#pragma unroll
    for (int i = 0; i < 4; i++)
        t[ty + i*8][tx] = x[(long long)b*65536 + (long long)(c0 + ty + i*8)*Kk + k0 + tx];
    __syncthreads();
#pragma unroll
    for (int i = 0; i < 4; i++)
        xr[((long long)(b*Kk + k0 + ty + i*8))*128 + c0 + tx] = t[tx][ty + i*8];
}

// ---------------- row layernorm: warp per row ----------------
__global__ void __launch_bounds__(256) ln_k(
    const float* __restrict__ in, int lda,
    const float* __restrict__ g, const float* __restrict__ be,
    float* __restrict__ ln)
{
    const int row = blockIdx.x * 8 + (threadIdx.x >> 5);
    const int lane = threadIdx.x & 31;
    const float* p = in + (long long)row * lda;
    float x[4];
#pragma unroll
    for (int q = 0; q < 4; q++) x[q] = p[lane + q*32];
    float s = x[0] + x[1] + x[2] + x[3];
#pragma unroll
    for (int off = 16; off; off >>= 1) s += __shfl_xor_sync(0xffffffffu, s, off);
    float mu = s * (1.f/128.f);
    float v = 0.f;
#pragma unroll
    for (int q = 0; q < 4; q++) { float d = x[q] - mu; v = fmaf(d, d, v); }
#pragma unroll
    for (int off = 16; off; off >>= 1) v += __shfl_xor_sync(0xffffffffu, v, off);
    float inv = rsqrtf(v * (1.f/128.f) + 1e-6f);
    float* o = ln + (long long)row * 128;
#pragma unroll
    for (int q = 0; q < 4; q++) {
        int c = lane + q*32;
        o[c] = (x[q] - mu) * inv * g[c] + be[c];
    }
}

// ---------------- flash attention over packed qkv (BK,768) ----------------
__global__ void __launch_bounds__(256) attn_k(
    const float* __restrict__ qkv, float* __restrict__ r)
{
    const int b = blockIdx.z, h = blockIdx.y, q0 = blockIdx.x * 64;
    __shared__ float qs[64][33];
    __shared__ float ks[32][33];
    __shared__ __align__(16) float vs[32][128];
    __shared__ float ss[64][33];
    __shared__ float sm[64], sl[64], sa[64];
    const int tid = threadIdx.x, tx = tid & 15, ty = tid >> 4;

#pragma unroll
    for (int it = 0; it < 2; it++) {
        int idx = tid*2 + it;
        int row = idx >> 3, c4 = (idx & 7) * 4;
        float4 t = *(const float4*)(qkv + ((long long)(b*Kk + q0 + row))*768 + h*32 + c4);
        qs[row][c4] = t.x; qs[row][c4+1] = t.y; qs[row][c4+2] = t.z; qs[row][c4+3] = t.w;
    }
    if (tid < 64) { sm[tid] = -3.0e38f; sl[tid] = 0.f; }
    float acc[4][8];
#pragma unroll
    for (int i = 0; i < 4; i++)
#pragma unroll
        for (int j = 0; j < 8; j++) acc[i][j] = 0.f;
    const float scale = 0.17677669529663687f; // 1/sqrt(32)

    for (int kc = 0; kc < Kk; kc += 32) {
        __syncthreads();
        {
            int row = tid >> 3, c4 = (tid & 7) * 4;
            float4 t = *(const float4*)(qkv + ((long long)(b*Kk + kc + row))*768 + 128 + h*32 + c4);
            ks[row][c4] = t.x; ks[row][c4+1] = t.y; ks[row][c4+2] = t.z; ks[row][c4+3] = t.w;
        }
#pragma unroll
        for (int it = 0; it < 4; it++) {
            int idx = tid + it*256;
            int row = idx >> 5, c4 = (idx & 31) * 4;
            *(float4*)&vs[row][c4] =
                *(const float4*)(qkv + ((long long)(b*Kk + kc + row))*768 + 256 + h*128 + c4);
        }
        __syncthreads();
        float sacc[4][2] = {{0.f,0.f},{0.f,0.f},{0.f,0.f},{0.f,0.f}};
#pragma unroll
        for (int d = 0; d < 32; d++) {
            float qa[4], ka[2];
#pragma unroll
            for (int i = 0; i < 4; i++) qa[i] = qs[ty*4+i][d];
#pragma unroll
            for (int j = 0; j < 2; j++) ka[j] = ks[tx*2+j][d];
#pragma unroll
            for (int i = 0; i < 4; i++)
#pragma unroll
                for (int j = 0; j < 2; j++) sacc[i][j] = fmaf(qa[i], ka[j], sacc[i][j]);
        }
#pragma unroll
        for (int i = 0; i < 4; i++)
#pragma unroll
            for (int j = 0; j < 2; j++) ss[ty*4+i][tx*2+j] = sacc[i][j] * scale;
        __syncthreads();
        if (tid < 64) {
            float mo = sm[tid];
            float mx = mo;
#pragma unroll
            for (int j = 0; j < 32; j++) mx = fmaxf(mx, ss[tid][j]);
            float a = __expf(mo - mx);
            float s = 0.f;
#pragma unroll
            for (int j = 0; j < 32; j++) { float p = __expf(ss[tid][j] - mx); ss[tid][j] = p; s += p; }
            sl[tid] = sl[tid]*a + s;
            sm[tid] = mx;
            sa[tid] = a;
        }
        __syncthreads();
        float a4[4];
#pragma unroll
        for (int i = 0; i < 4; i++) a4[i] = sa[ty*4+i];
#pragma unroll
        for (int i = 0; i < 4; i++)
#pragma unroll
            for (int j = 0; j < 8; j++) acc[i][j] *= a4[i];
#pragma unroll
        for (int j = 0; j < 32; j++) {
            float p0 = ss[ty*4+0][j], p1 = ss[ty*4+1][j], p2 = ss[ty*4+2][j], p3 = ss[ty*4+3][j];
            float4 v0 = *(const float4*)&vs[j][tx*8];
            float4 v1 = *(const float4*)&vs[j][tx*8+4];
            float vv[8] = {v0.x,v0.y,v0.z,v0.w,v1.x,v1.y,v1.z,v1.w};
#pragma unroll
            for (int c = 0; c < 8; c++) {
                acc[0][c] = fmaf(p0, vv[c], acc[0][c]);
                acc[1][c] = fmaf(p1, vv[c], acc[1][c]);
                acc[2][c] = fmaf(p2, vv[c], acc[2][c]);
                acc[3][c] = fmaf(p3, vv[c], acc[3][c]);
            }
        }
    }
#pragma unroll
    for (int i = 0; i < 4; i++) {
        int row = ty*4 + i;
        float inv = 1.f / sl[row];
        float* rp = r + ((long long)(b*Kk + q0 + row))*512 + h*128 + tx*8;
        *(float4*)rp     = make_float4(acc[i][0]*inv, acc[i][1]*inv, acc[i][2]*inv, acc[i][3]*inv);
        *(float4*)(rp+4) = make_float4(acc[i][4]*inv, acc[i][5]*inv, acc[i][6]*inv, acc[i][7]*inv);
    }
}

// ---------------- dilated circular conv as implicit GEMM + relu + residual into state ----------------
__global__ void __launch_bounds__(256) conv_k(
    const float* __restrict__ y, const float* __restrict__ wt_l,
    const float* __restrict__ cbl, float* __restrict__ state,
    int layer, int dil)
{
    const int tile = blockIdx.x;
    const int b = tile >> 3;
    const int k0 = (tile & 7) * 64;
    const float* yb = y + (long long)b * Kk * 128;
    __shared__ __align__(16) float As[16][64];
    __shared__ __align__(16) float Bs[16][128];
    const int tid = threadIdx.x, tx = tid & 15, ty = tid >> 4;
    const int arow = tid >> 2, ak = (tid & 3) * 4;
    const int brow = tid >> 5, bn = (tid & 31) * 4;
    float acc[4][8];
#pragma unroll
    for (int i = 0; i < 4; i++)
#pragma unroll
        for (int j = 0; j < 8; j++) acc[i][j] = 0.f;

    for (int t = 0; t < 9; t++) {
        int src = (k0 + arow + (t - 4) * dil + Kk) & (Kk - 1);
        const float* yr = yb + (long long)src * 128 + ak;
        const float* wt = wt_l + (long long)t * 128 * 128;
        for (int ic = 0; ic < 128; ic += 16) {
            float4 av = *(const float4*)(yr + ic);
            As[ak+0][arow] = av.x; As[ak+1][arow] = av.y;
            As[ak+2][arow] = av.z; As[ak+3][arow] = av.w;
            const float* bpg = wt + (long long)(ic + brow) * 128 + bn;
            float4 b0 = *(const float4*)bpg;
            float4 b1 = *(const float4*)(bpg + 8*128);
            *(float4*)&Bs[brow][bn]   = b0;
            *(float4*)&Bs[brow+8][bn] = b1;
            __syncthreads();
#pragma unroll
            for (int kkk = 0; kkk < 16; kkk++) {
                float4 a  = *(const float4*)&As[kkk][ty*4];
                float4 bx = *(const float4*)&Bs[kkk][tx*8];
                float4 by = *(const float4*)&Bs[kkk][tx*8+4];
                float ar[4] = {a.x, a.y, a.z, a.w};
                float br[8] = {bx.x, bx.y, bx.z, bx.w, by.x, by.y, by.z, by.w};
#pragma unroll
                for (int i = 0; i < 4; i++)
#pragma unroll
                    for (int j = 0; j < 8; j++) acc[i][j] = fmaf(ar[i], br[j], acc[i][j]);
            }
            __syncthreads();
        }
    }
#pragma unroll
    for (int i = 0; i < 4; i++) {
        long long row = (long long)b*Kk + k0 + ty*4 + i;
        long long sidx = row*1536 + 512 + layer*128 + tx*8;
        float o[8];
#pragma unroll
        for (int j = 0; j < 8; j++) {
            float v = fmaxf(acc[i][j] + cbl[tx*8 + j], 0.f);
            o[j] = v;
        }
        if (layer > 0) {
            float4 r0 = *(float4*)&state[sidx - 128];
            float4 r1 = *(float4*)&state[sidx - 128 + 4];
            o[0]+=r0.x; o[1]+=r0.y; o[2]+=r0.z; o[3]+=r0.w;
            o[4]+=r1.x; o[5]+=r1.y; o[6]+=r1.z; o[7]+=r1.w;
        }
        *(float4*)&state[sidx]   = make_float4(o[0],o[1],o[2],o[3]);
        *(float4*)&state[sidx+4] = make_float4(o[4],o[5],o[6],o[7]);
    }
}

// ---------------- conv weight transpose: cw(l,o,i,t) -> wT(l,t,i,o) ----------------
__global__ void wtrans_k(const float* __restrict__ cw, float* __restrict__ wT)
{
    long long idx = (long long)blockIdx.x * 256 + threadIdx.x;
    if (idx >= 8LL*9*128*128) return;
    int o = (int)(idx & 127); long long r = idx >> 7;
    int i = (int)(r & 127); r >>= 7;
    int t = (int)(r % 9); int l = (int)(r / 9);
    wT[idx] = cw[(((long long)l*128 + o)*128 + i)*9 + t];
}

// ---------------- pack Wq|Wk|Wv -> Wqkv[l][128][768] ----------------
__global__ void qkvpack_k(const float* __restrict__ Wq, const float* __restrict__ Wk,
                          const float* __restrict__ Wv, float* __restrict__ W)
{
    long long idx = (long long)blockIdx.x * 256 + threadIdx.x;
    if (idx >= 8LL*128*768) return;
    int j = (int)(idx % 768); long long r = idx / 768;
    int c = (int)(r & 127); int l = (int)(r >> 7);
    float v;
    if (j < 128)      v = Wq[((long long)l*128 + c)*128 + j];
    else if (j < 256) v = Wk[((long long)l*128 + c)*128 + (j-128)];
    else              v = Wv[((long long)l*128 + c)*512 + (j-256)];
    W[idx] = v;
}

// ---------------- weight transpose: dst[c*ldd + rp] = (rp<R ? src[rp*C + c] : 0) ----------------
__global__ void wtT_k(const float* __restrict__ src, int R, int C, float* __restrict__ dst, int ldd)
{
    long long idx = (long long)blockIdx.x * 256 + threadIdx.x;
    long long tot = (long long)C * ldd;
    if (idx >= tot) return;
    int rp = (int)(idx % ldd);
    int c  = (int)(idx / ldd);
    dst[idx] = (rp < R) ? src[(long long)rp * C + c] : 0.f;
}

__global__ void biaspad_k(const float* __restrict__ b, float* __restrict__ dst)
{
    int j = threadIdx.x;
    dst[j] = (j < 64) ? b[j] : 0.f;
}

// ---------------- max over K + bias -> g (B,256) ----------------
__global__ void __launch_bounds__(256) maxg_k(
    const float* __restrict__ fus, const float* __restrict__ fb, float* __restrict__ g)
{
    const int b = blockIdx.x, f = threadIdx.x;
    const float* p = fus + (long long)b * Kk * 256 + f;
    float mx = -3.0e38f;
    for (int k = 0; k < Kk; k++) mx = fmaxf(mx, p[(long long)k*256]);
    g[b*256 + f] = mx + fb[f];
}

// ---------------- broadcast g into state cols 256:512 ----------------
__global__ void gfill_k(const float* __restrict__ g, float* __restrict__ state)
{
    long long idx = (long long)blockIdx.x * 256 + threadIdx.x; // BK*256
    int f = (int)(idx & 255); long long row = idx >> 8; int b = (int)(row >> 9);
    state[row*1536 + 256 + f] = g[b*256 + f];
}

// ---------------- LSTM elementwise ----------------
__device__ __forceinline__ float sigm(float x) { return 1.f / (1.f + __expf(-x)); }

__global__ void __launch_bounds__(256) lstm_k(
    const float* __restrict__ gates, const float* __restrict__ c0,
    float* __restrict__ state, float* __restrict__ ho, float* __restrict__ co)
{
    long long idx = (long long)blockIdx.x * 256 + threadIdx.x; // BK*256
    int j = (int)(idx & 255); long long row = idx >> 8;
    const float* gr = gates + row * 1024;
    float gi = gr[j], gf = gr[256+j], gg = gr[512+j], go = gr[768+j];
    float c = sigm(gf) * c0[row*256 + j] + sigm(gi) * tanhf(gg);
    float h = sigm(go) * tanhf(c);
    state[row*1536 + j] = h;
    ho[idx] = h;
    co[idx] = c;
}

// ---------------- final p3: (BK,64)->(B,2,K) ----------------
__global__ void __launch_bounds__(256) p3_k(
    const float* __restrict__ p2, const float* __restrict__ w,
    const float* __restrict__ b3, float* __restrict__ out)
{
    const int row = blockIdx.x * 8 + (threadIdx.x >> 5);
    const int lane = threadIdx.x & 31;
    const float* pr = p2 + (long long)row * 128;
    float x0 = pr[lane], x1 = pr[lane + 32];
    float s0 = x0 * w[lane]      + x1 * w[lane + 32];
    float s1 = x0 * w[64 + lane] + x1 * w[96 + lane];
#pragma unroll
    for (int off = 16; off; off >>= 1) {
        s0 += __shfl_xor_sync(0xffffffffu, s0, off);
        s1 += __shfl_xor_sync(0xffffffffu, s1, off);
    }
    if (lane == 0) {
        int b = row >> 9, k = row & 511;
        out[(long long)b*1024 + k]       = s0 + b3[0];
        out[(long long)b*1024 + 512 + k] = s1 + b3[1];
    }
}

// ---------------- launch ----------------
extern "C" void kernel_launch(void* const* d_in, const int* in_sizes, int n_in,
                              void* d_out, int out_size)
{
    const float* x    = (const float*)d_in[0];
    const float* h0   = (const float*)d_in[1];
    const float* c0   = (const float*)d_in[2];
    const float* ln_g = (const float*)d_in[3];
    const float* ln_b = (const float*)d_in[4];
    const float* Wq   = (const float*)d_in[5];
    const float* Wkm  = (const float*)d_in[6];
    const float* Wv   = (const float*)d_in[7];
    const float* Ww   = (const float*)d_in[8];
    const float* Wa   = (const float*)d_in[9];
    const float* cw   = (const float*)d_in[10];
    const float* cb   = (const float*)d_in[11];
    const float* fus_w = (const float*)d_in[12];
    const float* fus_b = (const float*)d_in[13];
    const float* rs_w  = (const float*)d_in[14];
    const float* rs_b  = (const float*)d_in[15];
    const float* W_ih  = (const float*)d_in[16];
    const float* W_hh  = (const float*)d_in[17];
    const float* b_ih  = (const float*)d_in[18];
    const float* b_hh  = (const float*)d_in[19];
    const float* p1_w  = (const float*)d_in[20];
    const float* p1_b  = (const float*)d_in[21];
    const float* p2_w  = (const float*)d_in[22];
    const float* p2_b  = (const float*)d_in[23];
    const float* p3_w  = (const float*)d_in[24];
    const float* p3_b  = (const float*)d_in[25];
    float* out = (float*)d_out;

    void* sp = nullptr;
    cudaGetSymbolAddress(&sp, d_scratch);
    float* S = (float*)sp;
    float* xrows = S + O_XROWS;
    float* lnb   = S + O_LNB;
    float* qkv   = S + O_QKV;
    float* rbuf  = S + O_R;
    float* ybuf  = S + O_Y;
    float* state = S + O_STATE;
    float* fusb  = S + O_FUS;
    float* rnnb  = S + O_RNN;
    float* gates = S + O_GATES;
    float* p1b   = S + O_P1;
    float* p2bf  = S + O_P2;
    float* gbuf  = S + O_G;
    float* wT    = S + O_WT;
    float* Wqkv  = S + O_WQKV;
    float* Wc    = S + O_WC;
    float* fuswt = S + O_FUSWT;
    float* rswt  = S + O_RSWT;
    float* wiht  = S + O_WIHT;
    float* whht  = S + O_WHHT;
    float* p1wt  = S + O_P1WT;
    float* p2wt  = S + O_P2WT;
    float* p2bp  = S + O_P2B;

    // ---- prep ----
    xtrans_k<<<dim3(4,16,64), 256>>>(x, xrows);
    wtrans_k<<<(int)((8LL*9*128*128 + 255)/256), 256>>>(cw, wT);
    qkvpack_k<<<(int)((8LL*128*768 + 255)/256), 256>>>(Wq, Wkm, Wv, Wqkv);
    // Wc[l] = Ww[l] @ Wa_top[l]  (512x128x128, batched over 8 layers)
    gemm_k<false,false><<<dim3(8,1,8), 256>>>(Ww, 128, 65536LL, Wa, 128, 32768LL,
                                              Wc, 128, 65536LL, nullptr, 128);
    wtT_k<<<1024, 256>>>(fus_w, 256, 1024, fuswt, 256);
    wtT_k<<<1280, 256>>>(rs_w, 256, 1280, rswt, 256);
    wtT_k<<<1024, 256>>>(W_ih, 1024, 256, wiht, 1024);
    wtT_k<<<1024, 256>>>(W_hh, 1024, 256, whht, 1024);
    wtT_k<<<1536, 256>>>(p1_w, 256, 1536, p1wt, 256);
    wtT_k<<<128, 256>>>(p2_w, 64, 256, p2wt, 128);
    biaspad_k<<<1, 128>>>(p2_b, p2bp);

    static const int DIL[8] = {1,1,1,1,2,2,4,4};
    for (int l = 0; l < 8; l++) {
        const float* inrows = (l == 0) ? xrows : (state + 512 + (l-1)*128);
        int lda = (l == 0) ? 128 : 1536;
        ln_k<<<BK/8, 256>>>(inrows, lda, ln_g + l*128, ln_b + l*128, lnb);
        // qkv = ln @ Wqkv[l]  (BK x 768 x 128)
        gemm_k<false,false><<<dim3(512,6,1), 256>>>(lnb, 128, 0, Wqkv + (long long)l*128*768, 768, 0,
                                                    qkv, 768, 0, nullptr, 128);
        attn_k<<<dim3(8,4,64), 256>>>(qkv, rbuf);
        // y = r @ Wc[l]
        gemm_k<false,false><<<dim3(512,1,1), 256>>>(rbuf, 512, 0, Wc + (long long)l*65536, 128, 0,
                                                    ybuf, 128, 0, nullptr, 512);
        // y += inrows @ Wa_bot[l]
        gemm_k<true,false><<<dim3(512,1,1), 256>>>(inrows, lda, 0, Wa + (long long)l*32768 + 128*128, 128, 0,
                                                   ybuf, 128, 0, nullptr, 128);
        conv_k<<<512, 256>>>(ybuf, wT + (long long)l*147456, cb + l*128, state, l, DIL[l]);
    }

    // fus = state[512:1536] @ fus_wT  (BK x 256 x 1024)
    gemm_k<false,false><<<dim3(512,2,1), 256>>>(state + 512, 1536, 0, fuswt, 256, 0,
                                                fusb, 256, 0, nullptr, 1024);
    maxg_k<<<64, 256>>>(fusb, fus_b, gbuf);
    gfill_k<<<BK, 256>>>(gbuf, state);
    // rnn_in = state[256:1536] @ rs_wT + rs_b  (BK x 256 x 1280)
    gemm_k<false,false><<<dim3(512,2,1), 256>>>(state + 256, 1536, 0, rswt, 256, 0,
                                                rnnb, 256, 0, rs_b, 1280);
    // gates = rnn_in @ W_ih^T + b_ih
    gemm_k<false,false><<<dim3(512,8,1), 256>>>(rnnb, 256, 0, wiht, 1024, 0,
                                                gates, 1024, 0, b_ih, 256);
    // gates += h0 @ W_hh^T + b_hh
    gemm_k<true,false><<<dim3(512,8,1), 256>>>(h0, 256, 0, whht, 1024, 0,
                                               gates, 1024, 0, b_hh, 256);
    float* ho = out + 65536;
    float* co = out + 65536 + (long long)BK*256;
    lstm_k<<<BK, 256>>>(gates, c0, state, ho, co);
    // p1 = relu(state @ p1_wT + p1_b)  (BK x 256 x 1536)
    gemm_k<false,true><<<dim3(512,2,1), 256>>>(state, 1536, 0, p1wt, 256, 0,
                                               p1b, 256, 0, p1_b, 1536);
    // p2 = relu(p1 @ p2_wT_pad + p2_b_pad)  (BK x 128 x 256)
    gemm_k<false,true><<<dim3(512,1,1), 256>>>(p1b, 256, 0, p2wt, 128, 0,
                                               p2bf, 128, 0, p2bp, 256);
    p3_k<<<BK/8, 256>>>(p2bf, p3_w, p3_b, out);
}

// round 4
// speedup vs baseline: 2.1253x; 2.1253x over previous
#include <cuda_runtime.h>

#define BK 32768
#define Kk 512

// ---------------- scratch offsets (floats) ----------------
constexpr long long O_XROWS = 0,                      SZ_XROWS = (long long)BK*128;
constexpr long long O_LNB   = O_XROWS + SZ_XROWS,     SZ_LNB   = (long long)BK*128;
constexpr long long O_QKV   = O_LNB + SZ_LNB,         SZ_QKV   = (long long)BK*768;
constexpr long long O_R     = O_QKV + SZ_QKV,         SZ_R     = (long long)BK*512;
constexpr long long O_Y     = O_R + SZ_R,             SZ_Y     = (long long)BK*128;
constexpr long long O_STATE = O_Y + SZ_Y,             SZ_STATE = (long long)BK*1536;
constexpr long long O_FUS   = O_STATE + SZ_STATE,     SZ_FUS   = (long long)BK*256;
constexpr long long O_RNN   = O_FUS + SZ_FUS,         SZ_RNN   = (long long)BK*256;
constexpr long long O_GATES = O_RNN + SZ_RNN,         SZ_GATES = (long long)BK*1024;
constexpr long long O_P1    = O_GATES + SZ_GATES,     SZ_P1    = (long long)BK*256;
constexpr long long O_P2    = O_P1 + SZ_P1,           SZ_P2    = (long long)BK*128;
constexpr long long O_G     = O_P2 + SZ_P2,           SZ_G     = 64*256;
constexpr long long O_S     = O_G + SZ_G,             SZ_S     = 256LL*512*512;
constexpr long long O_VT    = O_S + SZ_S,             SZ_VT    = 256LL*128*512;
constexpr long long O_WT    = O_VT + SZ_VT,           SZ_WT    = 8LL*9*128*128;
constexpr long long O_WQKV  = O_WT + SZ_WT,           SZ_WQKV  = 8LL*768*128;
constexpr long long O_WC    = O_WQKV + SZ_WQKV,       SZ_WC    = 8LL*512*128;
constexpr long long O_WCT   = O_WC + SZ_WC,           SZ_WCT   = 8LL*128*512;
constexpr long long O_WAT   = O_WCT + SZ_WCT,         SZ_WAT   = 8LL*128*256;
constexpr long long O_P2N   = O_WAT + SZ_WAT,         SZ_P2N   = 128LL*256;
constexpr long long O_P2B   = O_P2N + SZ_P2N,         SZ_P2B   = 128;
constexpr long long SCRATCH_TOTAL = O_P2B + SZ_P2B;

__device__ __align__(16) float d_scratch[SCRATCH_TOTAL];

// ---------------- bf16 split helpers ----------------
// word layout [row][kp], kp in 0..7 (k pairs); swizzled to avoid bank conflicts
__device__ __forceinline__ int swz(int row, int kp) {
    return row*8 + (kp ^ (((row >> 2) & 1) << 2));
}
// pack (x->low, y->high) as bf16x2; produce hi word and lo (residual) word
__device__ __forceinline__ void split2(float x, float y, unsigned& h, unsigned& l) {
    asm("cvt.rn.bf16x2.f32 %0, %1, %2;" : "=r"(h) : "f"(y), "f"(x));
    float hx = __uint_as_float(h << 16);
    float hy = __uint_as_float(h & 0xffff0000u);
    asm("cvt.rn.bf16x2.f32 %0, %1, %2;" : "=r"(l) : "f"(y - hy), "f"(x - hx));
}
__device__ __forceinline__ void mma16(float* c, const unsigned* a, const unsigned* b) {
    asm volatile(
        "mma.sync.aligned.m16n8k16.row.col.f32.bf16.bf16.f32 "
        "{%0,%1,%2,%3},{%4,%5,%6,%7},{%8,%9},{%0,%1,%2,%3};"
        : "+f"(c[0]), "+f"(c[1]), "+f"(c[2]), "+f"(c[3])
        : "r"(a[0]), "r"(a[1]), "r"(a[2]), "r"(a[3]), "r"(b[0]), "r"(b[1]));
}

// stage one 8-float row segment (hi+lo) into smem
__device__ __forceinline__ void stage8(unsigned* H, unsigned* L, int row, int half,
                                       float4 v0, float4 v1) {
    unsigned h0,l0,h1,l1,h2,l2,h3,l3;
    split2(v0.x, v0.y, h0, l0); split2(v0.z, v0.w, h1, l1);
    split2(v1.x, v1.y, h2, l2); split2(v1.z, v1.w, h3, l3);
    const int kpb = (half*4) ^ (((row >> 2) & 1) << 2);
    *(uint4*)&H[row*8 + kpb] = make_uint4(h0, h1, h2, h3);
    *(uint4*)&L[row*8 + kpb] = make_uint4(l0, l1, l2, l3);
}

__device__ __forceinline__ void tile_compute(
    const unsigned* __restrict__ Ah, const unsigned* __restrict__ Al,
    const unsigned* __restrict__ Bh, const unsigned* __restrict__ Bl,
    float c[4][4][4], int qg, int rg, int wm, int wn)
{
    unsigned ah[4][4], al[4][4], bh[4][2], bl[4][2];
#pragma unroll
    for (int mt = 0; mt < 4; mt++) {
        const int r0 = wm + mt*16 + qg, r1 = r0 + 8;
        ah[mt][0] = Ah[swz(r0, rg)];   ah[mt][1] = Ah[swz(r1, rg)];
        ah[mt][2] = Ah[swz(r0, rg+4)]; ah[mt][3] = Ah[swz(r1, rg+4)];
        al[mt][0] = Al[swz(r0, rg)];   al[mt][1] = Al[swz(r1, rg)];
        al[mt][2] = Al[swz(r0, rg+4)]; al[mt][3] = Al[swz(r1, rg+4)];
    }
#pragma unroll
    for (int nt = 0; nt < 4; nt++) {
        const int col = wn + nt*8 + qg;
        bh[nt][0] = Bh[swz(col, rg)]; bh[nt][1] = Bh[swz(col, rg+4)];
        bl[nt][0] = Bl[swz(col, rg)]; bl[nt][1] = Bl[swz(col, rg+4)];
    }
#pragma unroll
    for (int mt = 0; mt < 4; mt++)
#pragma unroll
        for (int nt = 0; nt < 4; nt++) {
            mma16(c[mt][nt], ah[mt], bh[nt]);
            mma16(c[mt][nt], ah[mt], bl[nt]);
            mma16(c[mt][nt], al[mt], bh[nt]);
        }
}

// ---------------- tensor-core GEMM (bf16x3): 128x128 tile ----------------
// C = A(M,Kd) @ Bn^T  [+C] [+bias(col)] [relu];  B given n-major Bn[N][Kd]
// batch z: hi = z>>zshift, lo = rest; ptr += hi*s + lo*s2
template<bool ACC, bool RELU>
__global__ void __launch_bounds__(256) gemm_tc(
    const float* __restrict__ A, int lda, long long sA, long long sA2,
    const float* __restrict__ B, int ldb, long long sB, long long sB2,
    float* __restrict__ C, int ldc, long long sC, long long sC2,
    const float* __restrict__ bias, int Kd, int zshift)
{
    const int bz = blockIdx.z;
    const int hi = bz >> zshift, lo = bz - (hi << zshift);
    A += hi*sA + lo*sA2;
    B += hi*sB + lo*sB2;
    C += hi*sC + lo*sC2;
    const int m0 = blockIdx.x*128, n0 = blockIdx.y*128;
    __shared__ __align__(16) unsigned Ah[2][1024], Al[2][1024];
    __shared__ __align__(16) unsigned Bh[2][1024], Bl[2][1024];
    const int tid = threadIdx.x;
    const int lane = tid & 31, warp = tid >> 5;
    const int qg = lane >> 2, rg = lane & 3;
    const int wm = (warp & 1)*64, wn = (warp >> 1)*32;

    float c[4][4][4];
#pragma unroll
    for (int i = 0; i < 4; i++)
#pragma unroll
        for (int j = 0; j < 4; j++)
#pragma unroll
            for (int k = 0; k < 4; k++) c[i][j][k] = 0.f;

    const int srow = tid >> 1, half = tid & 1;
    const float* Ap = A + (long long)(m0 + srow)*lda + half*8;
    const float* Bp = B + (long long)(n0 + srow)*ldb + half*8;
    const int nc = Kd >> 4;

    float4 ra0, ra1, rb0, rb1;
    ra0 = *(const float4*)Ap;       ra1 = *(const float4*)(Ap + 4);
    rb0 = *(const float4*)Bp;       rb1 = *(const float4*)(Bp + 4);
    stage8(Ah[0], Al[0], srow, half, ra0, ra1);
    stage8(Bh[0], Bl[0], srow, half, rb0, rb1);
    __syncthreads();

    for (int ch = 0; ch < nc; ch++) {
        const int s = ch & 1;
        if (ch + 1 < nc) {
            const int kb = (ch + 1) << 4;
            ra0 = *(const float4*)(Ap + kb); ra1 = *(const float4*)(Ap + kb + 4);
            rb0 = *(const float4*)(Bp + kb); rb1 = *(const float4*)(Bp + kb + 4);
        }
        tile_compute(Ah[s], Al[s], Bh[s], Bl[s], c, qg, rg, wm, wn);
        if (ch + 1 < nc) {
            const int d = s ^ 1;
            stage8(Ah[d], Al[d], srow, half, ra0, ra1);
            stage8(Bh[d], Bl[d], srow, half, rb0, rb1);
        }
        __syncthreads();
    }

#pragma unroll
    for (int mt = 0; mt < 4; mt++) {
#pragma unroll
        for (int rh = 0; rh < 2; rh++) {
            const int m = m0 + wm + mt*16 + qg + rh*8;
#pragma unroll
            for (int nt = 0; nt < 4; nt++) {
                const int n = n0 + wn + nt*8 + rg*2;
                float vx = c[mt][nt][rh*2], vy = c[mt][nt][rh*2 + 1];
                if (bias) { float2 bb = *(const float2*)(bias + n); vx += bb.x; vy += bb.y; }
                float* cp = C + (long long)m*ldc + n;
                if (ACC) { float2 o = *(float2*)cp; vx += o.x; vy += o.y; }
                if (RELU) { vx = fmaxf(vx, 0.f); vy = fmaxf(vy, 0.f); }
                *(float2*)cp = make_float2(vx, vy);
            }
        }
    }
}

// ---------------- dilated circular conv as implicit TC GEMM (bf16x3) ----------------
__global__ void __launch_bounds__(256) conv_tc(
    const float* __restrict__ y, const float* __restrict__ wtl,
    const float* __restrict__ cbl, float* __restrict__ state,
    int layer, int dil)
{
    const int tile = blockIdx.x;
    const int b = tile >> 2, k0 = (tile & 3) << 7;
    const float* yb = y + (long long)b*Kk*128;
    __shared__ __align__(16) unsigned Ah[2][1024], Al[2][1024];
    __shared__ __align__(16) unsigned Bh[2][1024], Bl[2][1024];
    const int tid = threadIdx.x;
    const int lane = tid & 31, warp = tid >> 5;
    const int qg = lane >> 2, rg = lane & 3;
    const int wm = (warp & 1)*64, wn = (warp >> 1)*32;

    float c[4][4][4];
#pragma unroll
    for (int i = 0; i < 4; i++)
#pragma unroll
        for (int j = 0; j < 4; j++)
#pragma unroll
            for (int k = 0; k < 4; k++) c[i][j][k] = 0.f;

    const int srow = tid >> 1, half = tid & 1;
    float4 ra0, ra1, rb0, rb1;

    // chunk 0: t=0, icb=0
    {
        const int src = (k0 + srow - 4*dil + Kk) & (Kk - 1);
        const float* ap = yb + (long long)src*128 + half*8;
        ra0 = *(const float4*)ap; ra1 = *(const float4*)(ap + 4);
        const float* bp = wtl + (long long)srow*128 + half*8;
        rb0 = *(const float4*)bp; rb1 = *(const float4*)(bp + 4);
    }
    stage8(Ah[0], Al[0], srow, half, ra0, ra1);
    stage8(Bh[0], Bl[0], srow, half, rb0, rb1);
    __syncthreads();

    for (int ch = 0; ch < 72; ch++) {
        const int s = ch & 1;
        if (ch + 1 < 72) {
            const int tn = (ch + 1) / 8, icb = (ch + 1) & 7;
            const int kb = icb << 4;
            const int src = (k0 + srow + (tn - 4)*dil + Kk) & (Kk - 1);
            const float* ap = yb + (long long)src*128 + kb + half*8;
            ra0 = *(const float4*)ap; ra1 = *(const float4*)(ap + 4);
            const float* bp = wtl + (long long)tn*16384 + (long long)srow*128 + kb + half*8;
            rb0 = *(const float4*)bp; rb1 = *(const float4*)(bp + 4);
        }
        tile_compute(Ah[s], Al[s], Bh[s], Bl[s], c, qg, rg, wm, wn);
        if (ch + 1 < 72) {
            const int d = s ^ 1;
            stage8(Ah[d], Al[d], srow, half, ra0, ra1);
            stage8(Bh[d], Bl[d], srow, half, rb0, rb1);
        }
        __syncthreads();
    }

#pragma unroll
    for (int mt = 0; mt < 4; mt++) {
#pragma unroll
        for (int rh = 0; rh < 2; rh++) {
            const int pos = k0 + wm + mt*16 + qg + rh*8;
            const long long row = (long long)b*Kk + pos;
#pragma unroll
            for (int nt = 0; nt < 4; nt++) {
                const int n = wn + nt*8 + rg*2;
                float vx = c[mt][nt][rh*2]   + cbl[n];
                float vy = c[mt][nt][rh*2+1] + cbl[n+1];
                vx = fmaxf(vx, 0.f); vy = fmaxf(vy, 0.f);
                const long long sidx = row*1536 + 512 + (long long)layer*128 + n;
                if (layer > 0) {
                    float2 r = *(float2*)&state[sidx - 128];
                    vx += r.x; vy += r.y;
                }
                *(float2*)&state[sidx] = make_float2(vx, vy);
            }
        }
    }
}

// ---------------- row softmax over 512-wide rows (in place, scaled) ----------------
__global__ void __launch_bounds__(256) softmax_k(float* __restrict__ S)
{
    const long long row = (long long)blockIdx.x*8 + (threadIdx.x >> 5);
    const int lane = threadIdx.x & 31;
    float* p = S + row*512 + lane*16;
    float4 v[4];
#pragma unroll
    for (int i = 0; i < 4; i++) v[i] = *(float4*)(p + i*4);
    float m = -3.0e38f;
#pragma unroll
    for (int i = 0; i < 4; i++)
        m = fmaxf(m, fmaxf(fmaxf(v[i].x, v[i].y), fmaxf(v[i].z, v[i].w)));
#pragma unroll
    for (int off = 16; off; off >>= 1) m = fmaxf(m, __shfl_xor_sync(0xffffffffu, m, off));
    const float sc = 0.17677669529663687f; // 1/sqrt(32)
    float s = 0.f;
#pragma unroll
    for (int i = 0; i < 4; i++) {
        v[i].x = __expf((v[i].x - m)*sc); v[i].y = __expf((v[i].y - m)*sc);
        v[i].z = __expf((v[i].z - m)*sc); v[i].w = __expf((v[i].w - m)*sc);
        s += v[i].x + v[i].y + v[i].z + v[i].w;
    }
#pragma unroll
    for (int off = 16; off; off >>= 1) s += __shfl_xor_sync(0xffffffffu, s, off);
    const float inv = 1.f / s;
#pragma unroll
    for (int i = 0; i < 4; i++) {
        v[i].x *= inv; v[i].y *= inv; v[i].z *= inv; v[i].w *= inv;
        *(float4*)(p + i*4) = v[i];
    }
}

// ---------------- transpose x (B,128,K) -> xrows (B*K,128) ----------------
__global__ void __launch_bounds__(256) xtrans_k(const float* __restrict__ x, float* __restrict__ xr)
{
    __shared__ float t[32][33];
    const int c0 = blockIdx.x*32, k0 = blockIdx.y*32, b = blockIdx.z;
    const int tx = threadIdx.x & 31, ty = threadIdx.x >> 5;
#pragma unroll
    for (int i = 0; i < 4; i++)
        t[ty + i*8][tx] = x[(long long)b*65536 + (long long)(c0 + ty + i*8)*Kk + k0 + tx];
    __syncthreads();
#pragma unroll
    for (int i = 0; i < 4; i++)
        xr[((long long)(b*Kk + k0 + ty + i*8))*128 + c0 + tx] = t[tx][ty + i*8];
}

// ---------------- V transpose: qkv -> vT[bh][c][k] ----------------
__global__ void __launch_bounds__(256) vtrans_k(const float* __restrict__ qkv, float* __restrict__ vT)
{
    __shared__ float t[32][33];
    const int c0 = blockIdx.x*32, k0 = blockIdx.y*32, bh = blockIdx.z;
    const int b = bh >> 2, h = bh & 3;
    const int tx = threadIdx.x & 31, ty = threadIdx.x >> 5;
#pragma unroll
    for (int i = 0; i < 4; i++)
        t[ty + i*8][tx] = qkv[((long long)(b*Kk + k0 + ty + i*8))*768 + 256 + h*128 + c0 + tx];
    __syncthreads();
#pragma unroll
    for (int i = 0; i < 4; i++)
        vT[(long long)bh*65536 + (long long)(c0 + ty + i*8)*512 + k0 + tx] = t[tx][ty + i*8];
}

// ---------------- row layernorm: warp per row ----------------
__global__ void __launch_bounds__(256) ln_k(
    const float* __restrict__ in, int lda,
    const float* __restrict__ g, const float* __restrict__ be,
    float* __restrict__ ln)
{
    const int row = blockIdx.x*8 + (threadIdx.x >> 5);
    const int lane = threadIdx.x & 31;
    const float* p = in + (long long)row*lda;
    float x[4];
#pragma unroll
    for (int q = 0; q < 4; q++) x[q] = p[lane + q*32];
    float s = x[0] + x[1] + x[2] + x[3];
#pragma unroll
    for (int off = 16; off; off >>= 1) s += __shfl_xor_sync(0xffffffffu, s, off);
    const float mu = s * (1.f/128.f);
    float v = 0.f;
#pragma unroll
    for (int q = 0; q < 4; q++) { float d = x[q] - mu; v = fmaf(d, d, v); }
#pragma unroll
    for (int off = 16; off; off >>= 1) v += __shfl_xor_sync(0xffffffffu, v, off);
    const float inv = rsqrtf(v * (1.f/128.f) + 1e-6f);
    float* o = ln + (long long)row*128;
#pragma unroll
    for (int q = 0; q < 4; q++) {
        int c = lane + q*32;
        o[c] = (x[q] - mu)*inv*g[c] + be[c];
    }
}

// ---------------- prep kernels ----------------
// wT[l][t][o][i] = cw[l][o][i][t]   (n-major conv weights)
__global__ void wtrans_k(const float* __restrict__ cw, float* __restrict__ wT)
{
    long long idx = (long long)blockIdx.x*256 + threadIdx.x;
    if (idx >= 8LL*9*128*128) return;
    int i = (int)(idx & 127); long long r = idx >> 7;
    int o = (int)(r & 127); r >>= 7;
    int t = (int)(r % 9); int l = (int)(r / 9);
    wT[idx] = cw[(((long long)l*128 + o)*128 + i)*9 + t];
}

// Wqkv n-major: W[l][j][c], j in 0..767
__global__ void qkvpack_k(const float* __restrict__ Wq, const float* __restrict__ Wkm,
                          const float* __restrict__ Wv, float* __restrict__ W)
{
    long long idx = (long long)blockIdx.x*256 + threadIdx.x;
    if (idx >= 8LL*768*128) return;
    int cc = (int)(idx & 127); long long r = idx >> 7;
    int j = (int)(r % 768); int l = (int)(r / 768);
    float v;
    if (j < 128)      v = Wq[((long long)l*128 + cc)*128 + j];
    else if (j < 256) v = Wkm[((long long)l*128 + cc)*128 + (j - 128)];
    else              v = Wv[((long long)l*128 + cc)*512 + (j - 256)];
    W[idx] = v;
}

// WcT[l][n][m] = Wc[l][m][n]  (n-major Wc: [128][512])
__global__ void wcT_k(const float* __restrict__ Wc, float* __restrict__ WcT)
{
    long long idx = (long long)blockIdx.x*256 + threadIdx.x;
    if (idx >= 8LL*128*512) return;
    int m = (int)(idx & 511); long long r = idx >> 9;
    int n = (int)(r & 127); int l = (int)(r >> 7);
    WcT[idx] = Wc[((long long)l*512 + m)*128 + n];
}

// WaT[l][o][i] = Wa[l][i][o]  (Wa: [l][256][128] -> WaT: [l][128][256])
__global__ void waT_k(const float* __restrict__ Wa, float* __restrict__ WaT)
{
    long long idx = (long long)blockIdx.x*256 + threadIdx.x;
    if (idx >= 8LL*128*256) return;
    int i = (int)(idx & 255); long long r = idx >> 8;
    int o = (int)(r & 127); int l = (int)(r >> 7);
    WaT[idx] = Wa[((long long)l*256 + i)*128 + o];
}

// p2n[n][k]: pad p2_w (64,256) to (128,256) with zeros
__global__ void p2pad_k(const float* __restrict__ w, float* __restrict__ dst)
{
    int idx = blockIdx.x*256 + threadIdx.x; // 128*256
    int k = idx & 255, n = idx >> 8;
    dst[idx] = (n < 64) ? w[n*256 + k] : 0.f;
}

__global__ void biaspad_k(const float* __restrict__ b, float* __restrict__ dst)
{
    int j = threadIdx.x;
    dst[j] = (j < 64) ? b[j] : 0.f;
}

// ---------------- max over K + bias -> g (B,256) ----------------
__global__ void __launch_bounds__(256) maxg_k(
    const float* __restrict__ fus, const float* __restrict__ fb, float* __restrict__ g)
{
    const int b = blockIdx.x, f = threadIdx.x;
    const float* p = fus + (long long)b*Kk*256 + f;
    float mx = -3.0e38f;
    for (int k = 0; k < Kk; k++) mx = fmaxf(mx, p[(long long)k*256]);
    g[b*256 + f] = mx + fb[f];
}

__global__ void gfill_k(const float* __restrict__ g, float* __restrict__ state)
{
    long long idx = (long long)blockIdx.x*256 + threadIdx.x; // BK*256
    int f = (int)(idx & 255); long long row = idx >> 8; int b = (int)(row >> 9);
    state[row*1536 + 256 + f] = g[b*256 + f];
}

// ---------------- LSTM elementwise ----------------
__device__ __forceinline__ float sigm(float x) { return 1.f / (1.f + __expf(-x)); }

__global__ void __launch_bounds__(256) lstm_k(
    const float* __restrict__ gates, const float* __restrict__ c0,
    float* __restrict__ state, float* __restrict__ ho, float* __restrict__ co)
{
    long long idx = (long long)blockIdx.x*256 + threadIdx.x; // BK*256
    int j = (int)(idx & 255); long long row = idx >> 8;
    const float* gr = gates + row*1024;
    float gi = gr[j], gf = gr[256+j], gg = gr[512+j], go = gr[768+j];
    float c = sigm(gf)*c0[row*256 + j] + sigm(gi)*tanhf(gg);
    float h = sigm(go)*tanhf(c);
    state[row*1536 + j] = h;
    ho[idx] = h;
    co[idx] = c;
}

// ---------------- final p3: (BK,128pad)->(B,2,K) ----------------
__global__ void __launch_bounds__(256) p3_k(
    const float* __restrict__ p2, const float* __restrict__ w,
    const float* __restrict__ b3, float* __restrict__ out)
{
    const int row = blockIdx.x*8 + (threadIdx.x >> 5);
    const int lane = threadIdx.x & 31;
    const float* pr = p2 + (long long)row*128;
    float x0 = pr[lane], x1 = pr[lane + 32];
    float s0 = x0*w[lane]      + x1*w[lane + 32];
    float s1 = x0*w[64 + lane] + x1*w[96 + lane];
#pragma unroll
    for (int off = 16; off; off >>= 1) {
        s0 += __shfl_xor_sync(0xffffffffu, s0, off);
        s1 += __shfl_xor_sync(0xffffffffu, s1, off);
    }
    if (lane == 0) {
        int b = row >> 9, k = row & 511;
        out[(long long)b*1024 + k]       = s0 + b3[0];
        out[(long long)b*1024 + 512 + k] = s1 + b3[1];
    }
}

// ---------------- launch ----------------
extern "C" void kernel_launch(void* const* d_in, const int* in_sizes, int n_in,
                              void* d_out, int out_size)
{
    const float* x    = (const float*)d_in[0];
    const float* h0   = (const float*)d_in[1];
    const float* c0   = (const float*)d_in[2];
    const float* ln_g = (const float*)d_in[3];
    const float* ln_b = (const float*)d_in[4];
    const float* Wq   = (const float*)d_in[5];
    const float* Wkm  = (const float*)d_in[6];
    const float* Wv   = (const float*)d_in[7];
    const float* Ww   = (const float*)d_in[8];
    const float* Wa   = (const float*)d_in[9];
    const float* cw   = (const float*)d_in[10];
    const float* cb   = (const float*)d_in[11];
    const float* fus_w = (const float*)d_in[12];
    const float* fus_b = (const float*)d_in[13];
    const float* rs_w  = (const float*)d_in[14];
    const float* rs_b  = (const float*)d_in[15];
    const float* W_ih  = (const float*)d_in[16];
    const float* W_hh  = (const float*)d_in[17];
    const float* b_ih  = (const float*)d_in[18];
    const float* b_hh  = (const float*)d_in[19];
    const float* p1_w  = (const float*)d_in[20];
    const float* p1_b  = (const float*)d_in[21];
    const float* p2_w  = (const float*)d_in[22];
    const float* p2_b  = (const float*)d_in[23];
    const float* p3_w  = (const float*)d_in[24];
    const float* p3_b  = (const float*)d_in[25];
    float* out = (float*)d_out;

    void* sp = nullptr;
    cudaGetSymbolAddress(&sp, d_scratch);
    float* S = (float*)sp;
    float* xrows = S + O_XROWS;
    float* lnb   = S + O_LNB;
    float* qkv   = S + O_QKV;
    float* rbuf  = S + O_R;
    float* ybuf  = S + O_Y;
    float* state = S + O_STATE;
    float* fusb  = S + O_FUS;
    float* rnnb  = S + O_RNN;
    float* gates = S + O_GATES;
    float* p1b   = S + O_P1;
    float* p2bf  = S + O_P2;
    float* gbuf  = S + O_G;
    float* Sbuf  = S + O_S;
    float* vT    = S + O_VT;
    float* wT    = S + O_WT;
    float* Wqkv  = S + O_WQKV;
    float* Wc    = S + O_WC;
    float* WcT   = S + O_WCT;
    float* WaT   = S + O_WAT;
    float* p2n   = S + O_P2N;
    float* p2bp  = S + O_P2B;

    // ---- prep ----
    xtrans_k<<<dim3(4,16,64), 256>>>(x, xrows);
    wtrans_k<<<(int)((8LL*9*128*128 + 255)/256), 256>>>(cw, wT);
    qkvpack_k<<<(int)((8LL*768*128 + 255)/256), 256>>>(Wq, Wkm, Wv, Wqkv);
    waT_k<<<(int)((8LL*128*256 + 255)/256), 256>>>(Wa, WaT);
    // Wc[l] = Ww[l](512x128) @ Wa_top[l]; B n-major = WaT rows (k=first 128 cols)
    gemm_tc<false,false><<<dim3(4,1,8), 256>>>(
        Ww, 128, 65536, 0,  WaT, 256, 32768, 0,  Wc, 128, 65536, 0, nullptr, 128, 0);
    wcT_k<<<(int)((8LL*128*512 + 255)/256), 256>>>(Wc, WcT);
    p2pad_k<<<128, 256>>>(p2_w, p2n);
    biaspad_k<<<1, 128>>>(p2_b, p2bp);

    static const int DIL[8] = {1,1,1,1,2,2,4,4};
    for (int l = 0; l < 8; l++) {
        const float* inrows = (l == 0) ? xrows : (state + 512 + (l-1)*128);
        int lda = (l == 0) ? 128 : 1536;
        ln_k<<<BK/8, 256>>>(inrows, lda, ln_g + l*128, ln_b + l*128, lnb);
        // qkv = ln @ Wqkv[l]
        gemm_tc<false,false><<<dim3(256,6,1), 256>>>(
            lnb, 128, 0, 0,  Wqkv + (long long)l*98304, 128, 0, 0,
            qkv, 768, 0, 0, nullptr, 128, 0);
        vtrans_k<<<dim3(4,16,256), 256>>>(qkv, vT);
        // S = Q @ K^T, batched over (b,h):  z = b*4+h
        gemm_tc<false,false><<<dim3(4,4,256), 256>>>(
            qkv, 768, 393216, 32,  qkv + 128, 768, 393216, 32,
            Sbuf, 512, 1048576, 262144, nullptr, 32, 2);
        softmax_k<<<16384, 256>>>(Sbuf);
        // O = P @ V  (B n-major = vT[bh])
        gemm_tc<false,false><<<dim3(4,1,256), 256>>>(
            Sbuf, 512, 1048576, 262144,  vT, 512, 262144, 65536,
            rbuf, 512, 262144, 128, nullptr, 512, 2);
        // y = r @ Wc[l]  (WcT n-major)
        gemm_tc<false,false><<<dim3(256,1,1), 256>>>(
            rbuf, 512, 0, 0,  WcT + (long long)l*65536, 512, 0, 0,
            ybuf, 128, 0, 0, nullptr, 512, 0);
        // y += inrows @ Wa_bot[l]  (B n-major = WaT, k offset 128)
        gemm_tc<true,false><<<dim3(256,1,1), 256>>>(
            inrows, lda, 0, 0,  WaT + (long long)l*32768 + 128, 256, 0, 0,
            ybuf, 128, 0, 0, nullptr, 128, 0);
        conv_tc<<<256, 256>>>(ybuf, wT + (long long)l*147456, cb + l*128, state, l, DIL[l]);
    }

    // fus = state[512:1536] @ fus_w^T (n-major native)
    gemm_tc<false,false><<<dim3(256,2,1), 256>>>(
        state + 512, 1536, 0, 0,  fus_w, 1024, 0, 0,
        fusb, 256, 0, 0, nullptr, 1024, 0);
    maxg_k<<<64, 256>>>(fusb, fus_b, gbuf);
    gfill_k<<<BK, 256>>>(gbuf, state);
    // rnn_in = state[256:1536] @ rs_w^T + rs_b
    gemm_tc<false,false><<<dim3(256,2,1), 256>>>(
        state + 256, 1536, 0, 0,  rs_w, 1280, 0, 0,
        rnnb, 256, 0, 0, rs_b, 1280, 0);
    // gates = rnn_in @ W_ih^T + b_ih
    gemm_tc<false,false><<<dim3(256,8,1), 256>>>(
        rnnb, 256, 0, 0,  W_ih, 256, 0, 0,
        gates, 1024, 0, 0, b_ih, 256, 0);
    // gates += h0 @ W_hh^T + b_hh
    gemm_tc<true,false><<<dim3(256,8,1), 256>>>(
        h0, 256, 0, 0,  W_hh, 256, 0, 0,
        gates, 1024, 0, 0, b_hh, 256, 0);
    float* ho = out + 65536;
    float* co = out + 65536 + (long long)BK*256;
    lstm_k<<<BK, 256>>>(gates, c0, state, ho, co);
    // p1 = relu(state @ p1_w^T + p1_b)
    gemm_tc<false,true><<<dim3(256,2,1), 256>>>(
        state, 1536, 0, 0,  p1_w, 1536, 0, 0,
        p1b, 256, 0, 0, p1_b, 1536, 0);
    // p2 = relu(p1 @ p2n^T + p2_b_pad)
    gemm_tc<false,true><<<dim3(256,1,1), 256>>>(
        p1b, 256, 0, 0,  p2n, 256, 0, 0,
        p2bf, 128, 0, 0, p2bp, 256, 0);
    p3_k<<<BK/8, 256>>>(p2bf, p3_w, p3_b, out);
}

// round 5
// speedup vs baseline: 2.5861x; 1.2168x over previous
#include <cuda_runtime.h>

#define BK 32768
#define Kk 512

// ---------------- scratch offsets (floats) ----------------
constexpr long long O_XROWS = 0,                      SZ_XROWS = (long long)BK*128;
constexpr long long O_LNB   = O_XROWS + SZ_XROWS,     SZ_LNB   = (long long)BK*128;
constexpr long long O_QKV   = O_LNB + SZ_LNB,         SZ_QKV   = (long long)BK*768;
constexpr long long O_R     = O_QKV + SZ_QKV,         SZ_R     = (long long)BK*512;
constexpr long long O_Y     = O_R + SZ_R,             SZ_Y     = (long long)BK*128;
constexpr long long O_STATE = O_Y + SZ_Y,             SZ_STATE = (long long)BK*1536;
constexpr long long O_FUS   = O_STATE + SZ_STATE,     SZ_FUS   = (long long)BK*256;
constexpr long long O_RNN   = O_FUS + SZ_FUS,         SZ_RNN   = (long long)BK*256;
constexpr long long O_GATES = O_RNN + SZ_RNN,         SZ_GATES = (long long)BK*1024;
constexpr long long O_P1    = O_GATES + SZ_GATES,     SZ_P1    = (long long)BK*256;
constexpr long long O_P2    = O_P1 + SZ_P1,           SZ_P2    = (long long)BK*128;
constexpr long long O_G     = O_P2 + SZ_P2,           SZ_G     = 64*256;
constexpr long long O_VT    = O_G + SZ_G,             SZ_VT    = 256LL*128*512;
constexpr long long O_WT    = O_VT + SZ_VT,           SZ_WT    = 8LL*9*128*128;
constexpr long long O_WQKV  = O_WT + SZ_WT,           SZ_WQKV  = 8LL*768*128;
constexpr long long O_WC    = O_WQKV + SZ_WQKV,       SZ_WC    = 8LL*512*128;
constexpr long long O_WCT   = O_WC + SZ_WC,           SZ_WCT   = 8LL*128*512;
constexpr long long O_WAT   = O_WCT + SZ_WCT,         SZ_WAT   = 8LL*128*256;
constexpr long long O_P2N   = O_WAT + SZ_WAT,         SZ_P2N   = 128LL*256;
constexpr long long O_P2B   = O_P2N + SZ_P2N,         SZ_P2B   = 128;
constexpr long long SCRATCH_TOTAL = O_P2B + SZ_P2B;

__device__ __align__(16) float d_scratch[SCRATCH_TOTAL];

// ---------------- bf16 split helpers ----------------
// word layout [row][kp], kp in 0..7 (k pairs); swizzled to avoid bank conflicts
__device__ __forceinline__ int swz(int row, int kp) {
    return row*8 + (kp ^ (((row >> 2) & 1) << 2));
}
// pack (x->low, y->high) as bf16x2; produce hi word and lo (residual) word
__device__ __forceinline__ void split2(float x, float y, unsigned& h, unsigned& l) {
    asm("cvt.rn.bf16x2.f32 %0, %1, %2;" : "=r"(h) : "f"(y), "f"(x));
    float hx = __uint_as_float(h << 16);
    float hy = __uint_as_float(h & 0xffff0000u);
    asm("cvt.rn.bf16x2.f32 %0, %1, %2;" : "=r"(l) : "f"(y - hy), "f"(x - hx));
}
__device__ __forceinline__ void mma16(float* c, const unsigned* a, const unsigned* b) {
    asm volatile(
        "mma.sync.aligned.m16n8k16.row.col.f32.bf16.bf16.f32 "
        "{%0,%1,%2,%3},{%4,%5,%6,%7},{%8,%9},{%0,%1,%2,%3};"
        : "+f"(c[0]), "+f"(c[1]), "+f"(c[2]), "+f"(c[3])
        : "r"(a[0]), "r"(a[1]), "r"(a[2]), "r"(a[3]), "r"(b[0]), "r"(b[1]));
}

// stage one 8-float row segment (hi+lo) into smem
__device__ __forceinline__ void stage8(unsigned* H, unsigned* L, int row, int half,
                                       float4 v0, float4 v1) {
    unsigned h0,l0,h1,l1,h2,l2,h3,l3;
    split2(v0.x, v0.y, h0, l0); split2(v0.z, v0.w, h1, l1);
    split2(v1.x, v1.y, h2, l2); split2(v1.z, v1.w, h3, l3);
    const int kpb = (half*4) ^ (((row >> 2) & 1) << 2);
    *(uint4*)&H[row*8 + kpb] = make_uint4(h0, h1, h2, h3);
    *(uint4*)&L[row*8 + kpb] = make_uint4(l0, l1, l2, l3);
}

__device__ __forceinline__ void tile_compute(
    const unsigned* __restrict__ Ah, const unsigned* __restrict__ Al,
    const unsigned* __restrict__ Bh, const unsigned* __restrict__ Bl,
    float c[4][4][4], int qg, int rg, int wm, int wn)
{
    unsigned ah[4][4], al[4][4], bh[4][2], bl[4][2];
#pragma unroll
    for (int mt = 0; mt < 4; mt++) {
        const int r0 = wm + mt*16 + qg, r1 = r0 + 8;
        ah[mt][0] = Ah[swz(r0, rg)];   ah[mt][1] = Ah[swz(r1, rg)];
        ah[mt][2] = Ah[swz(r0, rg+4)]; ah[mt][3] = Ah[swz(r1, rg+4)];
        al[mt][0] = Al[swz(r0, rg)];   al[mt][1] = Al[swz(r1, rg)];
        al[mt][2] = Al[swz(r0, rg+4)]; al[mt][3] = Al[swz(r1, rg+4)];
    }
#pragma unroll
    for (int nt = 0; nt < 4; nt++) {
        const int col = wn + nt*8 + qg;
        bh[nt][0] = Bh[swz(col, rg)]; bh[nt][1] = Bh[swz(col, rg+4)];
        bl[nt][0] = Bl[swz(col, rg)]; bl[nt][1] = Bl[swz(col, rg+4)];
    }
#pragma unroll
    for (int mt = 0; mt < 4; mt++)
#pragma unroll
        for (int nt = 0; nt < 4; nt++) {
            mma16(c[mt][nt], ah[mt], bh[nt]);
            mma16(c[mt][nt], ah[mt], bl[nt]);
            mma16(c[mt][nt], al[mt], bh[nt]);
        }
}

// ---------------- tensor-core GEMM (bf16x3): 128x128 tile ----------------
// C = A(M,Kd) @ Bn^T  [+C] [+bias(col)] [relu];  B given n-major Bn[N][Kd]
template<bool ACC, bool RELU>
__global__ void __launch_bounds__(256) gemm_tc(
    const float* __restrict__ A, int lda, long long sA, long long sA2,
    const float* __restrict__ B, int ldb, long long sB, long long sB2,
    float* __restrict__ C, int ldc, long long sC, long long sC2,
    const float* __restrict__ bias, int Kd, int zshift)
{
    const int bz = blockIdx.z;
    const int hi = bz >> zshift, lo = bz - (hi << zshift);
    A += hi*sA + lo*sA2;
    B += hi*sB + lo*sB2;
    C += hi*sC + lo*sC2;
    const int m0 = blockIdx.x*128, n0 = blockIdx.y*128;
    __shared__ __align__(16) unsigned Ah[2][1024], Al[2][1024];
    __shared__ __align__(16) unsigned Bh[2][1024], Bl[2][1024];
    const int tid = threadIdx.x;
    const int lane = tid & 31, warp = tid >> 5;
    const int qg = lane >> 2, rg = lane & 3;
    const int wm = (warp & 1)*64, wn = (warp >> 1)*32;

    float c[4][4][4];
#pragma unroll
    for (int i = 0; i < 4; i++)
#pragma unroll
        for (int j = 0; j < 4; j++)
#pragma unroll
            for (int k = 0; k < 4; k++) c[i][j][k] = 0.f;

    const int srow = tid >> 1, half = tid & 1;
    const float* Ap = A + (long long)(m0 + srow)*lda + half*8;
    const float* Bp = B + (long long)(n0 + srow)*ldb + half*8;
    const int nc = Kd >> 4;

    float4 ra0, ra1, rb0, rb1;
    ra0 = *(const float4*)Ap;       ra1 = *(const float4*)(Ap + 4);
    rb0 = *(const float4*)Bp;       rb1 = *(const float4*)(Bp + 4);
    stage8(Ah[0], Al[0], srow, half, ra0, ra1);
    stage8(Bh[0], Bl[0], srow, half, rb0, rb1);
    __syncthreads();

    for (int ch = 0; ch < nc; ch++) {
        const int s = ch & 1;
        if (ch + 1 < nc) {
            const int kb = (ch + 1) << 4;
            ra0 = *(const float4*)(Ap + kb); ra1 = *(const float4*)(Ap + kb + 4);
            rb0 = *(const float4*)(Bp + kb); rb1 = *(const float4*)(Bp + kb + 4);
        }
        tile_compute(Ah[s], Al[s], Bh[s], Bl[s], c, qg, rg, wm, wn);
        if (ch + 1 < nc) {
            const int d = s ^ 1;
            stage8(Ah[d], Al[d], srow, half, ra0, ra1);
            stage8(Bh[d], Bl[d], srow, half, rb0, rb1);
        }
        __syncthreads();
    }

#pragma unroll
    for (int mt = 0; mt < 4; mt++) {
#pragma unroll
        for (int rh = 0; rh < 2; rh++) {
            const int m = m0 + wm + mt*16 + qg + rh*8;
#pragma unroll
            for (int nt = 0; nt < 4; nt++) {
                const int n = n0 + wn + nt*8 + rg*2;
                float vx = c[mt][nt][rh*2], vy = c[mt][nt][rh*2 + 1];
                if (bias) { float2 bb = *(const float2*)(bias + n); vx += bb.x; vy += bb.y; }
                float* cp = C + (long long)m*ldc + n;
                if (ACC) { float2 o = *(float2*)cp; vx += o.x; vy += o.y; }
                if (RELU) { vx = fmaxf(vx, 0.f); vy = fmaxf(vy, 0.f); }
                *(float2*)cp = make_float2(vx, vy);
            }
        }
    }
}

// ---------------- fused flash attention (bf16x3 mma, online softmax) ----------------
// grid (4 qtiles, 4 heads, 64 b), 256 threads; dynamic smem 169472 B
constexpr int FLASH_SMEM = 169472;
__global__ void __launch_bounds__(256) flash_k(
    const float* __restrict__ qkv, const float* __restrict__ vT, float* __restrict__ r)
{
    extern __shared__ __align__(16) unsigned sm_[];
    unsigned* Qh = sm_;
    unsigned* Ql = Qh + 2048;
    unsigned* Kh = Ql + 2048;
    unsigned* Kl = Kh + 2048;
    unsigned* Vh = Kl + 2048;
    unsigned* Vl = Vh + 8192;
    unsigned* Ph = Vl + 8192;
    unsigned* Pl = Ph + 8192;
    float* rowM = (float*)(Pl + 8192);
    float* rowL = rowM + 128;
    float* rowA = rowL + 128;
    float* redM = rowA + 128;   // [4][128]
    float* redS = redM + 512;   // [4][128]

    const int b = blockIdx.z, h = blockIdx.y, q0 = blockIdx.x*128;
    const int tid = threadIdx.x, lane = tid & 31, warp = tid >> 5;
    const int qg = lane >> 2, rg = lane & 3;
    const int wm = (warp & 1)*64, wn = (warp >> 1)*32;
    const int srow = tid >> 1, half = tid & 1;
    const int bh = b*4 + h;

    {   // Q tile: 128 rows x 32 k (two 16-k sub-chunks)
        const float* qp = qkv + ((long long)(b*Kk + q0 + srow))*768 + h*32 + half*8;
        float4 a0 = *(const float4*)qp, a1 = *(const float4*)(qp + 4);
        stage8(Qh, Ql, srow, half, a0, a1);
        a0 = *(const float4*)(qp + 16); a1 = *(const float4*)(qp + 20);
        stage8(Qh + 1024, Ql + 1024, srow, half, a0, a1);
    }
    if (tid < 128) { rowM[tid] = -3.0e38f; rowL[tid] = 0.f; }

    float co[4][4][4];
#pragma unroll
    for (int i = 0; i < 4; i++)
#pragma unroll
        for (int j = 0; j < 4; j++)
#pragma unroll
            for (int k = 0; k < 4; k++) co[i][j][k] = 0.f;

    const float sc = 0.17677669529663687f; // 1/sqrt(32)

    for (int kc = 0; kc < 4; kc++) {
        {   // K chunk: 128 keys x 32 k
            const float* kp_ = qkv + ((long long)(b*Kk + kc*128 + srow))*768 + 128 + h*32 + half*8;
            float4 a0 = *(const float4*)kp_, a1 = *(const float4*)(kp_ + 4);
            stage8(Kh, Kl, srow, half, a0, a1);
            a0 = *(const float4*)(kp_ + 16); a1 = *(const float4*)(kp_ + 20);
            stage8(Kh + 1024, Kl + 1024, srow, half, a0, a1);
        }
        {   // V chunk: 128 channels (rows) x 128 keys (k), 8 sub-chunks
            const float* vp = vT + (long long)bh*65536 + (long long)srow*512 + kc*128 + half*8;
#pragma unroll
            for (int j = 0; j < 8; j++) {
                float4 v0 = *(const float4*)(vp + j*16), v1 = *(const float4*)(vp + j*16 + 4);
                stage8(Vh + j*1024, Vl + j*1024, srow, half, v0, v1);
            }
        }
        __syncthreads();

        float cs[4][4][4];
#pragma unroll
        for (int i = 0; i < 4; i++)
#pragma unroll
            for (int j = 0; j < 4; j++)
#pragma unroll
                for (int k = 0; k < 4; k++) cs[i][j][k] = 0.f;
        tile_compute(Qh, Ql, Kh, Kl, cs, qg, rg, wm, wn);
        tile_compute(Qh + 1024, Ql + 1024, Kh + 1024, Kl + 1024, cs, qg, rg, wm, wn);

        // warp-level row max (over this warp's 32 cols)
#pragma unroll
        for (int mt = 0; mt < 4; mt++)
#pragma unroll
            for (int rh = 0; rh < 2; rh++) {
                float m = -3.0e38f;
#pragma unroll
                for (int nt = 0; nt < 4; nt++)
                    m = fmaxf(m, fmaxf(cs[mt][nt][rh*2], cs[mt][nt][rh*2+1]));
                m *= sc;
                m = fmaxf(m, __shfl_xor_sync(0xffffffffu, m, 1));
                m = fmaxf(m, __shfl_xor_sync(0xffffffffu, m, 2));
                if (rg == 0) redM[(warp>>1)*128 + wm + mt*16 + qg + rh*8] = m;
            }
        __syncthreads();

        // P = exp(s*sc - newM); partial row sums; write P hi/lo to smem
#pragma unroll
        for (int mt = 0; mt < 4; mt++)
#pragma unroll
            for (int rh = 0; rh < 2; rh++) {
                const int row = wm + mt*16 + qg + rh*8;
                const float mOld = rowM[row];
                const float nm = fmaxf(fmaxf(fmaxf(redM[row], redM[128+row]),
                                       fmaxf(redM[256+row], redM[384+row])), mOld);
                float s = 0.f;
#pragma unroll
                for (int nt = 0; nt < 4; nt++) {
                    float p0 = __expf(cs[mt][nt][rh*2]*sc   - nm);
                    float p1 = __expf(cs[mt][nt][rh*2+1]*sc - nm);
                    s += p0 + p1;
                    const int col = wn + nt*8 + rg*2;
                    unsigned hw, lw; split2(p0, p1, hw, lw);
                    const int ci = col >> 4, kp = (col >> 1) & 7;
                    Ph[ci*1024 + swz(row, kp)] = hw;
                    Pl[ci*1024 + swz(row, kp)] = lw;
                }
                s += __shfl_xor_sync(0xffffffffu, s, 1);
                s += __shfl_xor_sync(0xffffffffu, s, 2);
                if (rg == 0) redS[(warp>>1)*128 + row] = s;
            }
        __syncthreads();

        if (tid < 128) {
            const int row = tid;
            const float mOld = rowM[row];
            const float nm = fmaxf(fmaxf(fmaxf(redM[row], redM[128+row]),
                                   fmaxf(redM[256+row], redM[384+row])), mOld);
            const float a = __expf(mOld - nm);
            rowL[row] = rowL[row]*a + redS[row] + redS[128+row] + redS[256+row] + redS[384+row];
            rowM[row] = nm;
            rowA[row] = a;
        }
        __syncthreads();

        // rescale O acc, then accumulate P @ V
#pragma unroll
        for (int mt = 0; mt < 4; mt++) {
            const float a0_ = rowA[wm + mt*16 + qg];
            const float a1_ = rowA[wm + mt*16 + qg + 8];
#pragma unroll
            for (int nt = 0; nt < 4; nt++) {
                co[mt][nt][0] *= a0_; co[mt][nt][1] *= a0_;
                co[mt][nt][2] *= a1_; co[mt][nt][3] *= a1_;
            }
        }
#pragma unroll
        for (int j = 0; j < 8; j++)
            tile_compute(Ph + j*1024, Pl + j*1024, Vh + j*1024, Vl + j*1024, co, qg, rg, wm, wn);
        __syncthreads();
    }

    // normalize and write out
#pragma unroll
    for (int mt = 0; mt < 4; mt++)
#pragma unroll
        for (int rh = 0; rh < 2; rh++) {
            const int row = wm + mt*16 + qg + rh*8;
            const float inv = 1.f / rowL[row];
            float* rp = r + ((long long)(b*Kk + q0 + row))*512 + h*128;
#pragma unroll
            for (int nt = 0; nt < 4; nt++) {
                const int col = wn + nt*8 + rg*2;
                *(float2*)(rp + col) = make_float2(co[mt][nt][rh*2]*inv, co[mt][nt][rh*2+1]*inv);
            }
        }
}

// ---------------- dilated circular conv as implicit TC GEMM (bf16x3) ----------------
__global__ void __launch_bounds__(256) conv_tc(
    const float* __restrict__ y, const float* __restrict__ wtl,
    const float* __restrict__ cbl, float* __restrict__ state,
    int layer, int dil)
{
    const int tile = blockIdx.x;
    const int b = tile >> 2, k0 = (tile & 3) << 7;
    const float* yb = y + (long long)b*Kk*128;
    __shared__ __align__(16) unsigned Ah[2][1024], Al[2][1024];
    __shared__ __align__(16) unsigned Bh[2][1024], Bl[2][1024];
    const int tid = threadIdx.x;
    const int lane = tid & 31, warp = tid >> 5;
    const int qg = lane >> 2, rg = lane & 3;
    const int wm = (warp & 1)*64, wn = (warp >> 1)*32;

    float c[4][4][4];
#pragma unroll
    for (int i = 0; i < 4; i++)
#pragma unroll
        for (int j = 0; j < 4; j++)
#pragma unroll
            for (int k = 0; k < 4; k++) c[i][j][k] = 0.f;

    const int srow = tid >> 1, half = tid & 1;
    float4 ra0, ra1, rb0, rb1;

    {
        const int src = (k0 + srow - 4*dil + Kk) & (Kk - 1);
        const float* ap = yb + (long long)src*128 + half*8;
        ra0 = *(const float4*)ap; ra1 = *(const float4*)(ap + 4);
        const float* bp = wtl + (long long)srow*128 + half*8;
        rb0 = *(const float4*)bp; rb1 = *(const float4*)(bp + 4);
    }
    stage8(Ah[0], Al[0], srow, half, ra0, ra1);
    stage8(Bh[0], Bl[0], srow, half, rb0, rb1);
    __syncthreads();

    for (int ch = 0; ch < 72; ch++) {
        const int s = ch & 1;
        if (ch + 1 < 72) {
            const int tn = (ch + 1) / 8, icb = (ch + 1) & 7;
            const int kb = icb << 4;
            const int src = (k0 + srow + (tn - 4)*dil + Kk) & (Kk - 1);
            const float* ap = yb + (long long)src*128 + kb + half*8;
            ra0 = *(const float4*)ap; ra1 = *(const float4*)(ap + 4);
            const float* bp = wtl + (long long)tn*16384 + (long long)srow*128 + kb + half*8;
            rb0 = *(const float4*)bp; rb1 = *(const float4*)(bp + 4);
        }
        tile_compute(Ah[s], Al[s], Bh[s], Bl[s], c, qg, rg, wm, wn);
        if (ch + 1 < 72) {
            const int d = s ^ 1;
            stage8(Ah[d], Al[d], srow, half, ra0, ra1);
            stage8(Bh[d], Bl[d], srow, half, rb0, rb1);
        }
        __syncthreads();
    }

#pragma unroll
    for (int mt = 0; mt < 4; mt++) {
#pragma unroll
        for (int rh = 0; rh < 2; rh++) {
            const int pos = k0 + wm + mt*16 + qg + rh*8;
            const long long row = (long long)b*Kk + pos;
#pragma unroll
            for (int nt = 0; nt < 4; nt++) {
                const int n = wn + nt*8 + rg*2;
                float vx = c[mt][nt][rh*2]   + cbl[n];
                float vy = c[mt][nt][rh*2+1] + cbl[n+1];
                vx = fmaxf(vx, 0.f); vy = fmaxf(vy, 0.f);
                const long long sidx = row*1536 + 512 + (long long)layer*128 + n;
                if (layer > 0) {
                    float2 r = *(float2*)&state[sidx - 128];
                    vx += r.x; vy += r.y;
                }
                *(float2*)&state[sidx] = make_float2(vx, vy);
            }
        }
    }
}

// ---------------- transpose x (B,128,K) -> xrows (B*K,128) ----------------
__global__ void __launch_bounds__(256) xtrans_k(const float* __restrict__ x, float* __restrict__ xr)
{
    __shared__ float t[32][33];
    const int c0 = blockIdx.x*32, k0 = blockIdx.y*32, b = blockIdx.z;
    const int tx = threadIdx.x & 31, ty = threadIdx.x >> 5;
#pragma unroll
    for (int i = 0; i < 4; i++)
        t[ty + i*8][tx] = x[(long long)b*65536 + (long long)(c0 + ty + i*8)*Kk + k0 + tx];
    __syncthreads();
#pragma unroll
    for (int i = 0; i < 4; i++)
        xr[((long long)(b*Kk + k0 + ty + i*8))*128 + c0 + tx] = t[tx][ty + i*8];
}

// ---------------- V transpose: qkv -> vT[bh][c][k] ----------------
__global__ void __launch_bounds__(256) vtrans_k(const float* __restrict__ qkv, float* __restrict__ vT)
{
    __shared__ float t[32][33];
    const int c0 = blockIdx.x*32, k0 = blockIdx.y*32, bh = blockIdx.z;
    const int b = bh >> 2, h = bh & 3;
    const int tx = threadIdx.x & 31, ty = threadIdx.x >> 5;
#pragma unroll
    for (int i = 0; i < 4; i++)
        t[ty + i*8][tx] = qkv[((long long)(b*Kk + k0 + ty + i*8))*768 + 256 + h*128 + c0 + tx];
    __syncthreads();
#pragma unroll
    for (int i = 0; i < 4; i++)
        vT[(long long)bh*65536 + (long long)(c0 + ty + i*8)*512 + k0 + tx] = t[tx][ty + i*8];
}

// ---------------- row layernorm: warp per row ----------------
__global__ void __launch_bounds__(256) ln_k(
    const float* __restrict__ in, int lda,
    const float* __restrict__ g, const float* __restrict__ be,
    float* __restrict__ ln)
{
    const int row = blockIdx.x*8 + (threadIdx.x >> 5);
    const int lane = threadIdx.x & 31;
    const float* p = in + (long long)row*lda;
    float x[4];
#pragma unroll
    for (int q = 0; q < 4; q++) x[q] = p[lane + q*32];
    float s = x[0] + x[1] + x[2] + x[3];
#pragma unroll
    for (int off = 16; off; off >>= 1) s += __shfl_xor_sync(0xffffffffu, s, off);
    const float mu = s * (1.f/128.f);
    float v = 0.f;
#pragma unroll
    for (int q = 0; q < 4; q++) { float d = x[q] - mu; v = fmaf(d, d, v); }
#pragma unroll
    for (int off = 16; off; off >>= 1) v += __shfl_xor_sync(0xffffffffu, v, off);
    const float inv = rsqrtf(v * (1.f/128.f) + 1e-6f);
    float* o = ln + (long long)row*128;
#pragma unroll
    for (int q = 0; q < 4; q++) {
        int c = lane + q*32;
        o[c] = (x[q] - mu)*inv*g[c] + be[c];
    }
}

// ---------------- prep kernels ----------------
__global__ void wtrans_k(const float* __restrict__ cw, float* __restrict__ wT)
{
    long long idx = (long long)blockIdx.x*256 + threadIdx.x;
    if (idx >= 8LL*9*128*128) return;
    int i = (int)(idx & 127); long long r = idx >> 7;
    int o = (int)(r & 127); r >>= 7;
    int t = (int)(r % 9); int l = (int)(r / 9);
    wT[idx] = cw[(((long long)l*128 + o)*128 + i)*9 + t];
}

__global__ void qkvpack_k(const float* __restrict__ Wq, const float* __restrict__ Wkm,
                          const float* __restrict__ Wv, float* __restrict__ W)
{
    long long idx = (long long)blockIdx.x*256 + threadIdx.x;
    if (idx >= 8LL*768*128) return;
    int cc = (int)(idx & 127); long long r = idx >> 7;
    int j = (int)(r % 768); int l = (int)(r / 768);
    float v;
    if (j < 128)      v = Wq[((long long)l*128 + cc)*128 + j];
    else if (j < 256) v = Wkm[((long long)l*128 + cc)*128 + (j - 128)];
    else              v = Wv[((long long)l*128 + cc)*512 + (j - 256)];
    W[idx] = v;
}

__global__ void wcT_k(const float* __restrict__ Wc, float* __restrict__ WcT)
{
    long long idx = (long long)blockIdx.x*256 + threadIdx.x;
    if (idx >= 8LL*128*512) return;
    int m = (int)(idx & 511); long long r = idx >> 9;
    int n = (int)(r & 127); int l = (int)(r >> 7);
    WcT[idx] = Wc[((long long)l*512 + m)*128 + n];
}

__global__ void waT_k(const float* __restrict__ Wa, float* __restrict__ WaT)
{
    long long idx = (long long)blockIdx.x*256 + threadIdx.x;
    if (idx >= 8LL*128*256) return;
    int i = (int)(idx & 255); long long r = idx >> 8;
    int o = (int)(r & 127); int l = (int)(r >> 7);
    WaT[idx] = Wa[((long long)l*256 + i)*128 + o];
}

__global__ void p2pad_k(const float* __restrict__ w, float* __restrict__ dst)
{
    int idx = blockIdx.x*256 + threadIdx.x;
    int k = idx & 255, n = idx >> 8;
    dst[idx] = (n < 64) ? w[n*256 + k] : 0.f;
}

__global__ void biaspad_k(const float* __restrict__ b, float* __restrict__ dst)
{
    int j = threadIdx.x;
    dst[j] = (j < 64) ? b[j] : 0.f;
}

// ---------------- max over K + bias -> g (B,256) ----------------
__global__ void __launch_bounds__(256) maxg_k(
    const float* __restrict__ fus, const float* __restrict__ fb, float* __restrict__ g)
{
    const int b = blockIdx.x, f = threadIdx.x;
    const float* p = fus + (long long)b*Kk*256 + f;
    float mx = -3.0e38f;
    for (int k = 0; k < Kk; k++) mx = fmaxf(mx, p[(long long)k*256]);
    g[b*256 + f] = mx + fb[f];
}

__global__ void gfill_k(const float* __restrict__ g, float* __restrict__ state)
{
    long long idx = (long long)blockIdx.x*256 + threadIdx.x;
    int f = (int)(idx & 255); long long row = idx >> 8; int b = (int)(row >> 9);
    state[row*1536 + 256 + f] = g[b*256 + f];
}

// ---------------- LSTM elementwise ----------------
__device__ __forceinline__ float sigm(float x) { return 1.f / (1.f + __expf(-x)); }

__global__ void __launch_bounds__(256) lstm_k(
    const float* __restrict__ gates, const float* __restrict__ c0,
    float* __restrict__ state, float* __restrict__ ho, float* __restrict__ co)
{
    long long idx = (long long)blockIdx.x*256 + threadIdx.x;
    int j = (int)(idx & 255); long long row = idx >> 8;
    const float* gr = gates + row*1024;
    float gi = gr[j], gf = gr[256+j], gg = gr[512+j], go = gr[768+j];
    float c = sigm(gf)*c0[row*256 + j] + sigm(gi)*tanhf(gg);
    float h = sigm(go)*tanhf(c);
    state[row*1536 + j] = h;
    ho[idx] = h;
    co[idx] = c;
}

// ---------------- final p3: (BK,128pad)->(B,2,K) ----------------
__global__ void __launch_bounds__(256) p3_k(
    const float* __restrict__ p2, const float* __restrict__ w,
    const float* __restrict__ b3, float* __restrict__ out)
{
    const int row = blockIdx.x*8 + (threadIdx.x >> 5);
    const int lane = threadIdx.x & 31;
    const float* pr = p2 + (long long)row*128;
    float x0 = pr[lane], x1 = pr[lane + 32];
    float s0 = x0*w[lane]      + x1*w[lane + 32];
    float s1 = x0*w[64 + lane] + x1*w[96 + lane];
#pragma unroll
    for (int off = 16; off; off >>= 1) {
        s0 += __shfl_xor_sync(0xffffffffu, s0, off);
        s1 += __shfl_xor_sync(0xffffffffu, s1, off);
    }
    if (lane == 0) {
        int b = row >> 9, k = row & 511;
        out[(long long)b*1024 + k]       = s0 + b3[0];
        out[(long long)b*1024 + 512 + k] = s1 + b3[1];
    }
}

// ---------------- launch ----------------
extern "C" void kernel_launch(void* const* d_in, const int* in_sizes, int n_in,
                              void* d_out, int out_size)
{
    const float* x    = (const float*)d_in[0];
    const float* h0   = (const float*)d_in[1];
    const float* c0   = (const float*)d_in[2];
    const float* ln_g = (const float*)d_in[3];
    const float* ln_b = (const float*)d_in[4];
    const float* Wq   = (const float*)d_in[5];
    const float* Wkm  = (const float*)d_in[6];
    const float* Wv   = (const float*)d_in[7];
    const float* Ww   = (const float*)d_in[8];
    const float* Wa   = (const float*)d_in[9];
    const float* cw   = (const float*)d_in[10];
    const float* cb   = (const float*)d_in[11];
    const float* fus_w = (const float*)d_in[12];
    const float* fus_b = (const float*)d_in[13];
    const float* rs_w  = (const float*)d_in[14];
    const float* rs_b  = (const float*)d_in[15];
    const float* W_ih  = (const float*)d_in[16];
    const float* W_hh  = (const float*)d_in[17];
    const float* b_ih  = (const float*)d_in[18];
    const float* b_hh  = (const float*)d_in[19];
    const float* p1_w  = (const float*)d_in[20];
    const float* p1_b  = (const float*)d_in[21];
    const float* p2_w  = (const float*)d_in[22];
    const float* p2_b  = (const float*)d_in[23];
    const float* p3_w  = (const float*)d_in[24];
    const float* p3_b  = (const float*)d_in[25];
    float* out = (float*)d_out;

    void* sp = nullptr;
    cudaGetSymbolAddress(&sp, d_scratch);
    float* S = (float*)sp;
    float* xrows = S + O_XROWS;
    float* lnb   = S + O_LNB;
    float* qkv   = S + O_QKV;
    float* rbuf  = S + O_R;
    float* ybuf  = S + O_Y;
    float* state = S + O_STATE;
    float* fusb  = S + O_FUS;
    float* rnnb  = S + O_RNN;
    float* gates = S + O_GATES;
    float* p1b   = S + O_P1;
    float* p2bf  = S + O_P2;
    float* gbuf  = S + O_G;
    float* vT    = S + O_VT;
    float* wT    = S + O_WT;
    float* Wqkv  = S + O_WQKV;
    float* Wc    = S + O_WC;
    float* WcT   = S + O_WCT;
    float* WaT   = S + O_WAT;
    float* p2n   = S + O_P2N;
    float* p2bp  = S + O_P2B;

    cudaFuncSetAttribute(flash_k, cudaFuncAttributeMaxDynamicSharedMemorySize, FLASH_SMEM);

    // ---- prep ----
    xtrans_k<<<dim3(4,16,64), 256>>>(x, xrows);
    wtrans_k<<<(int)((8LL*9*128*128 + 255)/256), 256>>>(cw, wT);
    qkvpack_k<<<(int)((8LL*768*128 + 255)/256), 256>>>(Wq, Wkm, Wv, Wqkv);
    waT_k<<<(int)((8LL*128*256 + 255)/256), 256>>>(Wa, WaT);
    gemm_tc<false,false><<<dim3(4,1,8), 256>>>(
        Ww, 128, 65536, 0,  WaT, 256, 32768, 0,  Wc, 128, 65536, 0, nullptr, 128, 0);
    wcT_k<<<(int)((8LL*128*512 + 255)/256), 256>>>(Wc, WcT);
    p2pad_k<<<128, 256>>>(p2_w, p2n);
    biaspad_k<<<1, 128>>>(p2_b, p2bp);

    static const int DIL[8] = {1,1,1,1,2,2,4,4};
    for (int l = 0; l < 8; l++) {
        const float* inrows = (l == 0) ? xrows : (state + 512 + (l-1)*128);
        int lda = (l == 0) ? 128 : 1536;
        ln_k<<<BK/8, 256>>>(inrows, lda, ln_g + l*128, ln_b + l*128, lnb);
        gemm_tc<false,false><<<dim3(256,6,1), 256>>>(
            lnb, 128, 0, 0,  Wqkv + (long long)l*98304, 128, 0, 0,
            qkv, 768, 0, 0, nullptr, 128, 0);
        vtrans_k<<<dim3(4,16,256), 256>>>(qkv, vT);
        flash_k<<<dim3(4,4,64), 256, FLASH_SMEM>>>(qkv, vT, rbuf);
        gemm_tc<false,false><<<dim3(256,1,1), 256>>>(
            rbuf, 512, 0, 0,  WcT + (long long)l*65536, 512, 0, 0,
            ybuf, 128, 0, 0, nullptr, 512, 0);
        gemm_tc<true,false><<<dim3(256,1,1), 256>>>(
            inrows, lda, 0, 0,  WaT + (long long)l*32768 + 128, 256, 0, 0,
            ybuf, 128, 0, 0, nullptr, 128, 0);
        conv_tc<<<256, 256>>>(ybuf, wT + (long long)l*147456, cb + l*128, state, l, DIL[l]);
    }

    gemm_tc<false,false><<<dim3(256,2,1), 256>>>(
        state + 512, 1536, 0, 0,  fus_w, 1024, 0, 0,
        fusb, 256, 0, 0, nullptr, 1024, 0);
    maxg_k<<<64, 256>>>(fusb, fus_b, gbuf);
    gfill_k<<<BK, 256>>>(gbuf, state);
    gemm_tc<false,false><<<dim3(256,2,1), 256>>>(
        state + 256, 1536, 0, 0,  rs_w, 1280, 0, 0,
        rnnb, 256, 0, 0, rs_b, 1280, 0);
    gemm_tc<false,false><<<dim3(256,8,1), 256>>>(
        rnnb, 256, 0, 0,  W_ih, 256, 0, 0,
        gates, 1024, 0, 0, b_ih, 256, 0);
    gemm_tc<true,false><<<dim3(256,8,1), 256>>>(
        h0, 256, 0, 0,  W_hh, 256, 0, 0,
        gates, 1024, 0, 0, b_hh, 256, 0);
    float* ho = out + 65536;
    float* co = out + 65536 + (long long)BK*256;
    lstm_k<<<BK, 256>>>(gates, c0, state, ho, co);
    gemm_tc<false,true><<<dim3(256,2,1), 256>>>(
        state, 1536, 0, 0,  p1_w, 1536, 0, 0,
        p1b, 256, 0, 0, p1_b, 1536, 0);
    gemm_tc<false,true><<<dim3(256,1,1), 256>>>(
        p1b, 256, 0, 0,  p2n, 256, 0, 0,
        p2bf, 128, 0, 0, p2bp, 256, 0);
    p3_k<<<BK/8, 256>>>(p2bf, p3_w, p3_b, out);
}

// round 8
// speedup vs baseline: 2.6480x; 1.0240x over previous
#include <cuda_runtime.h>

#define BK 32768
#define Kk 512

// ---------------- scratch offsets (floats) ----------------
constexpr long long O_XROWS = 0,                      SZ_XROWS = (long long)BK*128;
constexpr long long O_LNS   = O_XROWS + SZ_XROWS,     SZ_LNS   = (long long)BK*2;
constexpr long long O_QKV   = O_LNS + SZ_LNS,         SZ_QKV   = (long long)BK*768;
constexpr long long O_R     = O_QKV + SZ_QKV,         SZ_R     = (long long)BK*512;
constexpr long long O_Y     = O_R + SZ_R,             SZ_Y     = (long long)BK*128;
constexpr long long O_STATE = O_Y + SZ_Y,             SZ_STATE = (long long)BK*1536;
constexpr long long O_FUS   = O_STATE + SZ_STATE,     SZ_FUS   = (long long)BK*256;
constexpr long long O_RNN   = O_FUS + SZ_FUS,         SZ_RNN   = (long long)BK*256;
constexpr long long O_GATES = O_RNN + SZ_RNN,         SZ_GATES = (long long)BK*1024;
constexpr long long O_P1    = O_GATES + SZ_GATES,     SZ_P1    = (long long)BK*256;
constexpr long long O_P2    = O_P1 + SZ_P1,           SZ_P2    = (long long)BK*128;
constexpr long long O_G     = O_P2 + SZ_P2,           SZ_G     = 64*256;
constexpr long long O_PM    = O_G + SZ_G,             SZ_PM    = 64LL*8*256;
constexpr long long O_VT    = O_PM + SZ_PM,           SZ_VT    = 256LL*128*512;
constexpr long long O_WT    = O_VT + SZ_VT,           SZ_WT    = 8LL*9*128*128;
constexpr long long O_WQKV  = O_WT + SZ_WT,           SZ_WQKV  = 8LL*768*128;
constexpr long long O_WC    = O_WQKV + SZ_WQKV,       SZ_WC    = 8LL*512*128;
constexpr long long O_WCT   = O_WC + SZ_WC,           SZ_WCT   = 8LL*128*512;
constexpr long long O_WAT   = O_WCT + SZ_WCT,         SZ_WAT   = 8LL*128*256;
constexpr long long O_P2N   = O_WAT + SZ_WAT,         SZ_P2N   = 128LL*256;
constexpr long long O_P2B   = O_P2N + SZ_P2N,         SZ_P2B   = 128;
constexpr long long SCRATCH_TOTAL = O_P2B + SZ_P2B;

__device__ __align__(16) float d_scratch[SCRATCH_TOTAL];

// ---------------- bf16 split helpers ----------------
__device__ __forceinline__ int swz(int row, int kp) {
    return row*8 + (kp ^ (((row >> 2) & 1) << 2));
}
__device__ __forceinline__ void split2(float x, float y, unsigned& h, unsigned& l) {
    asm("cvt.rn.bf16x2.f32 %0, %1, %2;" : "=r"(h) : "f"(y), "f"(x));
    float hx = __uint_as_float(h << 16);
    float hy = __uint_as_float(h & 0xffff0000u);
    asm("cvt.rn.bf16x2.f32 %0, %1, %2;" : "=r"(l) : "f"(y - hy), "f"(x - hx));
}
__device__ __forceinline__ void mma16(float* c, const unsigned* a, const unsigned* b) {
    asm volatile(
        "mma.sync.aligned.m16n8k16.row.col.f32.bf16.bf16.f32 "
        "{%0,%1,%2,%3},{%4,%5,%6,%7},{%8,%9},{%0,%1,%2,%3};"
        : "+f"(c[0]), "+f"(c[1]), "+f"(c[2]), "+f"(c[3])
        : "r"(a[0]), "r"(a[1]), "r"(a[2]), "r"(a[3]), "r"(b[0]), "r"(b[1]));
}

// stage one 8-float row segment (hi+lo) into smem
__device__ __forceinline__ void stage8(unsigned* H, unsigned* L, int row, int half,
                                       float4 v0, float4 v1) {
    unsigned h0,l0,h1,l1,h2,l2,h3,l3;
    split2(v0.x, v0.y, h0, l0); split2(v0.z, v0.w, h1, l1);
    split2(v1.x, v1.y, h2, l2); split2(v1.z, v1.w, h3, l3);
    const int kpb = (half*4) ^ (((row >> 2) & 1) << 2);
    *(uint4*)&H[row*8 + kpb] = make_uint4(h0, h1, h2, h3);
    *(uint4*)&L[row*8 + kpb] = make_uint4(l0, l1, l2, l3);
}

__device__ __forceinline__ void tile_compute(
    const unsigned* __restrict__ Ah, const unsigned* __restrict__ Al,
    const unsigned* __restrict__ Bh, const unsigned* __restrict__ Bl,
    float c[4][4][4], int qg, int rg, int wm, int wn)
{
    unsigned ah[4][4], al[4][4], bh[4][2], bl[4][2];
#pragma unroll
    for (int mt = 0; mt < 4; mt++) {
        const int r0 = wm + mt*16 + qg, r1 = r0 + 8;
        ah[mt][0] = Ah[swz(r0, rg)];   ah[mt][1] = Ah[swz(r1, rg)];
        ah[mt][2] = Ah[swz(r0, rg+4)]; ah[mt][3] = Ah[swz(r1, rg+4)];
        al[mt][0] = Al[swz(r0, rg)];   al[mt][1] = Al[swz(r1, rg)];
        al[mt][2] = Al[swz(r0, rg+4)]; al[mt][3] = Al[swz(r1, rg+4)];
    }
#pragma unroll
    for (int nt = 0; nt < 4; nt++) {
        const int col = wn + nt*8 + qg;
        bh[nt][0] = Bh[swz(col, rg)]; bh[nt][1] = Bh[swz(col, rg+4)];
        bl[nt][0] = Bl[swz(col, rg)]; bl[nt][1] = Bl[swz(col, rg+4)];
    }
#pragma unroll
    for (int mt = 0; mt < 4; mt++)
#pragma unroll
        for (int nt = 0; nt < 4; nt++) {
            mma16(c[mt][nt], ah[mt], bh[nt]);
            mma16(c[mt][nt], ah[mt], bl[nt]);
            mma16(c[mt][nt], al[mt], bh[nt]);
        }
}

// ---------------- tensor-core GEMM (bf16x3): 128x128 tile ----------------
// C = A(M,Kd) @ Bn^T  [+C] [+bias(col)] [relu];  B given n-major Bn[N][Kd]
// LNA: apply per-row (mu,inv) from lnstat and per-col affine lg/lb to A during staging
template<bool ACC, bool RELU, bool LNA = false>
__global__ void __launch_bounds__(256) gemm_tc(
    const float* __restrict__ A, int lda, long long sA, long long sA2,
    const float* __restrict__ B, int ldb, long long sB, long long sB2,
    float* __restrict__ C, int ldc, long long sC, long long sC2,
    const float* __restrict__ bias, int Kd, int zshift,
    const float* __restrict__ lnstat = nullptr,
    const float* __restrict__ lg = nullptr,
    const float* __restrict__ lb = nullptr)
{
    const int bz = blockIdx.z;
    const int hi = bz >> zshift, lo = bz - (hi << zshift);
    A += hi*sA + lo*sA2;
    B += hi*sB + lo*sB2;
    C += hi*sC + lo*sC2;
    const int m0 = blockIdx.x*128, n0 = blockIdx.y*128;
    __shared__ __align__(16) unsigned Ah[2][1024], Al[2][1024];
    __shared__ __align__(16) unsigned Bh[2][1024], Bl[2][1024];
    const int tid = threadIdx.x;
    const int lane = tid & 31, warp = tid >> 5;
    const int qg = lane >> 2, rg = lane & 3;
    const int wm = (warp & 1)*64, wn = (warp >> 1)*32;

    float c[4][4][4];
#pragma unroll
    for (int i = 0; i < 4; i++)
#pragma unroll
        for (int j = 0; j < 4; j++)
#pragma unroll
            for (int k = 0; k < 4; k++) c[i][j][k] = 0.f;

    const int srow = tid >> 1, half = tid & 1;
    const float* Ap = A + (long long)(m0 + srow)*lda + half*8;
    const float* Bp = B + (long long)(n0 + srow)*ldb + half*8;
    const int nc = Kd >> 4;

    float mu = 0.f, inv = 1.f;
    if (LNA) {
        mu  = lnstat[(long long)(m0 + srow)*2];
        inv = lnstat[(long long)(m0 + srow)*2 + 1];
    }

    float4 ra0, ra1, rb0, rb1;
    ra0 = *(const float4*)Ap;       ra1 = *(const float4*)(Ap + 4);
    rb0 = *(const float4*)Bp;       rb1 = *(const float4*)(Bp + 4);
    if (LNA) {
        float4 g0 = *(const float4*)(lg + half*8), g1 = *(const float4*)(lg + half*8 + 4);
        float4 b0 = *(const float4*)(lb + half*8), b1 = *(const float4*)(lb + half*8 + 4);
        ra0.x = (ra0.x - mu)*inv*g0.x + b0.x; ra0.y = (ra0.y - mu)*inv*g0.y + b0.y;
        ra0.z = (ra0.z - mu)*inv*g0.z + b0.z; ra0.w = (ra0.w - mu)*inv*g0.w + b0.w;
        ra1.x = (ra1.x - mu)*inv*g1.x + b1.x; ra1.y = (ra1.y - mu)*inv*g1.y + b1.y;
        ra1.z = (ra1.z - mu)*inv*g1.z + b1.z; ra1.w = (ra1.w - mu)*inv*g1.w + b1.w;
    }
    stage8(Ah[0], Al[0], srow, half, ra0, ra1);
    stage8(Bh[0], Bl[0], srow, half, rb0, rb1);
    __syncthreads();

    for (int ch = 0; ch < nc; ch++) {
        const int s = ch & 1;
        if (ch + 1 < nc) {
            const int kb = (ch + 1) << 4;
            ra0 = *(const float4*)(Ap + kb); ra1 = *(const float4*)(Ap + kb + 4);
            rb0 = *(const float4*)(Bp + kb); rb1 = *(const float4*)(Bp + kb + 4);
            if (LNA) {
                float4 g0 = *(const float4*)(lg + kb + half*8), g1 = *(const float4*)(lg + kb + half*8 + 4);
                float4 b0 = *(const float4*)(lb + kb + half*8), b1 = *(const float4*)(lb + kb + half*8 + 4);
                ra0.x = (ra0.x - mu)*inv*g0.x + b0.x; ra0.y = (ra0.y - mu)*inv*g0.y + b0.y;
                ra0.z = (ra0.z - mu)*inv*g0.z + b0.z; ra0.w = (ra0.w - mu)*inv*g0.w + b0.w;
                ra1.x = (ra1.x - mu)*inv*g1.x + b1.x; ra1.y = (ra1.y - mu)*inv*g1.y + b1.y;
                ra1.z = (ra1.z - mu)*inv*g1.z + b1.z; ra1.w = (ra1.w - mu)*inv*g1.w + b1.w;
            }
        }
        tile_compute(Ah[s], Al[s], Bh[s], Bl[s], c, qg, rg, wm, wn);
        if (ch + 1 < nc) {
            const int d = s ^ 1;
            stage8(Ah[d], Al[d], srow, half, ra0, ra1);
            stage8(Bh[d], Bl[d], srow, half, rb0, rb1);
        }
        __syncthreads();
    }

#pragma unroll
    for (int mt = 0; mt < 4; mt++) {
#pragma unroll
        for (int rh = 0; rh < 2; rh++) {
            const int m = m0 + wm + mt*16 + qg + rh*8;
#pragma unroll
            for (int nt = 0; nt < 4; nt++) {
                const int n = n0 + wn + nt*8 + rg*2;
                float vx = c[mt][nt][rh*2], vy = c[mt][nt][rh*2 + 1];
                if (bias) { float2 bb = *(const float2*)(bias + n); vx += bb.x; vy += bb.y; }
                float* cp = C + (long long)m*ldc + n;
                if (ACC) { float2 o = *(float2*)cp; vx += o.x; vy += o.y; }
                if (RELU) { vx = fmaxf(vx, 0.f); vy = fmaxf(vy, 0.f); }
                *(float2*)cp = make_float2(vx, vy);
            }
        }
    }
}

// ---------------- dual-source GEMM: C = A1@B1n^T + A2@B2n^T (128x128 tile) ----------------
__global__ void __launch_bounds__(256) gemm2_tc(
    const float* __restrict__ A1, int lda1,
    const float* __restrict__ B1, int ldb1, int Kd1,
    const float* __restrict__ A2, int lda2,
    const float* __restrict__ B2, int ldb2, int Kd2,
    float* __restrict__ C, int ldc)
{
    const int m0 = blockIdx.x*128, n0 = blockIdx.y*128;
    __shared__ __align__(16) unsigned Ah[2][1024], Al[2][1024];
    __shared__ __align__(16) unsigned Bh[2][1024], Bl[2][1024];
    const int tid = threadIdx.x;
    const int lane = tid & 31, warp = tid >> 5;
    const int qg = lane >> 2, rg = lane & 3;
    const int wm = (warp & 1)*64, wn = (warp >> 1)*32;

    float c[4][4][4];
#pragma unroll
    for (int i = 0; i < 4; i++)
#pragma unroll
        for (int j = 0; j < 4; j++)
#pragma unroll
            for (int k = 0; k < 4; k++) c[i][j][k] = 0.f;

    const int srow = tid >> 1, half = tid & 1;

    for (int pass = 0; pass < 2; pass++) {
        const float* Ap = (pass == 0 ? A1 : A2) + (long long)(m0 + srow)*(pass == 0 ? lda1 : lda2) + half*8;
        const float* Bp = (pass == 0 ? B1 : B2) + (long long)(n0 + srow)*(pass == 0 ? ldb1 : ldb2) + half*8;
        const int nc = (pass == 0 ? Kd1 : Kd2) >> 4;

        float4 ra0 = *(const float4*)Ap, ra1 = *(const float4*)(Ap + 4);
        float4 rb0 = *(const float4*)Bp, rb1 = *(const float4*)(Bp + 4);
        stage8(Ah[0], Al[0], srow, half, ra0, ra1);
        stage8(Bh[0], Bl[0], srow, half, rb0, rb1);
        __syncthreads();

        for (int ch = 0; ch < nc; ch++) {
            const int s = ch & 1;
            if (ch + 1 < nc) {
                const int kb = (ch + 1) << 4;
                ra0 = *(const float4*)(Ap + kb); ra1 = *(const float4*)(Ap + kb + 4);
                rb0 = *(const float4*)(Bp + kb); rb1 = *(const float4*)(Bp + kb + 4);
            }
            tile_compute(Ah[s], Al[s], Bh[s], Bl[s], c, qg, rg, wm, wn);
            if (ch + 1 < nc) {
                const int d = s ^ 1;
                stage8(Ah[d], Al[d], srow, half, ra0, ra1);
                stage8(Bh[d], Bl[d], srow, half, rb0, rb1);
            }
            __syncthreads();
        }
    }

#pragma unroll
    for (int mt = 0; mt < 4; mt++) {
#pragma unroll
        for (int rh = 0; rh < 2; rh++) {
            const int m = m0 + wm + mt*16 + qg + rh*8;
#pragma unroll
            for (int nt = 0; nt < 4; nt++) {
                const int n = n0 + wn + nt*8 + rg*2;
                float* cp = C + (long long)m*ldc + n;
                *(float2*)cp = make_float2(c[mt][nt][rh*2], c[mt][nt][rh*2 + 1]);
            }
        }
    }
}

// ---------------- fused flash attention (bf16x3 mma, online softmax) ----------------
constexpr int FLASH_SMEM = 169472;
__global__ void __launch_bounds__(256) flash_k(
    const float* __restrict__ qkv, const float* __restrict__ vT, float* __restrict__ r)
{
    extern __shared__ __align__(16) unsigned sm_[];
    unsigned* Qh = sm_;
    unsigned* Ql = Qh + 2048;
    unsigned* Kh = Ql + 2048;
    unsigned* Kl = Kh + 2048;
    unsigned* Vh = Kl + 2048;
    unsigned* Vl = Vh + 8192;
    unsigned* Ph = Vl + 8192;
    unsigned* Pl = Ph + 8192;
    float* rowM = (float*)(Pl + 8192);
    float* rowL = rowM + 128;
    float* rowA = rowL + 128;
    float* redM = rowA + 128;
    float* redS = redM + 512;

    const int b = blockIdx.z, h = blockIdx.y, q0 = blockIdx.x*128;
    const int tid = threadIdx.x, lane = tid & 31, warp = tid >> 5;
    const int qg = lane >> 2, rg = lane & 3;
    const int wm = (warp & 1)*64, wn = (warp >> 1)*32;
    const int srow = tid >> 1, half = tid & 1;
    const int bh = b*4 + h;

    {
        const float* qp = qkv + ((long long)(b*Kk + q0 + srow))*768 + h*32 + half*8;
        float4 a0 = *(const float4*)qp, a1 = *(const float4*)(qp + 4);
        stage8(Qh, Ql, srow, half, a0, a1);
        a0 = *(const float4*)(qp + 16); a1 = *(const float4*)(qp + 20);
        stage8(Qh + 1024, Ql + 1024, srow, half, a0, a1);
    }
    if (tid < 128) { rowM[tid] = -3.0e38f; rowL[tid] = 0.f; }

    float co[4][4][4];
#pragma unroll
    for (int i = 0; i < 4; i++)
#pragma unroll
        for (int j = 0; j < 4; j++)
#pragma unroll
            for (int k = 0; k < 4; k++) co[i][j][k] = 0.f;

    const float sc = 0.17677669529663687f;

    for (int kc = 0; kc < 4; kc++) {
        {
            const float* kp_ = qkv + ((long long)(b*Kk + kc*128 + srow))*768 + 128 + h*32 + half*8;
            float4 a0 = *(const float4*)kp_, a1 = *(const float4*)(kp_ + 4);
            stage8(Kh, Kl, srow, half, a0, a1);
            a0 = *(const float4*)(kp_ + 16); a1 = *(const float4*)(kp_ + 20);
            stage8(Kh + 1024, Kl + 1024, srow, half, a0, a1);
        }
        {
            const float* vp = vT + (long long)bh*65536 + (long long)srow*512 + kc*128 + half*8;
#pragma unroll
            for (int j = 0; j < 8; j++) {
                float4 v0 = *(const float4*)(vp + j*16), v1 = *(const float4*)(vp + j*16 + 4);
                stage8(Vh + j*1024, Vl + j*1024, srow, half, v0, v1);
            }
        }
        __syncthreads();

        float cs[4][4][4];
#pragma unroll
        for (int i = 0; i < 4; i++)
#pragma unroll
            for (int j = 0; j < 4; j++)
#pragma unroll
                for (int k = 0; k < 4; k++) cs[i][j][k] = 0.f;
        tile_compute(Qh, Ql, Kh, Kl, cs, qg, rg, wm, wn);
        tile_compute(Qh + 1024, Ql + 1024, Kh + 1024, Kl + 1024, cs, qg, rg, wm, wn);

#pragma unroll
        for (int mt = 0; mt < 4; mt++)
#pragma unroll
            for (int rh = 0; rh < 2; rh++) {
                float m = -3.0e38f;
#pragma unroll
                for (int nt = 0; nt < 4; nt++)
                    m = fmaxf(m, fmaxf(cs[mt][nt][rh*2], cs[mt][nt][rh*2+1]));
                m *= sc;
                m = fmaxf(m, __shfl_xor_sync(0xffffffffu, m, 1));
                m = fmaxf(m, __shfl_xor_sync(0xffffffffu, m, 2));
                if (rg == 0) redM[(warp>>1)*128 + wm + mt*16 + qg + rh*8] = m;
            }
        __syncthreads();

#pragma unroll
        for (int mt = 0; mt < 4; mt++)
#pragma unroll
            for (int rh = 0; rh < 2; rh++) {
                const int row = wm + mt*16 + qg + rh*8;
                const float mOld = rowM[row];
                const float nm = fmaxf(fmaxf(fmaxf(redM[row], redM[128+row]),
                                       fmaxf(redM[256+row], redM[384+row])), mOld);
                float s = 0.f;
#pragma unroll
                for (int nt = 0; nt < 4; nt++) {
                    float p0 = __expf(cs[mt][nt][rh*2]*sc   - nm);
                    float p1 = __expf(cs[mt][nt][rh*2+1]*sc - nm);
                    s += p0 + p1;
                    const int col = wn + nt*8 + rg*2;
                    unsigned hw, lw; split2(p0, p1, hw, lw);
                    const int ci = col >> 4, kp = (col >> 1) & 7;
                    Ph[ci*1024 + swz(row, kp)] = hw;
                    Pl[ci*1024 + swz(row, kp)] = lw;
                }
                s += __shfl_xor_sync(0xffffffffu, s, 1);
                s += __shfl_xor_sync(0xffffffffu, s, 2);
                if (rg == 0) redS[(warp>>1)*128 + row] = s;
            }
        __syncthreads();

        if (tid < 128) {
            const int row = tid;
            const float mOld = rowM[row];
            const float nm = fmaxf(fmaxf(fmaxf(redM[row], redM[128+row]),
                                   fmaxf(redM[256+row], redM[384+row])), mOld);
            const float a = __expf(mOld - nm);
            rowL[row] = rowL[row]*a + redS[row] + redS[128+row] + redS[256+row] + redS[384+row];
            rowM[row] = nm;
            rowA[row] = a;
        }
        __syncthreads();

#pragma unroll
        for (int mt = 0; mt < 4; mt++) {
            const float a0_ = rowA[wm + mt*16 + qg];
            const float a1_ = rowA[wm + mt*16 + qg + 8];
#pragma unroll
            for (int nt = 0; nt < 4; nt++) {
                co[mt][nt][0] *= a0_; co[mt][nt][1] *= a0_;
                co[mt][nt][2] *= a1_; co[mt][nt][3] *= a1_;
            }
        }
#pragma unroll
        for (int j = 0; j < 8; j++)
            tile_compute(Ph + j*1024, Pl + j*1024, Vh + j*1024, Vl + j*1024, co, qg, rg, wm, wn);
        __syncthreads();
    }

#pragma unroll
    for (int mt = 0; mt < 4; mt++)
#pragma unroll
        for (int rh = 0; rh < 2; rh++) {
            const int row = wm + mt*16 + qg + rh*8;
            const float inv = 1.f / rowL[row];
            float* rp = r + ((long long)(b*Kk + q0 + row))*512 + h*128;
#pragma unroll
            for (int nt = 0; nt < 4; nt++) {
                const int col = wn + nt*8 + rg*2;
                *(float2*)(rp + col) = make_float2(co[mt][nt][rh*2]*inv, co[mt][nt][rh*2+1]*inv);
            }
        }
}

// ---------------- dilated circular conv as implicit TC GEMM (bf16x3) ----------------
__global__ void __launch_bounds__(256) conv_tc(
    const float* __restrict__ y, const float* __restrict__ wtl,
    const float* __restrict__ cbl, float* __restrict__ state,
    int layer, int dil)
{
    const int tile = blockIdx.x;
    const int b = tile >> 2, k0 = (tile & 3) << 7;
    const float* yb = y + (long long)b*Kk*128;
    __shared__ __align__(16) unsigned Ah[2][1024], Al[2][1024];
    __shared__ __align__(16) unsigned Bh[2][1024], Bl[2][1024];
    const int tid = threadIdx.x;
    const int lane = tid & 31, warp = tid >> 5;
    const int qg = lane >> 2, rg = lane & 3;
    const int wm = (warp & 1)*64, wn = (warp >> 1)*32;

    float c[4][4][4];
#pragma unroll
    for (int i = 0; i < 4; i++)
#pragma unroll
        for (int j = 0; j < 4; j++)
#pragma unroll
            for (int k = 0; k < 4; k++) c[i][j][k] = 0.f;

    const int srow = tid >> 1, half = tid & 1;
    float4 ra0, ra1, rb0, rb1;

    {
        const int src = (k0 + srow - 4*dil + Kk) & (Kk - 1);
        const float* ap = yb + (long long)src*128 + half*8;
        ra0 = *(const float4*)ap; ra1 = *(const float4*)(ap + 4);
        const float* bp = wtl + (long long)srow*128 + half*8;
        rb0 = *(const float4*)bp; rb1 = *(const float4*)(bp + 4);
    }
    stage8(Ah[0], Al[0], srow, half, ra0, ra1);
    stage8(Bh[0], Bl[0], srow, half, rb0, rb1);
    __syncthreads();

    for (int ch = 0; ch < 72; ch++) {
        const int s = ch & 1;
        if (ch + 1 < 72) {
            const int tn = (ch + 1) / 8, icb = (ch + 1) & 7;
            const int kb = icb << 4;
            const int src = (k0 + srow + (tn - 4)*dil + Kk) & (Kk - 1);
            const float* ap = yb + (long long)src*128 + kb + half*8;
            ra0 = *(const float4*)ap; ra1 = *(const float4*)(ap + 4);
            const float* bp = wtl + (long long)tn*16384 + (long long)srow*128 + kb + half*8;
            rb0 = *(const float4*)bp; rb1 = *(const float4*)(bp + 4);
        }
        tile_compute(Ah[s], Al[s], Bh[s], Bl[s], c, qg, rg, wm, wn);
        if (ch + 1 < 72) {
            const int d = s ^ 1;
            stage8(Ah[d], Al[d], srow, half, ra0, ra1);
            stage8(Bh[d], Bl[d], srow, half, rb0, rb1);
        }
        __syncthreads();
    }

#pragma unroll
    for (int mt = 0; mt < 4; mt++) {
#pragma unroll
        for (int rh = 0; rh < 2; rh++) {
            const int pos = k0 + wm + mt*16 + qg + rh*8;
            const long long row = (long long)b*Kk + pos;
#pragma unroll
            for (int nt = 0; nt < 4; nt++) {
                const int n = wn + nt*8 + rg*2;
                float vx = c[mt][nt][rh*2]   + cbl[n];
                float vy = c[mt][nt][rh*2+1] + cbl[n+1];
                vx = fmaxf(vx, 0.f); vy = fmaxf(vy, 0.f);
                const long long sidx = row*1536 + 512 + (long long)layer*128 + n;
                if (layer > 0) {
                    float2 r = *(float2*)&state[sidx - 128];
                    vx += r.x; vy += r.y;
                }
                *(float2*)&state[sidx] = make_float2(vx, vy);
            }
        }
    }
}

// ---------------- transpose x (B,128,K) -> xrows (B*K,128) ----------------
__global__ void __launch_bounds__(256) xtrans_k(const float* __restrict__ x, float* __restrict__ xr)
{
    __shared__ float t[32][33];
    const int c0 = blockIdx.x*32, k0 = blockIdx.y*32, b = blockIdx.z;
    const int tx = threadIdx.x & 31, ty = threadIdx.x >> 5;
#pragma unroll
    for (int i = 0; i < 4; i++)
        t[ty + i*8][tx] = x[(long long)b*65536 + (long long)(c0 + ty + i*8)*Kk + k0 + tx];
    __syncthreads();
#pragma unroll
    for (int i = 0; i < 4; i++)
        xr[((long long)(b*Kk + k0 + ty + i*8))*128 + c0 + tx] = t[tx][ty + i*8];
}

// ---------------- V transpose: qkv -> vT[bh][c][k] ----------------
__global__ void __launch_bounds__(256) vtrans_k(const float* __restrict__ qkv, float* __restrict__ vT)
{
    __shared__ float t[32][33];
    const int c0 = blockIdx.x*32, k0 = blockIdx.y*32, bh = blockIdx.z;
    const int b = bh >> 2, h = bh & 3;
    const int tx = threadIdx.x & 31, ty = threadIdx.x >> 5;
#pragma unroll
    for (int i = 0; i < 4; i++)
        t[ty + i*8][tx] = qkv[((long long)(b*Kk + k0 + ty + i*8))*768 + 256 + h*128 + c0 + tx];
    __syncthreads();
#pragma unroll
    for (int i = 0; i < 4; i++)
        vT[(long long)bh*65536 + (long long)(c0 + ty + i*8)*512 + k0 + tx] = t[tx][ty + i*8];
}

// ---------------- layernorm stats: (mu, inv) per row ----------------
__global__ void __launch_bounds__(256) lnstat_k(
    const float* __restrict__ in, int lda, float* __restrict__ stat)
{
    const int row = blockIdx.x*8 + (threadIdx.x >> 5);
    const int lane = threadIdx.x & 31;
    const float* p = in + (long long)row*lda;
    float x[4];
#pragma unroll
    for (int q = 0; q < 4; q++) x[q] = p[lane + q*32];
    float s = x[0] + x[1] + x[2] + x[3];
#pragma unroll
    for (int off = 16; off; off >>= 1) s += __shfl_xor_sync(0xffffffffu, s, off);
    const float mu = s * (1.f/128.f);
    float v = 0.f;
#pragma unroll
    for (int q = 0; q < 4; q++) { float d = x[q] - mu; v = fmaf(d, d, v); }
#pragma unroll
    for (int off = 16; off; off >>= 1) v += __shfl_xor_sync(0xffffffffu, v, off);
    if (lane == 0) {
        stat[(long long)row*2]     = mu;
        stat[(long long)row*2 + 1] = rsqrtf(v * (1.f/128.f) + 1e-6f);
    }
}

// ---------------- prep kernels ----------------
__global__ void wtrans_k(const float* __restrict__ cw, float* __restrict__ wT)
{
    long long idx = (long long)blockIdx.x*256 + threadIdx.x;
    if (idx >= 8LL*9*128*128) return;
    int i = (int)(idx & 127); long long r = idx >> 7;
    int o = (int)(r & 127); r >>= 7;
    int t = (int)(r % 9); int l = (int)(r / 9);
    wT[idx] = cw[(((long long)l*128 + o)*128 + i)*9 + t];
}

__global__ void qkvpack_k(const float* __restrict__ Wq, const float* __restrict__ Wkm,
                          const float* __restrict__ Wv, float* __restrict__ W)
{
    long long idx = (long long)blockIdx.x*256 + threadIdx.x;
    if (idx >= 8LL*768*128) return;
    int cc = (int)(idx & 127); long long r = idx >> 7;
    int j = (int)(r % 768); int l = (int)(r / 768);
    float v;
    if (j < 128)      v = Wq[((long long)l*128 + cc)*128 + j];
    else if (j < 256) v = Wkm[((long long)l*128 + cc)*128 + (j - 128)];
    else              v = Wv[((long long)l*128 + cc)*512 + (j - 256)];
    W[idx] = v;
}

__global__ void wcT_k(const float* __restrict__ Wc, float* __restrict__ WcT)
{
    long long idx = (long long)blockIdx.x*256 + threadIdx.x;
    if (idx >= 8LL*128*512) return;
    int m = (int)(idx & 511); long long r = idx >> 9;
    int n = (int)(r & 127); int l = (int)(r >> 7);
    WcT[idx] = Wc[((long long)l*512 + m)*128 + n];
}

__global__ void waT_k(const float* __restrict__ Wa, float* __restrict__ WaT)
{
    long long idx = (long long)blockIdx.x*256 + threadIdx.x;
    if (idx >= 8LL*128*256) return;
    int i = (int)(idx & 255); long long r = idx >> 8;
    int o = (int)(r & 127); int l = (int)(r >> 7);
    WaT[idx] = Wa[((long long)l*256 + i)*128 + o];
}

__global__ void p2pad_k(const float* __restrict__ w, float* __restrict__ dst)
{
    int idx = blockIdx.x*256 + threadIdx.x;
    int k = idx & 255, n = idx >> 8;
    dst[idx] = (n < 64) ? w[n*256 + k] : 0.f;
}

__global__ void biaspad_k(const float* __restrict__ b, float* __restrict__ dst)
{
    int j = threadIdx.x;
    dst[j] = (j < 64) ? b[j] : 0.f;
}

// ---------------- max over K (two-stage) + bias -> g (B,256) ----------------
__global__ void __launch_bounds__(256) maxg1_k(
    const float* __restrict__ fus, float* __restrict__ pm)
{
    const int b = blockIdx.x, sl = blockIdx.y, f = threadIdx.x;
    const float* p = fus + (long long)b*Kk*256 + (long long)sl*64*256 + f;
    float mx = -3.0e38f;
    for (int k = 0; k < 64; k++) mx = fmaxf(mx, p[(long long)k*256]);
    pm[((long long)b*8 + sl)*256 + f] = mx;
}
__global__ void __launch_bounds__(256) maxg2_k(
    const float* __restrict__ pm, const float* __restrict__ fb, float* __restrict__ g)
{
    const int b = blockIdx.x, f = threadIdx.x;
    const float* p = pm + (long long)b*8*256 + f;
    float mx = -3.0e38f;
#pragma unroll
    for (int sl = 0; sl < 8; sl++) mx = fmaxf(mx, p[sl*256]);
    g[b*256 + f] = mx + fb[f];
}

__global__ void gfill_k(const float* __restrict__ g, float* __restrict__ state)
{
    long long idx = (long long)blockIdx.x*256 + threadIdx.x;
    int f = (int)(idx & 255); long long row = idx >> 8; int b = (int)(row >> 9);
    state[row*1536 + 256 + f] = g[b*256 + f];
}

// ---------------- LSTM elementwise ----------------
__device__ __forceinline__ float sigm(float x) { return 1.f / (1.f + __expf(-x)); }

__global__ void __launch_bounds__(256) lstm_k(
    const float* __restrict__ gates, const float* __restrict__ c0,
    float* __restrict__ state, float* __restrict__ ho, float* __restrict__ co)
{
    long long idx = (long long)blockIdx.x*256 + threadIdx.x;
    int j = (int)(idx & 255); long long row = idx >> 8;
    const float* gr = gates + row*1024;
    float gi = gr[j], gf = gr[256+j], gg = gr[512+j], go = gr[768+j];
    float c = sigm(gf)*c0[row*256 + j] + sigm(gi)*tanhf(gg);
    float h = sigm(go)*tanhf(c);
    state[row*1536 + j] = h;
    ho[idx] = h;
    co[idx] = c;
}

// ---------------- final p3: (BK,128pad)->(B,2,K) ----------------
__global__ void __launch_bounds__(256) p3_k(
    const float* __restrict__ p2, const float* __restrict__ w,
    const float* __restrict__ b3, float* __restrict__ out)
{
    const int row = blockIdx.x*8 + (threadIdx.x >> 5);
    const int lane = threadIdx.x & 31;
    const float* pr = p2 + (long long)row*128;
    float x0 = pr[lane], x1 = pr[lane + 32];
    float s0 = x0*w[lane]      + x1*w[lane + 32];
    float s1 = x0*w[64 + lane] + x1*w[96 + lane];
#pragma unroll
    for (int off = 16; off; off >>= 1) {
        s0 += __shfl_xor_sync(0xffffffffu, s0, off);
        s1 += __shfl_xor_sync(0xffffffffu, s1, off);
    }
    if (lane == 0) {
        int b = row >> 9, k = row & 511;
        out[(long long)b*1024 + k]       = s0 + b3[0];
        out[(long long)b*1024 + 512 + k] = s1 + b3[1];
    }
}

// ---------------- launch ----------------
extern "C" void kernel_launch(void* const* d_in, const int* in_sizes, int n_in,
                              void* d_out, int out_size)
{
    const float* x    = (const float*)d_in[0];
    const float* h0   = (const float*)d_in[1];
    const float* c0   = (const float*)d_in[2];
    const float* ln_g = (const float*)d_in[3];
    const float* ln_b = (const float*)d_in[4];
    const float* Wq   = (const float*)d_in[5];
    const float* Wkm  = (const float*)d_in[6];
    const float* Wv   = (const float*)d_in[7];
    const float* Ww   = (const float*)d_in[8];
    const float* Wa   = (const float*)d_in[9];
    const float* cw   = (const float*)d_in[10];
    const float* cb   = (const float*)d_in[11];
    const float* fus_w = (const float*)d_in[12];
    const float* fus_b = (const float*)d_in[13];
    const float* rs_w  = (const float*)d_in[14];
    const float* rs_b  = (const float*)d_in[15];
    const float* W_ih  = (const float*)d_in[16];
    const float* W_hh  = (const float*)d_in[17];
    const float* b_ih  = (const float*)d_in[18];
    const float* b_hh  = (const float*)d_in[19];
    const float* p1_w  = (const float*)d_in[20];
    const float* p1_b  = (const float*)d_in[21];
    const float* p2_w  = (const float*)d_in[22];
    const float* p2_b  = (const float*)d_in[23];
    const float* p3_w  = (const float*)d_in[24];
    const float* p3_b  = (const float*)d_in[25];
    float* out = (float*)d_out;

    void* sp = nullptr;
    cudaGetSymbolAddress(&sp, d_scratch);
    float* S = (float*)sp;
    float* xrows = S + O_XROWS;
    float* lns   = S + O_LNS;
    float* qkv   = S + O_QKV;
    float* rbuf  = S + O_R;
    float* ybuf  = S + O_Y;
    float* state = S + O_STATE;
    float* fusb  = S + O_FUS;
    float* rnnb  = S + O_RNN;
    float* gates = S + O_GATES;
    float* p1b   = S + O_P1;
    float* p2bf  = S + O_P2;
    float* gbuf  = S + O_G;
    float* pmbuf = S + O_PM;
    float* vT    = S + O_VT;
    float* wT    = S + O_WT;
    float* Wqkv  = S + O_WQKV;
    float* Wc    = S + O_WC;
    float* WcT   = S + O_WCT;
    float* WaT   = S + O_WAT;
    float* p2n   = S + O_P2N;
    float* p2bp  = S + O_P2B;

    cudaFuncSetAttribute(flash_k, cudaFuncAttributeMaxDynamicSharedMemorySize, FLASH_SMEM);

    // ---- prep ----
    xtrans_k<<<dim3(4,16,64), 256>>>(x, xrows);
    wtrans_k<<<(int)((8LL*9*128*128 + 255)/256), 256>>>(cw, wT);
    qkvpack_k<<<(int)((8LL*768*128 + 255)/256), 256>>>(Wq, Wkm, Wv, Wqkv);
    waT_k<<<(int)((8LL*128*256 + 255)/256), 256>>>(Wa, WaT);
    gemm_tc<false,false><<<dim3(4,1,8), 256>>>(
        Ww, 128, 65536, 0,  WaT, 256, 32768, 0,  Wc, 128, 65536, 0, nullptr, 128, 0);
    wcT_k<<<(int)((8LL*128*512 + 255)/256), 256>>>(Wc, WcT);
    p2pad_k<<<128, 256>>>(p2_w, p2n);
    biaspad_k<<<1, 128>>>(p2_b, p2bp);

    static const int DIL[8] = {1,1,1,1,2,2,4,4};
    for (int l = 0; l < 8; l++) {
        const float* inrows = (l == 0) ? xrows : (state + 512 + (l-1)*128);
        int lda = (l == 0) ? 128 : 1536;
        lnstat_k<<<BK/8, 256>>>(inrows, lda, lns);
        // qkv = LN(inrows) @ Wqkv[l]  (LN fused into A staging)
        gemm_tc<false,false,true><<<dim3(256,6,1), 256>>>(
            inrows, lda, 0, 0,  Wqkv + (long long)l*98304, 128, 0, 0,
            qkv, 768, 0, 0, nullptr, 128, 0,
            lns, ln_g + l*128, ln_b + l*128);
        vtrans_k<<<dim3(4,16,256), 256>>>(qkv, vT);
        flash_k<<<dim3(4,4,64), 256, FLASH_SMEM>>>(qkv, vT, rbuf);
        // y = r @ Wc[l] + inrows @ Wa_bot[l]  (merged)
        gemm2_tc<<<dim3(256,1,1), 256>>>(
            rbuf, 512,  WcT + (long long)l*65536, 512, 512,
            inrows, lda,  WaT + (long long)l*32768 + 128, 256, 128,
            ybuf, 128);
        conv_tc<<<256, 256>>>(ybuf, wT + (long long)l*147456, cb + l*128, state, l, DIL[l]);
    }

    gemm_tc<false,false><<<dim3(256,2,1), 256>>>(
        state + 512, 1536, 0, 0,  fus_w, 1024, 0, 0,
        fusb, 256, 0, 0, nullptr, 1024, 0);
    maxg1_k<<<dim3(64,8), 256>>>(fusb, pmbuf);
    maxg2_k<<<64, 256>>>(pmbuf, fus_b, gbuf);
    gfill_k<<<BK, 256>>>(gbuf, state);
    gemm_tc<false,false><<<dim3(256,2,1), 256>>>(
        state + 256, 1536, 0, 0,  rs_w, 1280, 0, 0,
        rnnb, 256, 0, 0, rs_b, 1280, 0);
    gemm_tc<false,false><<<dim3(256,8,1), 256>>>(
        rnnb, 256, 0, 0,  W_ih, 256, 0, 0,
        gates, 1024, 0, 0, b_ih, 256, 0);
    gemm_tc<true,false><<<dim3(256,8,1), 256>>>(
        h0, 256, 0, 0,  W_hh, 256, 0, 0,
        gates, 1024, 0, 0, b_hh, 256, 0);
    float* ho = out + 65536;
    float* co = out + 65536 + (long long)BK*256;
    lstm_k<<<BK, 256>>>(gates, c0, state, ho, co);
    gemm_tc<false,true><<<dim3(256,2,1), 256>>>(
        state, 1536, 0, 0,  p1_w, 1536, 0, 0,
        p1b, 256, 0, 0, p1_b, 1536, 0);
    gemm_tc<false,true><<<dim3(256,1,1), 256>>>(
        p1b, 256, 0, 0,  p2n, 256, 0, 0,
        p2bf, 128, 0, 0, p2bp, 256, 0);
    p3_k<<<BK/8, 256>>>(p2bf, p3_w, p3_b, out);
}

// round 9
// speedup vs baseline: 2.7896x; 1.0535x over previous
#include <cuda_runtime.h>

#define BK 32768
#define Kk 512

// ---------------- scratch offsets (floats) ----------------
constexpr long long O_XROWS = 0,                      SZ_XROWS = (long long)BK*128;
constexpr long long O_LNS   = O_XROWS + SZ_XROWS,     SZ_LNS   = (long long)BK*2;
constexpr long long O_QKV   = O_LNS + SZ_LNS,         SZ_QKV   = (long long)BK*768;
constexpr long long O_R     = O_QKV + SZ_QKV,         SZ_R     = (long long)BK*512;
constexpr long long O_Y     = O_R + SZ_R,             SZ_Y     = (long long)BK*128;
constexpr long long O_STATE = O_Y + SZ_Y,             SZ_STATE = (long long)BK*1536;
constexpr long long O_FUS   = O_STATE + SZ_STATE,     SZ_FUS   = (long long)BK*256;
constexpr long long O_RNN   = O_FUS + SZ_FUS,         SZ_RNN   = (long long)BK*256;
constexpr long long O_GATES = O_RNN + SZ_RNN,         SZ_GATES = (long long)BK*1024;
constexpr long long O_P1    = O_GATES + SZ_GATES,     SZ_P1    = (long long)BK*256;
constexpr long long O_P2    = O_P1 + SZ_P1,           SZ_P2    = (long long)BK*128;
constexpr long long O_G     = O_P2 + SZ_P2,           SZ_G     = 64*256;
constexpr long long O_PM    = O_G + SZ_G,             SZ_PM    = 64LL*8*256;
constexpr long long O_VT    = O_PM + SZ_PM,           SZ_VT    = 256LL*128*512;
constexpr long long O_WT    = O_VT + SZ_VT,           SZ_WT    = 8LL*9*128*128;
constexpr long long O_WQKV  = O_WT + SZ_WT,           SZ_WQKV  = 8LL*768*128;
constexpr long long O_WC    = O_WQKV + SZ_WQKV,       SZ_WC    = 8LL*512*128;
constexpr long long O_WCT   = O_WC + SZ_WC,           SZ_WCT   = 8LL*128*512;
constexpr long long O_WAT   = O_WCT + SZ_WCT,         SZ_WAT   = 8LL*128*256;
constexpr long long O_P2N   = O_WAT + SZ_WAT,         SZ_P2N   = 128LL*256;
constexpr long long O_P2B   = O_P2N + SZ_P2N,         SZ_P2B   = 128;
constexpr long long SCRATCH_TOTAL = O_P2B + SZ_P2B;

__device__ __align__(16) float d_scratch[SCRATCH_TOTAL];

// ---------------- bf16 split helpers ----------------
__device__ __forceinline__ int swz(int row, int kp) {
    return row*8 + (kp ^ (((row >> 2) & 1) << 2));
}
__device__ __forceinline__ void split2(float x, float y, unsigned& h, unsigned& l) {
    asm("cvt.rn.bf16x2.f32 %0, %1, %2;" : "=r"(h) : "f"(y), "f"(x));
    float hx = __uint_as_float(h << 16);
    float hy = __uint_as_float(h & 0xffff0000u);
    asm("cvt.rn.bf16x2.f32 %0, %1, %2;" : "=r"(l) : "f"(y - hy), "f"(x - hx));
}
__device__ __forceinline__ void mma16(float* c, const unsigned* a, const unsigned* b) {
    asm volatile(
        "mma.sync.aligned.m16n8k16.row.col.f32.bf16.bf16.f32 "
        "{%0,%1,%2,%3},{%4,%5,%6,%7},{%8,%9},{%0,%1,%2,%3};"
        : "+f"(c[0]), "+f"(c[1]), "+f"(c[2]), "+f"(c[3])
        : "r"(a[0]), "r"(a[1]), "r"(a[2]), "r"(a[3]), "r"(b[0]), "r"(b[1]));
}

// stage one 8-float row segment (hi+lo) into smem
__device__ __forceinline__ void stage8(unsigned* H, unsigned* L, int row, int half,
                                       float4 v0, float4 v1) {
    unsigned h0,l0,h1,l1,h2,l2,h3,l3;
    split2(v0.x, v0.y, h0, l0); split2(v0.z, v0.w, h1, l1);
    split2(v1.x, v1.y, h2, l2); split2(v1.z, v1.w, h3, l3);
    const int kpb = (half*4) ^ (((row >> 2) & 1) << 2);
    *(uint4*)&H[row*8 + kpb] = make_uint4(h0, h1, h2, h3);
    *(uint4*)&L[row*8 + kpb] = make_uint4(l0, l1, l2, l3);
}

__device__ __forceinline__ void tile_compute(
    const unsigned* __restrict__ Ah, const unsigned* __restrict__ Al,
    const unsigned* __restrict__ Bh, const unsigned* __restrict__ Bl,
    float c[4][4][4], int qg, int rg, int wm, int wn)
{
    unsigned ah[4][4], al[4][4], bh[4][2], bl[4][2];
#pragma unroll
    for (int mt = 0; mt < 4; mt++) {
        const int r0 = wm + mt*16 + qg, r1 = r0 + 8;
        ah[mt][0] = Ah[swz(r0, rg)];   ah[mt][1] = Ah[swz(r1, rg)];
        ah[mt][2] = Ah[swz(r0, rg+4)]; ah[mt][3] = Ah[swz(r1, rg+4)];
        al[mt][0] = Al[swz(r0, rg)];   al[mt][1] = Al[swz(r1, rg)];
        al[mt][2] = Al[swz(r0, rg+4)]; al[mt][3] = Al[swz(r1, rg+4)];
    }
#pragma unroll
    for (int nt = 0; nt < 4; nt++) {
        const int col = wn + nt*8 + qg;
        bh[nt][0] = Bh[swz(col, rg)]; bh[nt][1] = Bh[swz(col, rg+4)];
        bl[nt][0] = Bl[swz(col, rg)]; bl[nt][1] = Bl[swz(col, rg+4)];
    }
#pragma unroll
    for (int mt = 0; mt < 4; mt++)
#pragma unroll
        for (int nt = 0; nt < 4; nt++) {
            mma16(c[mt][nt], ah[mt], bh[nt]);
            mma16(c[mt][nt], ah[mt], bl[nt]);
            mma16(c[mt][nt], al[mt], bh[nt]);
        }
}

// ---------------- tensor-core GEMM (bf16x3): 128x128 tile ----------------
template<bool ACC, bool RELU, bool LNA = false>
__global__ void __launch_bounds__(256) gemm_tc(
    const float* __restrict__ A, int lda, long long sA, long long sA2,
    const float* __restrict__ B, int ldb, long long sB, long long sB2,
    float* __restrict__ C, int ldc, long long sC, long long sC2,
    const float* __restrict__ bias, int Kd, int zshift,
    const float* __restrict__ lnstat = nullptr,
    const float* __restrict__ lg = nullptr,
    const float* __restrict__ lb = nullptr)
{
    const int bz = blockIdx.z;
    const int hi = bz >> zshift, lo = bz - (hi << zshift);
    A += hi*sA + lo*sA2;
    B += hi*sB + lo*sB2;
    C += hi*sC + lo*sC2;
    const int m0 = blockIdx.x*128, n0 = blockIdx.y*128;
    __shared__ __align__(16) unsigned Ah[2][1024], Al[2][1024];
    __shared__ __align__(16) unsigned Bh[2][1024], Bl[2][1024];
    const int tid = threadIdx.x;
    const int lane = tid & 31, warp = tid >> 5;
    const int qg = lane >> 2, rg = lane & 3;
    const int wm = (warp & 1)*64, wn = (warp >> 1)*32;

    float c[4][4][4];
#pragma unroll
    for (int i = 0; i < 4; i++)
#pragma unroll
        for (int j = 0; j < 4; j++)
#pragma unroll
            for (int k = 0; k < 4; k++) c[i][j][k] = 0.f;

    const int srow = tid >> 1, half = tid & 1;
    const float* Ap = A + (long long)(m0 + srow)*lda + half*8;
    const float* Bp = B + (long long)(n0 + srow)*ldb + half*8;
    const int nc = Kd >> 4;

    float mu = 0.f, inv = 1.f;
    if (LNA) {
        mu  = lnstat[(long long)(m0 + srow)*2];
        inv = lnstat[(long long)(m0 + srow)*2 + 1];
    }

    float4 ra0, ra1, rb0, rb1;
    ra0 = *(const float4*)Ap;       ra1 = *(const float4*)(Ap + 4);
    rb0 = *(const float4*)Bp;       rb1 = *(const float4*)(Bp + 4);
    if (LNA) {
        float4 g0 = *(const float4*)(lg + half*8), g1 = *(const float4*)(lg + half*8 + 4);
        float4 b0 = *(const float4*)(lb + half*8), b1 = *(const float4*)(lb + half*8 + 4);
        ra0.x = (ra0.x - mu)*inv*g0.x + b0.x; ra0.y = (ra0.y - mu)*inv*g0.y + b0.y;
        ra0.z = (ra0.z - mu)*inv*g0.z + b0.z; ra0.w = (ra0.w - mu)*inv*g0.w + b0.w;
        ra1.x = (ra1.x - mu)*inv*g1.x + b1.x; ra1.y = (ra1.y - mu)*inv*g1.y + b1.y;
        ra1.z = (ra1.z - mu)*inv*g1.z + b1.z; ra1.w = (ra1.w - mu)*inv*g1.w + b1.w;
    }
    stage8(Ah[0], Al[0], srow, half, ra0, ra1);
    stage8(Bh[0], Bl[0], srow, half, rb0, rb1);
    __syncthreads();

    for (int ch = 0; ch < nc; ch++) {
        const int s = ch & 1;
        if (ch + 1 < nc) {
            const int kb = (ch + 1) << 4;
            ra0 = *(const float4*)(Ap + kb); ra1 = *(const float4*)(Ap + kb + 4);
            rb0 = *(const float4*)(Bp + kb); rb1 = *(const float4*)(Bp + kb + 4);
            if (LNA) {
                float4 g0 = *(const float4*)(lg + kb + half*8), g1 = *(const float4*)(lg + kb + half*8 + 4);
                float4 b0 = *(const float4*)(lb + kb + half*8), b1 = *(const float4*)(lb + kb + half*8 + 4);
                ra0.x = (ra0.x - mu)*inv*g0.x + b0.x; ra0.y = (ra0.y - mu)*inv*g0.y + b0.y;
                ra0.z = (ra0.z - mu)*inv*g0.z + b0.z; ra0.w = (ra0.w - mu)*inv*g0.w + b0.w;
                ra1.x = (ra1.x - mu)*inv*g1.x + b1.x; ra1.y = (ra1.y - mu)*inv*g1.y + b1.y;
                ra1.z = (ra1.z - mu)*inv*g1.z + b1.z; ra1.w = (ra1.w - mu)*inv*g1.w + b1.w;
            }
        }
        tile_compute(Ah[s], Al[s], Bh[s], Bl[s], c, qg, rg, wm, wn);
        if (ch + 1 < nc) {
            const int d = s ^ 1;
            stage8(Ah[d], Al[d], srow, half, ra0, ra1);
            stage8(Bh[d], Bl[d], srow, half, rb0, rb1);
        }
        __syncthreads();
    }

#pragma unroll
    for (int mt = 0; mt < 4; mt++) {
#pragma unroll
        for (int rh = 0; rh < 2; rh++) {
            const int m = m0 + wm + mt*16 + qg + rh*8;
#pragma unroll
            for (int nt = 0; nt < 4; nt++) {
                const int n = n0 + wn + nt*8 + rg*2;
                float vx = c[mt][nt][rh*2], vy = c[mt][nt][rh*2 + 1];
                if (bias) { float2 bb = *(const float2*)(bias + n); vx += bb.x; vy += bb.y; }
                float* cp = C + (long long)m*ldc + n;
                if (ACC) { float2 o = *(float2*)cp; vx += o.x; vy += o.y; }
                if (RELU) { vx = fmaxf(vx, 0.f); vy = fmaxf(vy, 0.f); }
                *(float2*)cp = make_float2(vx, vy);
            }
        }
    }
}

// ---------------- dual-source GEMM: C = A1@B1n^T + A2@B2n^T [+bias1+bias2] ----------------
__global__ void __launch_bounds__(256) gemm2_tc(
    const float* __restrict__ A1, int lda1,
    const float* __restrict__ B1, int ldb1, int Kd1,
    const float* __restrict__ A2, int lda2,
    const float* __restrict__ B2, int ldb2, int Kd2,
    float* __restrict__ C, int ldc,
    const float* __restrict__ bias1, const float* __restrict__ bias2)
{
    const int m0 = blockIdx.x*128, n0 = blockIdx.y*128;
    __shared__ __align__(16) unsigned Ah[2][1024], Al[2][1024];
    __shared__ __align__(16) unsigned Bh[2][1024], Bl[2][1024];
    const int tid = threadIdx.x;
    const int lane = tid & 31, warp = tid >> 5;
    const int qg = lane >> 2, rg = lane & 3;
    const int wm = (warp & 1)*64, wn = (warp >> 1)*32;

    float c[4][4][4];
#pragma unroll
    for (int i = 0; i < 4; i++)
#pragma unroll
        for (int j = 0; j < 4; j++)
#pragma unroll
            for (int k = 0; k < 4; k++) c[i][j][k] = 0.f;

    const int srow = tid >> 1, half = tid & 1;

    for (int pass = 0; pass < 2; pass++) {
        const float* Ap = (pass == 0 ? A1 : A2) + (long long)(m0 + srow)*(pass == 0 ? lda1 : lda2) + half*8;
        const float* Bp = (pass == 0 ? B1 : B2) + (long long)(n0 + srow)*(pass == 0 ? ldb1 : ldb2) + half*8;
        const int nc = (pass == 0 ? Kd1 : Kd2) >> 4;

        float4 ra0 = *(const float4*)Ap, ra1 = *(const float4*)(Ap + 4);
        float4 rb0 = *(const float4*)Bp, rb1 = *(const float4*)(Bp + 4);
        stage8(Ah[0], Al[0], srow, half, ra0, ra1);
        stage8(Bh[0], Bl[0], srow, half, rb0, rb1);
        __syncthreads();

        for (int ch = 0; ch < nc; ch++) {
            const int s = ch & 1;
            if (ch + 1 < nc) {
                const int kb = (ch + 1) << 4;
                ra0 = *(const float4*)(Ap + kb); ra1 = *(const float4*)(Ap + kb + 4);
                rb0 = *(const float4*)(Bp + kb); rb1 = *(const float4*)(Bp + kb + 4);
            }
            tile_compute(Ah[s], Al[s], Bh[s], Bl[s], c, qg, rg, wm, wn);
            if (ch + 1 < nc) {
                const int d = s ^ 1;
                stage8(Ah[d], Al[d], srow, half, ra0, ra1);
                stage8(Bh[d], Bl[d], srow, half, rb0, rb1);
            }
            __syncthreads();
        }
    }

#pragma unroll
    for (int mt = 0; mt < 4; mt++) {
#pragma unroll
        for (int rh = 0; rh < 2; rh++) {
            const int m = m0 + wm + mt*16 + qg + rh*8;
#pragma unroll
            for (int nt = 0; nt < 4; nt++) {
                const int n = n0 + wn + nt*8 + rg*2;
                float vx = c[mt][nt][rh*2], vy = c[mt][nt][rh*2 + 1];
                if (bias1) { float2 bb = *(const float2*)(bias1 + n); vx += bb.x; vy += bb.y; }
                if (bias2) { float2 bb = *(const float2*)(bias2 + n); vx += bb.x; vy += bb.y; }
                float* cp = C + (long long)m*ldc + n;
                *(float2*)cp = make_float2(vx, vy);
            }
        }
    }
}

// ---------------- FA2-style flash attention: warp owns 16 rows x all keys ----------------
constexpr int FLASH_SMEM = 98304;
__global__ void __launch_bounds__(256) flash_k(
    const float* __restrict__ qkv, const float* __restrict__ vT, float* __restrict__ r)
{
    extern __shared__ __align__(16) unsigned sm_[];
    unsigned* Qh = sm_;
    unsigned* Ql = Qh + 2048;
    unsigned* Kh = Ql + 2048;
    unsigned* Kl = Kh + 2048;
    unsigned* Vh = Kl + 2048;
    unsigned* Vl = Vh + 8192;

    const int b = blockIdx.z, h = blockIdx.y, q0 = blockIdx.x*128;
    const int tid = threadIdx.x, lane = tid & 31, warp = tid >> 5;
    const int qg = lane >> 2, rg = lane & 3;
    const int wr = warp*16;
    const int srow = tid >> 1, half = tid & 1;
    const int bh = b*4 + h;
    const float sc = 0.17677669529663687f;

    {   // Q: 128 rows x 32 k
        const float* qp = qkv + ((long long)(b*Kk + q0 + srow))*768 + h*32 + half*8;
        stage8(Qh, Ql, srow, half, *(const float4*)qp, *(const float4*)(qp + 4));
        stage8(Qh + 1024, Ql + 1024, srow, half, *(const float4*)(qp + 16), *(const float4*)(qp + 20));
    }

    float co[16][4];
#pragma unroll
    for (int i = 0; i < 16; i++)
#pragma unroll
        for (int k = 0; k < 4; k++) co[i][k] = 0.f;
    float rM0 = -3.0e38f, rM1 = -3.0e38f, rL0 = 0.f, rL1 = 0.f;

    for (int kc = 0; kc < 4; kc++) {
        if (kc) __syncthreads();
        {   // K chunk
            const float* kp_ = qkv + ((long long)(b*Kk + kc*128 + srow))*768 + 128 + h*32 + half*8;
            stage8(Kh, Kl, srow, half, *(const float4*)kp_, *(const float4*)(kp_ + 4));
            stage8(Kh + 1024, Kl + 1024, srow, half, *(const float4*)(kp_ + 16), *(const float4*)(kp_ + 20));
        }
        {   // V chunk (c-major)
            const float* vp = vT + (long long)bh*65536 + (long long)srow*512 + kc*128 + half*8;
#pragma unroll
            for (int j = 0; j < 8; j++)
                stage8(Vh + j*1024, Vl + j*1024, srow, half,
                       *(const float4*)(vp + j*16), *(const float4*)(vp + j*16 + 4));
        }
        __syncthreads();

        // S = Q K^T for this warp's 16 rows
        float cs[16][4];
#pragma unroll
        for (int i = 0; i < 16; i++)
#pragma unroll
            for (int k = 0; k < 4; k++) cs[i][k] = 0.f;
#pragma unroll
        for (int sub = 0; sub < 2; sub++) {
            unsigned ah[4], al[4];
            ah[0] = Qh[sub*1024 + swz(wr + qg, rg)];
            ah[1] = Qh[sub*1024 + swz(wr + qg + 8, rg)];
            ah[2] = Qh[sub*1024 + swz(wr + qg, rg + 4)];
            ah[3] = Qh[sub*1024 + swz(wr + qg + 8, rg + 4)];
            al[0] = Ql[sub*1024 + swz(wr + qg, rg)];
            al[1] = Ql[sub*1024 + swz(wr + qg + 8, rg)];
            al[2] = Ql[sub*1024 + swz(wr + qg, rg + 4)];
            al[3] = Ql[sub*1024 + swz(wr + qg + 8, rg + 4)];
#pragma unroll
            for (int nt = 0; nt < 16; nt++) {
                unsigned b2[2], bl2[2];
                b2[0]  = Kh[sub*1024 + swz(nt*8 + qg, rg)];
                b2[1]  = Kh[sub*1024 + swz(nt*8 + qg, rg + 4)];
                bl2[0] = Kl[sub*1024 + swz(nt*8 + qg, rg)];
                bl2[1] = Kl[sub*1024 + swz(nt*8 + qg, rg + 4)];
                mma16(cs[nt], ah, b2);
                mma16(cs[nt], ah, bl2);
                mma16(cs[nt], al, b2);
            }
        }

        // warp-local online softmax for rows wr+qg, wr+qg+8
        float m0 = -3.0e38f, m1 = -3.0e38f;
#pragma unroll
        for (int nt = 0; nt < 16; nt++) {
            m0 = fmaxf(m0, fmaxf(cs[nt][0], cs[nt][1]));
            m1 = fmaxf(m1, fmaxf(cs[nt][2], cs[nt][3]));
        }
        m0 *= sc; m1 *= sc;
        m0 = fmaxf(m0, __shfl_xor_sync(0xffffffffu, m0, 1));
        m0 = fmaxf(m0, __shfl_xor_sync(0xffffffffu, m0, 2));
        m1 = fmaxf(m1, __shfl_xor_sync(0xffffffffu, m1, 1));
        m1 = fmaxf(m1, __shfl_xor_sync(0xffffffffu, m1, 2));
        const float nm0 = fmaxf(rM0, m0), nm1 = fmaxf(rM1, m1);
        const float a0 = __expf(rM0 - nm0), a1 = __expf(rM1 - nm1);
        float s0 = 0.f, s1 = 0.f;
        unsigned pfh[8][4], pfl[8][4];
#pragma unroll
        for (int nt = 0; nt < 16; nt++) {
            float p0 = __expf(cs[nt][0]*sc - nm0), p1 = __expf(cs[nt][1]*sc - nm0);
            float p2 = __expf(cs[nt][2]*sc - nm1), p3 = __expf(cs[nt][3]*sc - nm1);
            s0 += p0 + p1; s1 += p2 + p3;
            const int j = nt >> 1, o = (nt & 1)*2;
            split2(p0, p1, pfh[j][o],   pfl[j][o]);
            split2(p2, p3, pfh[j][o+1], pfl[j][o+1]);
        }
        s0 += __shfl_xor_sync(0xffffffffu, s0, 1);
        s0 += __shfl_xor_sync(0xffffffffu, s0, 2);
        s1 += __shfl_xor_sync(0xffffffffu, s1, 1);
        s1 += __shfl_xor_sync(0xffffffffu, s1, 2);
        rL0 = rL0*a0 + s0; rL1 = rL1*a1 + s1;
        rM0 = nm0; rM1 = nm1;
#pragma unroll
        for (int nt = 0; nt < 16; nt++) {
            co[nt][0] *= a0; co[nt][1] *= a0;
            co[nt][2] *= a1; co[nt][3] *= a1;
        }
        // O += P @ V  (P A-frags in registers)
#pragma unroll
        for (int j = 0; j < 8; j++) {
#pragma unroll
            for (int nt = 0; nt < 16; nt++) {
                unsigned b2[2], bl2[2];
                b2[0]  = Vh[j*1024 + swz(nt*8 + qg, rg)];
                b2[1]  = Vh[j*1024 + swz(nt*8 + qg, rg + 4)];
                bl2[0] = Vl[j*1024 + swz(nt*8 + qg, rg)];
                bl2[1] = Vl[j*1024 + swz(nt*8 + qg, rg + 4)];
                mma16(co[nt], pfh[j], b2);
                mma16(co[nt], pfh[j], bl2);
                mma16(co[nt], pfl[j], b2);
            }
        }
    }

    const float inv0 = 1.f / rL0, inv1 = 1.f / rL1;
    float* rp0 = r + ((long long)(b*Kk + q0 + wr + qg))*512 + h*128;
    float* rp1 = r + ((long long)(b*Kk + q0 + wr + qg + 8))*512 + h*128;
#pragma unroll
    for (int nt = 0; nt < 16; nt++) {
        const int col = nt*8 + rg*2;
        *(float2*)(rp0 + col) = make_float2(co[nt][0]*inv0, co[nt][1]*inv0);
        *(float2*)(rp1 + col) = make_float2(co[nt][2]*inv1, co[nt][3]*inv1);
    }
}

// ---------------- dilated circular conv as implicit TC GEMM (bf16x3) ----------------
__global__ void __launch_bounds__(256) conv_tc(
    const float* __restrict__ y, const float* __restrict__ wtl,
    const float* __restrict__ cbl, float* __restrict__ state,
    int layer, int dil)
{
    const int tile = blockIdx.x;
    const int b = tile >> 2, k0 = (tile & 3) << 7;
    const float* yb = y + (long long)b*Kk*128;
    __shared__ __align__(16) unsigned Ah[2][1024], Al[2][1024];
    __shared__ __align__(16) unsigned Bh[2][1024], Bl[2][1024];
    const int tid = threadIdx.x;
    const int lane = tid & 31, warp = tid >> 5;
    const int qg = lane >> 2, rg = lane & 3;
    const int wm = (warp & 1)*64, wn = (warp >> 1)*32;

    float c[4][4][4];
#pragma unroll
    for (int i = 0; i < 4; i++)
#pragma unroll
        for (int j = 0; j < 4; j++)
#pragma unroll
            for (int k = 0; k < 4; k++) c[i][j][k] = 0.f;

    const int srow = tid >> 1, half = tid & 1;
    float4 ra0, ra1, rb0, rb1;

    {
        const int src = (k0 + srow - 4*dil + Kk) & (Kk - 1);
        const float* ap = yb + (long long)src*128 + half*8;
        ra0 = *(const float4*)ap; ra1 = *(const float4*)(ap + 4);
        const float* bp = wtl + (long long)srow*128 + half*8;
        rb0 = *(const float4*)bp; rb1 = *(const float4*)(bp + 4);
    }
    stage8(Ah[0], Al[0], srow, half, ra0, ra1);
    stage8(Bh[0], Bl[0], srow, half, rb0, rb1);
    __syncthreads();

    for (int ch = 0; ch < 72; ch++) {
        const int s = ch & 1;
        if (ch + 1 < 72) {
            const int tn = (ch + 1) / 8, icb = (ch + 1) & 7;
            const int kb = icb << 4;
            const int src = (k0 + srow + (tn - 4)*dil + Kk) & (Kk - 1);
            const float* ap = yb + (long long)src*128 + kb + half*8;
            ra0 = *(const float4*)ap; ra1 = *(const float4*)(ap + 4);
            const float* bp = wtl + (long long)tn*16384 + (long long)srow*128 + kb + half*8;
            rb0 = *(const float4*)bp; rb1 = *(const float4*)(bp + 4);
        }
        tile_compute(Ah[s], Al[s], Bh[s], Bl[s], c, qg, rg, wm, wn);
        if (ch + 1 < 72) {
            const int d = s ^ 1;
            stage8(Ah[d], Al[d], srow, half, ra0, ra1);
            stage8(Bh[d], Bl[d], srow, half, rb0, rb1);
        }
        __syncthreads();
    }

#pragma unroll
    for (int mt = 0; mt < 4; mt++) {
#pragma unroll
        for (int rh = 0; rh < 2; rh++) {
            const int pos = k0 + wm + mt*16 + qg + rh*8;
            const long long row = (long long)b*Kk + pos;
#pragma unroll
            for (int nt = 0; nt < 4; nt++) {
                const int n = wn + nt*8 + rg*2;
                float vx = c[mt][nt][rh*2]   + cbl[n];
                float vy = c[mt][nt][rh*2+1] + cbl[n+1];
                vx = fmaxf(vx, 0.f); vy = fmaxf(vy, 0.f);
                const long long sidx = row*1536 + 512 + (long long)layer*128 + n;
                if (layer > 0) {
                    float2 r = *(float2*)&state[sidx - 128];
                    vx += r.x; vy += r.y;
                }
                *(float2*)&state[sidx] = make_float2(vx, vy);
            }
        }
    }
}

// ---------------- transpose x (B,128,K) -> xrows (B*K,128) ----------------
__global__ void __launch_bounds__(256) xtrans_k(const float* __restrict__ x, float* __restrict__ xr)
{
    __shared__ float t[32][33];
    const int c0 = blockIdx.x*32, k0 = blockIdx.y*32, b = blockIdx.z;
    const int tx = threadIdx.x & 31, ty = threadIdx.x >> 5;
#pragma unroll
    for (int i = 0; i < 4; i++)
        t[ty + i*8][tx] = x[(long long)b*65536 + (long long)(c0 + ty + i*8)*Kk + k0 + tx];
    __syncthreads();
#pragma unroll
    for (int i = 0; i < 4; i++)
        xr[((long long)(b*Kk + k0 + ty + i*8))*128 + c0 + tx] = t[tx][ty + i*8];
}

// ---------------- V transpose: qkv -> vT[bh][c][k] ----------------
__global__ void __launch_bounds__(256) vtrans_k(const float* __restrict__ qkv, float* __restrict__ vT)
{
    __shared__ float t[32][33];
    const int c0 = blockIdx.x*32, k0 = blockIdx.y*32, bh = blockIdx.z;
    const int b = bh >> 2, h = bh & 3;
    const int tx = threadIdx.x & 31, ty = threadIdx.x >> 5;
#pragma unroll
    for (int i = 0; i < 4; i++)
        t[ty + i*8][tx] = qkv[((long long)(b*Kk + k0 + ty + i*8))*768 + 256 + h*128 + c0 + tx];
    __syncthreads();
#pragma unroll
    for (int i = 0; i < 4; i++)
        vT[(long long)bh*65536 + (long long)(c0 + ty + i*8)*512 + k0 + tx] = t[tx][ty + i*8];
}

// ---------------- layernorm stats: (mu, inv) per row ----------------
__global__ void __launch_bounds__(256) lnstat_k(
    const float* __restrict__ in, int lda, float* __restrict__ stat)
{
    const int row = blockIdx.x*8 + (threadIdx.x >> 5);
    const int lane = threadIdx.x & 31;
    const float* p = in + (long long)row*lda;
    float x[4];
#pragma unroll
    for (int q = 0; q < 4; q++) x[q] = p[lane + q*32];
    float s = x[0] + x[1] + x[2] + x[3];
#pragma unroll
    for (int off = 16; off; off >>= 1) s += __shfl_xor_sync(0xffffffffu, s, off);
    const float mu = s * (1.f/128.f);
    float v = 0.f;
#pragma unroll
    for (int q = 0; q < 4; q++) { float d = x[q] - mu; v = fmaf(d, d, v); }
#pragma unroll
    for (int off = 16; off; off >>= 1) v += __shfl_xor_sync(0xffffffffu, v, off);
    if (lane == 0) {
        stat[(long long)row*2]     = mu;
        stat[(long long)row*2 + 1] = rsqrtf(v * (1.f/128.f) + 1e-6f);
    }
}

// ---------------- prep kernels ----------------
__global__ void wtrans_k(const float* __restrict__ cw, float* __restrict__ wT)
{
    long long idx = (long long)blockIdx.x*256 + threadIdx.x;
    if (idx >= 8LL*9*128*128) return;
    int i = (int)(idx & 127); long long r = idx >> 7;
    int o = (int)(r & 127); r >>= 7;
    int t = (int)(r % 9); int l = (int)(r / 9);
    wT[idx] = cw[(((long long)l*128 + o)*128 + i)*9 + t];
}

__global__ void qkvpack_k(const float* __restrict__ Wq, const float* __restrict__ Wkm,
                          const float* __restrict__ Wv, float* __restrict__ W)
{
    long long idx = (long long)blockIdx.x*256 + threadIdx.x;
    if (idx >= 8LL*768*128) return;
    int cc = (int)(idx & 127); long long r = idx >> 7;
    int j = (int)(r % 768); int l = (int)(r / 768);
    float v;
    if (j < 128)      v = Wq[((long long)l*128 + cc)*128 + j];
    else if (j < 256) v = Wkm[((long long)l*128 + cc)*128 + (j - 128)];
    else              v = Wv[((long long)l*128 + cc)*512 + (j - 256)];
    W[idx] = v;
}

__global__ void wcT_k(const float* __restrict__ Wc, float* __restrict__ WcT)
{
    long long idx = (long long)blockIdx.x*256 + threadIdx.x;
    if (idx >= 8LL*128*512) return;
    int m = (int)(idx & 511); long long r = idx >> 9;
    int n = (int)(r & 127); int l = (int)(r >> 7);
    WcT[idx] = Wc[((long long)l*512 + m)*128 + n];
}

__global__ void waT_k(const float* __restrict__ Wa, float* __restrict__ WaT)
{
    long long idx = (long long)blockIdx.x*256 + threadIdx.x;
    if (idx >= 8LL*128*256) return;
    int i = (int)(idx & 255); long long r = idx >> 8;
    int o = (int)(r & 127); int l = (int)(r >> 7);
    WaT[idx] = Wa[((long long)l*256 + i)*128 + o];
}

__global__ void p2pad_k(const float* __restrict__ w, float* __restrict__ dst)
{
    int idx = blockIdx.x*256 + threadIdx.x;
    int k = idx & 255, n = idx >> 8;
    dst[idx] = (n < 64) ? w[n*256 + k] : 0.f;
}

__global__ void biaspad_k(const float* __restrict__ b, float* __restrict__ dst)
{
    int j = threadIdx.x;
    dst[j] = (j < 64) ? b[j] : 0.f;
}

// ---------------- max over K (two-stage) + bias -> g (B,256) ----------------
__global__ void __launch_bounds__(256) maxg1_k(
    const float* __restrict__ fus, float* __restrict__ pm)
{
    const int b = blockIdx.x, sl = blockIdx.y, f = threadIdx.x;
    const float* p = fus + (long long)b*Kk*256 + (long long)sl*64*256 + f;
    float mx = -3.0e38f;
    for (int k = 0; k < 64; k++) mx = fmaxf(mx, p[(long long)k*256]);
    pm[((long long)b*8 + sl)*256 + f] = mx;
}
__global__ void __launch_bounds__(256) maxg2_k(
    const float* __restrict__ pm, const float* __restrict__ fb, float* __restrict__ g)
{
    const int b = blockIdx.x, f = threadIdx.x;
    const float* p = pm + (long long)b*8*256 + f;
    float mx = -3.0e38f;
#pragma unroll
    for (int sl = 0; sl < 8; sl++) mx = fmaxf(mx, p[sl*256]);
    g[b*256 + f] = mx + fb[f];
}

__global__ void gfill_k(const float* __restrict__ g, float* __restrict__ state)
{
    long long idx = (long long)blockIdx.x*256 + threadIdx.x;
    int f = (int)(idx & 255); long long row = idx >> 8; int b = (int)(row >> 9);
    state[row*1536 + 256 + f] = g[b*256 + f];
}

// ---------------- LSTM elementwise ----------------
__device__ __forceinline__ float sigm(float x) { return 1.f / (1.f + __expf(-x)); }

__global__ void __launch_bounds__(256) lstm_k(
    const float* __restrict__ gates, const float* __restrict__ c0,
    float* __restrict__ state, float* __restrict__ ho, float* __restrict__ co)
{
    long long idx = (long long)blockIdx.x*256 + threadIdx.x;
    int j = (int)(idx & 255); long long row = idx >> 8;
    const float* gr = gates + row*1024;
    float gi = gr[j], gf = gr[256+j], gg = gr[512+j], go = gr[768+j];
    float c = sigm(gf)*c0[row*256 + j] + sigm(gi)*tanhf(gg);
    float h = sigm(go)*tanhf(c);
    state[row*1536 + j] = h;
    ho[idx] = h;
    co[idx] = c;
}

// ---------------- final p3 ----------------
__global__ void __launch_bounds__(256) p3_k(
    const float* __restrict__ p2, const float* __restrict__ w,
    const float* __restrict__ b3, float* __restrict__ out)
{
    const int row = blockIdx.x*8 + (threadIdx.x >> 5);
    const int lane = threadIdx.x & 31;
    const float* pr = p2 + (long long)row*128;
    float x0 = pr[lane], x1 = pr[lane + 32];
    float s0 = x0*w[lane]      + x1*w[lane + 32];
    float s1 = x0*w[64 + lane] + x1*w[96 + lane];
#pragma unroll
    for (int off = 16; off; off >>= 1) {
        s0 += __shfl_xor_sync(0xffffffffu, s0, off);
        s1 += __shfl_xor_sync(0xffffffffu, s1, off);
    }
    if (lane == 0) {
        int b = row >> 9, k = row & 511;
        out[(long long)b*1024 + k]       = s0 + b3[0];
        out[(long long)b*1024 + 512 + k] = s1 + b3[1];
    }
}

// ---------------- launch ----------------
extern "C" void kernel_launch(void* const* d_in, const int* in_sizes, int n_in,
                              void* d_out, int out_size)
{
    const float* x    = (const float*)d_in[0];
    const float* h0   = (const float*)d_in[1];
    const float* c0   = (const float*)d_in[2];
    const float* ln_g = (const float*)d_in[3];
    const float* ln_b = (const float*)d_in[4];
    const float* Wq   = (const float*)d_in[5];
    const float* Wkm  = (const float*)d_in[6];
    const float* Wv   = (const float*)d_in[7];
    const float* Ww   = (const float*)d_in[8];
    const float* Wa   = (const float*)d_in[9];
    const float* cw   = (const float*)d_in[10];
    const float* cb   = (const float*)d_in[11];
    const float* fus_w = (const float*)d_in[12];
    const float* fus_b = (const float*)d_in[13];
    const float* rs_w  = (const float*)d_in[14];
    const float* rs_b  = (const float*)d_in[15];
    const float* W_ih  = (const float*)d_in[16];
    const float* W_hh  = (const float*)d_in[17];
    const float* b_ih  = (const float*)d_in[18];
    const float* b_hh  = (const float*)d_in[19];
    const float* p1_w  = (const float*)d_in[20];
    const float* p1_b  = (const float*)d_in[21];
    const float* p2_w  = (const float*)d_in[22];
    const float* p2_b  = (const float*)d_in[23];
    const float* p3_w  = (const float*)d_in[24];
    const float* p3_b  = (const float*)d_in[25];
    float* out = (float*)d_out;

    void* sp = nullptr;
    cudaGetSymbolAddress(&sp, d_scratch);
    float* S = (float*)sp;
    float* xrows = S + O_XROWS;
    float* lns   = S + O_LNS;
    float* qkv   = S + O_QKV;
    float* rbuf  = S + O_R;
    float* ybuf  = S + O_Y;
    float* state = S + O_STATE;
    float* fusb  = S + O_FUS;
    float* rnnb  = S + O_RNN;
    float* gates = S + O_GATES;
    float* p1b   = S + O_P1;
    float* p2bf  = S + O_P2;
    float* gbuf  = S + O_G;
    float* pmbuf = S + O_PM;
    float* vT    = S + O_VT;
    float* wT    = S + O_WT;
    float* Wqkv  = S + O_WQKV;
    float* Wc    = S + O_WC;
    float* WcT   = S + O_WCT;
    float* WaT   = S + O_WAT;
    float* p2n   = S + O_P2N;
    float* p2bp  = S + O_P2B;

    cudaFuncSetAttribute(flash_k, cudaFuncAttributeMaxDynamicSharedMemorySize, FLASH_SMEM);

    // ---- prep ----
    xtrans_k<<<dim3(4,16,64), 256>>>(x, xrows);
    wtrans_k<<<(int)((8LL*9*128*128 + 255)/256), 256>>>(cw, wT);
    qkvpack_k<<<(int)((8LL*768*128 + 255)/256), 256>>>(Wq, Wkm, Wv, Wqkv);
    waT_k<<<(int)((8LL*128*256 + 255)/256), 256>>>(Wa, WaT);
    gemm_tc<false,false><<<dim3(4,1,8), 256>>>(
        Ww, 128, 65536, 0,  WaT, 256, 32768, 0,  Wc, 128, 65536, 0, nullptr, 128, 0);
    wcT_k<<<(int)((8LL*128*512 + 255)/256), 256>>>(Wc, WcT);
    p2pad_k<<<128, 256>>>(p2_w, p2n);
    biaspad_k<<<1, 128>>>(p2_b, p2bp);

    static const int DIL[8] = {1,1,1,1,2,2,4,4};
    for (int l = 0; l < 8; l++) {
        const float* inrows = (l == 0) ? xrows : (state + 512 + (l-1)*128);
        int lda = (l == 0) ? 128 : 1536;
        lnstat_k<<<BK/8, 256>>>(inrows, lda, lns);
        gemm_tc<false,false,true><<<dim3(256,6,1), 256>>>(
            inrows, lda, 0, 0,  Wqkv + (long long)l*98304, 128, 0, 0,
            qkv, 768, 0, 0, nullptr, 128, 0,
            lns, ln_g + l*128, ln_b + l*128);
        vtrans_k<<<dim3(4,16,256), 256>>>(qkv, vT);
        flash_k<<<dim3(4,4,64), 256, FLASH_SMEM>>>(qkv, vT, rbuf);
        gemm2_tc<<<dim3(256,1,1), 256>>>(
            rbuf, 512,  WcT + (long long)l*65536, 512, 512,
            inrows, lda,  WaT + (long long)l*32768 + 128, 256, 128,
            ybuf, 128, nullptr, nullptr);
        conv_tc<<<256, 256>>>(ybuf, wT + (long long)l*147456, cb + l*128, state, l, DIL[l]);
    }

    gemm_tc<false,false><<<dim3(256,2,1), 256>>>(
        state + 512, 1536, 0, 0,  fus_w, 1024, 0, 0,
        fusb, 256, 0, 0, nullptr, 1024, 0);
    maxg1_k<<<dim3(64,8), 256>>>(fusb, pmbuf);
    maxg2_k<<<64, 256>>>(pmbuf, fus_b, gbuf);
    gfill_k<<<BK, 256>>>(gbuf, state);
    gemm_tc<false,false><<<dim3(256,2,1), 256>>>(
        state + 256, 1536, 0, 0,  rs_w, 1280, 0, 0,
        rnnb, 256, 0, 0, rs_b, 1280, 0);
    // gates = rnn_in @ W_ih^T + h0 @ W_hh^T + b_ih + b_hh  (merged)
    gemm2_tc<<<dim3(256,8,1), 256>>>(
        rnnb, 256,  W_ih, 256, 256,
        h0, 256,  W_hh, 256, 256,
        gates, 1024, b_ih, b_hh);
    float* ho = out + 65536;
    float* co = out + 65536 + (long long)BK*256;
    lstm_k<<<BK, 256>>>(gates, c0, state, ho, co);
    gemm_tc<false,true><<<dim3(256,2,1), 256>>>(
        state, 1536, 0, 0,  p1_w, 1536, 0, 0,
        p1b, 256, 0, 0, p1_b, 1536, 0);
    gemm_tc<false,true><<<dim3(256,1,1), 256>>>(
        p1b, 256, 0, 0,  p2n, 256, 0, 0,
        p2bf, 128, 0, 0, p2bp, 256, 0);
    p3_k<<<BK/8, 256>>>(p2bf, p3_w, p3_b, out);
}

// round 10
// speedup vs baseline: 2.8279x; 1.0137x over previous
#include <cuda_runtime.h>

#define BK 32768
#define Kk 512

// ---------------- scratch offsets (4-byte units) ----------------
constexpr long long O_XROWS = 0,                      SZ_XROWS = (long long)BK*128;
constexpr long long O_LNS   = O_XROWS + SZ_XROWS,     SZ_LNS   = (long long)BK*2;
constexpr long long O_QKV   = O_LNS + SZ_LNS,         SZ_QKV   = (long long)BK*768;
constexpr long long O_QKH   = O_QKV + SZ_QKV,         SZ_QKH   = (long long)BK*128;
constexpr long long O_QKL   = O_QKH + SZ_QKH,         SZ_QKL   = (long long)BK*128;
constexpr long long O_R     = O_QKL + SZ_QKL,         SZ_R     = (long long)BK*512;
constexpr long long O_VH    = O_R + SZ_R,             SZ_VH    = (long long)BK*256;
constexpr long long O_VL    = O_VH + SZ_VH,           SZ_VL    = (long long)BK*256;
constexpr long long O_YH    = O_VL + SZ_VL,           SZ_YH    = (long long)BK*64;
constexpr long long O_YL    = O_YH + SZ_YH,           SZ_YL    = (long long)BK*64;
constexpr long long O_STATE = O_YL + SZ_YL,           SZ_STATE = (long long)BK*1536;
constexpr long long O_FUS   = O_STATE + SZ_STATE,     SZ_FUS   = (long long)BK*256;
constexpr long long O_RNN   = O_FUS + SZ_FUS,         SZ_RNN   = (long long)BK*256;
constexpr long long O_GATES = O_RNN + SZ_RNN,         SZ_GATES = (long long)BK*1024;
constexpr long long O_P1    = O_GATES + SZ_GATES,     SZ_P1    = (long long)BK*256;
constexpr long long O_P2    = O_P1 + SZ_P1,           SZ_P2    = (long long)BK*128;
constexpr long long O_G     = O_P2 + SZ_P2,           SZ_G     = 64*256;
constexpr long long O_PM    = O_G + SZ_G,             SZ_PM    = 64LL*8*256;
constexpr long long O_WT    = O_PM + SZ_PM,           SZ_WT    = 8LL*9*128*128;
constexpr long long O_WQKV  = O_WT + SZ_WT,           SZ_WQKV  = 8LL*768*128;
constexpr long long O_WC    = O_WQKV + SZ_WQKV,       SZ_WC    = 8LL*512*128;
constexpr long long O_WCT   = O_WC + SZ_WC,           SZ_WCT   = 8LL*128*512;
constexpr long long O_WAT   = O_WCT + SZ_WCT,         SZ_WAT   = 8LL*128*256;
constexpr long long O_P2N   = O_WAT + SZ_WAT,         SZ_P2N   = 128LL*256;
constexpr long long O_P2B   = O_P2N + SZ_P2N,         SZ_P2B   = 128;
// bf16x2 weight planes (word units)
constexpr long long O_WQKVH = O_P2B + SZ_P2B,         SZ_WQKVH = 8LL*768*64;
constexpr long long O_WQKVL = O_WQKVH + SZ_WQKVH;
constexpr long long O_WCTH  = O_WQKVL + SZ_WQKVH,     SZ_WCTH  = 8LL*128*256;
constexpr long long O_WCTL  = O_WCTH + SZ_WCTH;
constexpr long long O_WATH  = O_WCTL + SZ_WCTH,       SZ_WATH  = 8LL*128*128;
constexpr long long O_WATL  = O_WATH + SZ_WATH;
constexpr long long O_WTH   = O_WATL + SZ_WATH,       SZ_WTH   = 8LL*9*128*64;
constexpr long long O_WTL   = O_WTH + SZ_WTH;
constexpr long long O_FUSH  = O_WTL + SZ_WTH,         SZ_FUSH  = 256LL*512;
constexpr long long O_FUSL  = O_FUSH + SZ_FUSH;
constexpr long long O_RSH   = O_FUSL + SZ_FUSH,       SZ_RSH   = 256LL*640;
constexpr long long O_RSL   = O_RSH + SZ_RSH;
constexpr long long O_WIHH  = O_RSL + SZ_RSH,         SZ_WIHH  = 1024LL*128;
constexpr long long O_WIHL  = O_WIHH + SZ_WIHH;
constexpr long long O_WHHH  = O_WIHL + SZ_WIHH,       SZ_WHHH  = 1024LL*128;
constexpr long long O_WHHL  = O_WHHH + SZ_WHHH;
constexpr long long O_P1H   = O_WHHL + SZ_WHHH,       SZ_P1H   = 256LL*768;
constexpr long long O_P1L   = O_P1H + SZ_P1H;
constexpr long long O_P2H   = O_P1L + SZ_P1H,         SZ_P2H   = 128LL*128;
constexpr long long O_P2L   = O_P2H + SZ_P2H;
constexpr long long SCRATCH_TOTAL = O_P2L + SZ_P2H;

__device__ __align__(16) float d_scratch[SCRATCH_TOTAL];

// ---------------- bf16 split helpers ----------------
__device__ __forceinline__ int swz(int row, int kp) {
    return row*8 + (kp ^ (((row >> 2) & 1) << 2));
}
__device__ __forceinline__ void split2(float x, float y, unsigned& h, unsigned& l) {
    asm("cvt.rn.bf16x2.f32 %0, %1, %2;" : "=r"(h) : "f"(y), "f"(x));
    float hx = __uint_as_float(h << 16);
    float hy = __uint_as_float(h & 0xffff0000u);
    asm("cvt.rn.bf16x2.f32 %0, %1, %2;" : "=r"(l) : "f"(y - hy), "f"(x - hx));
}
__device__ __forceinline__ void mma16(float* c, const unsigned* a, const unsigned* b) {
    asm volatile(
        "mma.sync.aligned.m16n8k16.row.col.f32.bf16.bf16.f32 "
        "{%0,%1,%2,%3},{%4,%5,%6,%7},{%8,%9},{%0,%1,%2,%3};"
        : "+f"(c[0]), "+f"(c[1]), "+f"(c[2]), "+f"(c[3])
        : "r"(a[0]), "r"(a[1]), "r"(a[2]), "r"(a[3]), "r"(b[0]), "r"(b[1]));
}

// stage 8 fp32 values (split on the fly)
__device__ __forceinline__ void stage8(unsigned* H, unsigned* L, int row, int half,
                                       float4 v0, float4 v1) {
    unsigned h0,l0,h1,l1,h2,l2,h3,l3;
    split2(v0.x, v0.y, h0, l0); split2(v0.z, v0.w, h1, l1);
    split2(v1.x, v1.y, h2, l2); split2(v1.z, v1.w, h3, l3);
    const int kpb = (half*4) ^ (((row >> 2) & 1) << 2);
    *(uint4*)&H[row*8 + kpb] = make_uint4(h0, h1, h2, h3);
    *(uint4*)&L[row*8 + kpb] = make_uint4(l0, l1, l2, l3);
}
// stage 8 pre-split words (no math)
__device__ __forceinline__ void stage8w(unsigned* H, unsigned* L, int row, int half,
                                        uint4 hv, uint4 lv) {
    const int kpb = (half*4) ^ (((row >> 2) & 1) << 2);
    *(uint4*)&H[row*8 + kpb] = hv;
    *(uint4*)&L[row*8 + kpb] = lv;
}

__device__ __forceinline__ void tile_compute(
    const unsigned* __restrict__ Ah, const unsigned* __restrict__ Al,
    const unsigned* __restrict__ Bh, const unsigned* __restrict__ Bl,
    float c[4][4][4], int qg, int rg, int wm, int wn)
{
    unsigned ah[4][4], al[4][4], bh[4][2], bl[4][2];
#pragma unroll
    for (int mt = 0; mt < 4; mt++) {
        const int r0 = wm + mt*16 + qg, r1 = r0 + 8;
        ah[mt][0] = Ah[swz(r0, rg)];   ah[mt][1] = Ah[swz(r1, rg)];
        ah[mt][2] = Ah[swz(r0, rg+4)]; ah[mt][3] = Ah[swz(r1, rg+4)];
        al[mt][0] = Al[swz(r0, rg)];   al[mt][1] = Al[swz(r1, rg)];
        al[mt][2] = Al[swz(r0, rg+4)]; al[mt][3] = Al[swz(r1, rg+4)];
    }
#pragma unroll
    for (int nt = 0; nt < 4; nt++) {
        const int col = wn + nt*8 + qg;
        bh[nt][0] = Bh[swz(col, rg)]; bh[nt][1] = Bh[swz(col, rg+4)];
        bl[nt][0] = Bl[swz(col, rg)]; bl[nt][1] = Bl[swz(col, rg+4)];
    }
#pragma unroll
    for (int mt = 0; mt < 4; mt++)
#pragma unroll
        for (int nt = 0; nt < 4; nt++) {
            mma16(c[mt][nt], ah[mt], bh[nt]);
            mma16(c[mt][nt], ah[mt], bl[nt]);
            mma16(c[mt][nt], al[mt], bh[nt]);
        }
}

// ---------------- tensor-core GEMM (bf16x3), B pre-split planes ----------------
// C = A(M,Kd) @ Bn^T;  BH/BL words [N][Kd/2]
// QKP: for n0<256 write split planes qkH/qkL instead of fp32 C (qkv Q/K region)
template<bool RELU, bool LNA, bool QKP>
__global__ void __launch_bounds__(256) gemm_tc(
    const float* __restrict__ A, int lda, long long sA,
    const unsigned* __restrict__ BH, const unsigned* __restrict__ BL, int ldbw, long long sBw,
    float* __restrict__ C, int ldc, long long sC,
    const float* __restrict__ bias, int Kd,
    const float* __restrict__ lnstat = nullptr,
    const float* __restrict__ lg = nullptr,
    const float* __restrict__ lb = nullptr,
    unsigned* __restrict__ qkH = nullptr, unsigned* __restrict__ qkL = nullptr)
{
    const int bz = blockIdx.z;
    A  += (long long)bz*sA;
    BH += (long long)bz*sBw;  BL += (long long)bz*sBw;
    C  += (long long)bz*sC;
    const int m0 = blockIdx.x*128, n0 = blockIdx.y*128;
    __shared__ __align__(16) unsigned Ah[2][1024], Al[2][1024];
    __shared__ __align__(16) unsigned Bh[2][1024], Bl[2][1024];
    const int tid = threadIdx.x;
    const int lane = tid & 31, warp = tid >> 5;
    const int qg = lane >> 2, rg = lane & 3;
    const int wm = (warp & 1)*64, wn = (warp >> 1)*32;

    float c[4][4][4];
#pragma unroll
    for (int i = 0; i < 4; i++)
#pragma unroll
        for (int j = 0; j < 4; j++)
#pragma unroll
            for (int k = 0; k < 4; k++) c[i][j][k] = 0.f;

    const int srow = tid >> 1, half = tid & 1;
    const float* Ap = A + (long long)(m0 + srow)*lda + half*8;
    const long long bW = (long long)(n0 + srow)*ldbw + half*4;
    const int nc = Kd >> 4;

    float mu = 0.f, inv = 1.f;
    if (LNA) {
        mu  = lnstat[(long long)(m0 + srow)*2];
        inv = lnstat[(long long)(m0 + srow)*2 + 1];
    }

    float4 ra0, ra1; uint4 rbh, rbl;
    ra0 = *(const float4*)Ap;  ra1 = *(const float4*)(Ap + 4);
    rbh = *(const uint4*)&BH[bW];  rbl = *(const uint4*)&BL[bW];
    if (LNA) {
        float4 g0 = *(const float4*)(lg + half*8), g1 = *(const float4*)(lg + half*8 + 4);
        float4 b0 = *(const float4*)(lb + half*8), b1 = *(const float4*)(lb + half*8 + 4);
        ra0.x = (ra0.x - mu)*inv*g0.x + b0.x; ra0.y = (ra0.y - mu)*inv*g0.y + b0.y;
        ra0.z = (ra0.z - mu)*inv*g0.z + b0.z; ra0.w = (ra0.w - mu)*inv*g0.w + b0.w;
        ra1.x = (ra1.x - mu)*inv*g1.x + b1.x; ra1.y = (ra1.y - mu)*inv*g1.y + b1.y;
        ra1.z = (ra1.z - mu)*inv*g1.z + b1.z; ra1.w = (ra1.w - mu)*inv*g1.w + b1.w;
    }
    stage8(Ah[0], Al[0], srow, half, ra0, ra1);
    stage8w(Bh[0], Bl[0], srow, half, rbh, rbl);
    __syncthreads();

    for (int ch = 0; ch < nc; ch++) {
        const int s = ch & 1;
        if (ch + 1 < nc) {
            const int kb = (ch + 1) << 4;
            ra0 = *(const float4*)(Ap + kb); ra1 = *(const float4*)(Ap + kb + 4);
            rbh = *(const uint4*)&BH[bW + (ch + 1)*8];
            rbl = *(const uint4*)&BL[bW + (ch + 1)*8];
            if (LNA) {
                float4 g0 = *(const float4*)(lg + kb + half*8), g1 = *(const float4*)(lg + kb + half*8 + 4);
                float4 b0 = *(const float4*)(lb + kb + half*8), b1 = *(const float4*)(lb + kb + half*8 + 4);
                ra0.x = (ra0.x - mu)*inv*g0.x + b0.x; ra0.y = (ra0.y - mu)*inv*g0.y + b0.y;
                ra0.z = (ra0.z - mu)*inv*g0.z + b0.z; ra0.w = (ra0.w - mu)*inv*g0.w + b0.w;
                ra1.x = (ra1.x - mu)*inv*g1.x + b1.x; ra1.y = (ra1.y - mu)*inv*g1.y + b1.y;
                ra1.z = (ra1.z - mu)*inv*g1.z + b1.z; ra1.w = (ra1.w - mu)*inv*g1.w + b1.w;
            }
        }
        tile_compute(Ah[s], Al[s], Bh[s], Bl[s], c, qg, rg, wm, wn);
        if (ch + 1 < nc) {
            const int d = s ^ 1;
            stage8(Ah[d], Al[d], srow, half, ra0, ra1);
            stage8w(Bh[d], Bl[d], srow, half, rbh, rbl);
        }
        __syncthreads();
    }

    const bool planeOut = QKP && (n0 < 256);
#pragma unroll
    for (int mt = 0; mt < 4; mt++) {
#pragma unroll
        for (int rh = 0; rh < 2; rh++) {
            const int m = m0 + wm + mt*16 + qg + rh*8;
#pragma unroll
            for (int nt = 0; nt < 4; nt++) {
                const int n = n0 + wn + nt*8 + rg*2;
                float vx = c[mt][nt][rh*2], vy = c[mt][nt][rh*2 + 1];
                if (bias) { float2 bb = *(const float2*)(bias + n); vx += bb.x; vy += bb.y; }
                if (RELU) { vx = fmaxf(vx, 0.f); vy = fmaxf(vy, 0.f); }
                if (planeOut) {
                    unsigned hw, lw; split2(vx, vy, hw, lw);
                    const long long w = (long long)m*128 + (n >> 1);
                    qkH[w] = hw; qkL[w] = lw;
                } else {
                    *(float2*)(C + (long long)m*ldc + n) = make_float2(vx, vy);
                }
            }
        }
    }
}

// ---------------- dual-source GEMM: C = A1@B1^T + A2@B2^T; optional plane output ----------------
__global__ void __launch_bounds__(256) gemm2_tc(
    const float* __restrict__ A1, int lda1,
    const unsigned* __restrict__ B1H, const unsigned* __restrict__ B1L, int ldb1w, int Kd1,
    const float* __restrict__ A2, int lda2,
    const unsigned* __restrict__ B2H, const unsigned* __restrict__ B2L, int ldb2w, int Kd2,
    float* __restrict__ C, int ldc,
    const float* __restrict__ bias1, const float* __restrict__ bias2,
    unsigned* __restrict__ YH, unsigned* __restrict__ YL)
{
    const int m0 = blockIdx.x*128, n0 = blockIdx.y*128;
    __shared__ __align__(16) unsigned Ah[2][1024], Al[2][1024];
    __shared__ __align__(16) unsigned Bh[2][1024], Bl[2][1024];
    const int tid = threadIdx.x;
    const int lane = tid & 31, warp = tid >> 5;
    const int qg = lane >> 2, rg = lane & 3;
    const int wm = (warp & 1)*64, wn = (warp >> 1)*32;

    float c[4][4][4];
#pragma unroll
    for (int i = 0; i < 4; i++)
#pragma unroll
        for (int j = 0; j < 4; j++)
#pragma unroll
            for (int k = 0; k < 4; k++) c[i][j][k] = 0.f;

    const int srow = tid >> 1, half = tid & 1;

    for (int pass = 0; pass < 2; pass++) {
        const float* Ap = (pass == 0 ? A1 : A2) + (long long)(m0 + srow)*(pass == 0 ? lda1 : lda2) + half*8;
        const unsigned* BHp = (pass == 0 ? B1H : B2H);
        const unsigned* BLp = (pass == 0 ? B1L : B2L);
        const int ldw = (pass == 0 ? ldb1w : ldb2w);
        const long long bW = (long long)(n0 + srow)*ldw + half*4;
        const int nc = (pass == 0 ? Kd1 : Kd2) >> 4;

        float4 ra0 = *(const float4*)Ap, ra1 = *(const float4*)(Ap + 4);
        uint4 rbh = *(const uint4*)&BHp[bW], rbl = *(const uint4*)&BLp[bW];
        stage8(Ah[0], Al[0], srow, half, ra0, ra1);
        stage8w(Bh[0], Bl[0], srow, half, rbh, rbl);
        __syncthreads();

        for (int ch = 0; ch < nc; ch++) {
            const int s = ch & 1;
            if (ch + 1 < nc) {
                const int kb = (ch + 1) << 4;
                ra0 = *(const float4*)(Ap + kb); ra1 = *(const float4*)(Ap + kb + 4);
                rbh = *(const uint4*)&BHp[bW + (ch + 1)*8];
                rbl = *(const uint4*)&BLp[bW + (ch + 1)*8];
            }
            tile_compute(Ah[s], Al[s], Bh[s], Bl[s], c, qg, rg, wm, wn);
            if (ch + 1 < nc) {
                const int d = s ^ 1;
                stage8(Ah[d], Al[d], srow, half, ra0, ra1);
                stage8w(Bh[d], Bl[d], srow, half, rbh, rbl);
            }
            __syncthreads();
        }
    }

#pragma unroll
    for (int mt = 0; mt < 4; mt++) {
#pragma unroll
        for (int rh = 0; rh < 2; rh++) {
            const int m = m0 + wm + mt*16 + qg + rh*8;
#pragma unroll
            for (int nt = 0; nt < 4; nt++) {
                const int n = n0 + wn + nt*8 + rg*2;
                float vx = c[mt][nt][rh*2], vy = c[mt][nt][rh*2 + 1];
                if (bias1) { float2 bb = *(const float2*)(bias1 + n); vx += bb.x; vy += bb.y; }
                if (bias2) { float2 bb = *(const float2*)(bias2 + n); vx += bb.x; vy += bb.y; }
                if (YH) {
                    unsigned hw, lw; split2(vx, vy, hw, lw);
                    const long long w = (long long)m*64 + (n >> 1);
                    YH[w] = hw; YL[w] = lw;
                } else {
                    *(float2*)(C + (long long)m*ldc + n) = make_float2(vx, vy);
                }
            }
        }
    }
}

// ---------------- FA2 flash: all operands pre-split planes ----------------
constexpr int FLASH_SMEM = 98304;
__global__ void __launch_bounds__(256) flash_k(
    const unsigned* __restrict__ QKH, const unsigned* __restrict__ QKL,
    const unsigned* __restrict__ VH, const unsigned* __restrict__ VL,
    float* __restrict__ r)
{
    extern __shared__ __align__(16) unsigned sm_[];
    unsigned* Qh = sm_;
    unsigned* Ql = Qh + 2048;
    unsigned* Kh = Ql + 2048;
    unsigned* Kl = Kh + 2048;
    unsigned* Vh = Kl + 2048;
    unsigned* Vl = Vh + 8192;

    const int b = blockIdx.z, h = blockIdx.y, q0 = blockIdx.x*128;
    const int tid = threadIdx.x, lane = tid & 31, warp = tid >> 5;
    const int qg = lane >> 2, rg = lane & 3;
    const int wr = warp*16;
    const int srow = tid >> 1, half = tid & 1;
    const int bh = b*4 + h;
    const float sc = 0.17677669529663687f;

    {   // Q: 128 rows x 32 ch = 16 words
        const long long qb = (long long)(b*Kk + q0 + srow)*128 + h*16 + half*4;
        stage8w(Qh, Ql, srow, half, *(const uint4*)&QKH[qb], *(const uint4*)&QKL[qb]);
        stage8w(Qh + 1024, Ql + 1024, srow, half, *(const uint4*)&QKH[qb + 8], *(const uint4*)&QKL[qb + 8]);
    }

    float co[16][4];
#pragma unroll
    for (int i = 0; i < 16; i++)
#pragma unroll
        for (int k = 0; k < 4; k++) co[i][k] = 0.f;
    float rM0 = -3.0e38f, rM1 = -3.0e38f, rL0 = 0.f, rL1 = 0.f;

    for (int kc = 0; kc < 4; kc++) {
        if (kc) __syncthreads();
        {   // K chunk
            const long long kb = (long long)(b*Kk + kc*128 + srow)*128 + 64 + h*16 + half*4;
            stage8w(Kh, Kl, srow, half, *(const uint4*)&QKH[kb], *(const uint4*)&QKL[kb]);
            stage8w(Kh + 1024, Kl + 1024, srow, half, *(const uint4*)&QKH[kb + 8], *(const uint4*)&QKL[kb + 8]);
        }
        {   // V chunk: row=channel, 128 k = 64 words
            const long long vb = ((long long)bh << 15) + (long long)srow*256 + kc*64 + half*4;
#pragma unroll
            for (int j = 0; j < 8; j++)
                stage8w(Vh + j*1024, Vl + j*1024, srow, half,
                        *(const uint4*)&VH[vb + j*8], *(const uint4*)&VL[vb + j*8]);
        }
        __syncthreads();

        float cs[16][4];
#pragma unroll
        for (int i = 0; i < 16; i++)
#pragma unroll
            for (int k = 0; k < 4; k++) cs[i][k] = 0.f;
#pragma unroll
        for (int sub = 0; sub < 2; sub++) {
            unsigned ah[4], al[4];
            ah[0] = Qh[sub*1024 + swz(wr + qg, rg)];
            ah[1] = Qh[sub*1024 + swz(wr + qg + 8, rg)];
            ah[2] = Qh[sub*1024 + swz(wr + qg, rg + 4)];
            ah[3] = Qh[sub*1024 + swz(wr + qg + 8, rg + 4)];
            al[0] = Ql[sub*1024 + swz(wr + qg, rg)];
            al[1] = Ql[sub*1024 + swz(wr + qg + 8, rg)];
            al[2] = Ql[sub*1024 + swz(wr + qg, rg + 4)];
            al[3] = Ql[sub*1024 + swz(wr + qg + 8, rg + 4)];
#pragma unroll
            for (int nt = 0; nt < 16; nt++) {
                unsigned b2[2], bl2[2];
                b2[0]  = Kh[sub*1024 + swz(nt*8 + qg, rg)];
                b2[1]  = Kh[sub*1024 + swz(nt*8 + qg, rg + 4)];
                bl2[0] = Kl[sub*1024 + swz(nt*8 + qg, rg)];
                bl2[1] = Kl[sub*1024 + swz(nt*8 + qg, rg + 4)];
                mma16(cs[nt], ah, b2);
                mma16(cs[nt], ah, bl2);
                mma16(cs[nt], al, b2);
            }
        }

        float m0 = -3.0e38f, m1 = -3.0e38f;
#pragma unroll
        for (int nt = 0; nt < 16; nt++) {
            m0 = fmaxf(m0, fmaxf(cs[nt][0], cs[nt][1]));
            m1 = fmaxf(m1, fmaxf(cs[nt][2], cs[nt][3]));
        }
        m0 *= sc; m1 *= sc;
        m0 = fmaxf(m0, __shfl_xor_sync(0xffffffffu, m0, 1));
        m0 = fmaxf(m0, __shfl_xor_sync(0xffffffffu, m0, 2));
        m1 = fmaxf(m1, __shfl_xor_sync(0xffffffffu, m1, 1));
        m1 = fmaxf(m1, __shfl_xor_sync(0xffffffffu, m1, 2));
        const float nm0 = fmaxf(rM0, m0), nm1 = fmaxf(rM1, m1);
        const float a0 = __expf(rM0 - nm0), a1 = __expf(rM1 - nm1);
        float s0 = 0.f, s1 = 0.f;
        unsigned pfh[8][4], pfl[8][4];
#pragma unroll
        for (int nt = 0; nt < 16; nt++) {
            float p0 = __expf(cs[nt][0]*sc - nm0), p1 = __expf(cs[nt][1]*sc - nm0);
            float p2 = __expf(cs[nt][2]*sc - nm1), p3 = __expf(cs[nt][3]*sc - nm1);
            s0 += p0 + p1; s1 += p2 + p3;
            const int j = nt >> 1, o = (nt & 1)*2;
            split2(p0, p1, pfh[j][o],   pfl[j][o]);
            split2(p2, p3, pfh[j][o+1], pfl[j][o+1]);
        }
        s0 += __shfl_xor_sync(0xffffffffu, s0, 1);
        s0 += __shfl_xor_sync(0xffffffffu, s0, 2);
        s1 += __shfl_xor_sync(0xffffffffu, s1, 1);
        s1 += __shfl_xor_sync(0xffffffffu, s1, 2);
        rL0 = rL0*a0 + s0; rL1 = rL1*a1 + s1;
        rM0 = nm0; rM1 = nm1;
#pragma unroll
        for (int nt = 0; nt < 16; nt++) {
            co[nt][0] *= a0; co[nt][1] *= a0;
            co[nt][2] *= a1; co[nt][3] *= a1;
        }
#pragma unroll
        for (int j = 0; j < 8; j++) {
#pragma unroll
            for (int nt = 0; nt < 16; nt++) {
                unsigned b2[2], bl2[2];
                b2[0]  = Vh[j*1024 + swz(nt*8 + qg, rg)];
                b2[1]  = Vh[j*1024 + swz(nt*8 + qg, rg + 4)];
                bl2[0] = Vl[j*1024 + swz(nt*8 + qg, rg)];
                bl2[1] = Vl[j*1024 + swz(nt*8 + qg, rg + 4)];
                mma16(co[nt], pfh[j], b2);
                mma16(co[nt], pfh[j], bl2);
                mma16(co[nt], pfl[j], b2);
            }
        }
    }

    const float inv0 = 1.f / rL0, inv1 = 1.f / rL1;
    float* rp0 = r + ((long long)(b*Kk + q0 + wr + qg))*512 + h*128;
    float* rp1 = r + ((long long)(b*Kk + q0 + wr + qg + 8))*512 + h*128;
#pragma unroll
    for (int nt = 0; nt < 16; nt++) {
        const int col = nt*8 + rg*2;
        *(float2*)(rp0 + col) = make_float2(co[nt][0]*inv0, co[nt][1]*inv0);
        *(float2*)(rp1 + col) = make_float2(co[nt][2]*inv1, co[nt][3]*inv1);
    }
}

// ---------------- conv: A from Y planes, B from WT planes (no cvt) ----------------
__global__ void __launch_bounds__(256) conv_tc(
    const unsigned* __restrict__ YH, const unsigned* __restrict__ YL,
    const unsigned* __restrict__ WH, const unsigned* __restrict__ WL,
    const float* __restrict__ cbl, float* __restrict__ state,
    int layer, int dil)
{
    const int tile = blockIdx.x;
    const int b = tile >> 2, k0 = (tile & 3) << 7;
    __shared__ __align__(16) unsigned Ah[2][1024], Al[2][1024];
    __shared__ __align__(16) unsigned Bh[2][1024], Bl[2][1024];
    const int tid = threadIdx.x;
    const int lane = tid & 31, warp = tid >> 5;
    const int qg = lane >> 2, rg = lane & 3;
    const int wm = (warp & 1)*64, wn = (warp >> 1)*32;

    float c[4][4][4];
#pragma unroll
    for (int i = 0; i < 4; i++)
#pragma unroll
        for (int j = 0; j < 4; j++)
#pragma unroll
            for (int k = 0; k < 4; k++) c[i][j][k] = 0.f;

    const int srow = tid >> 1, half = tid & 1;
    uint4 rah, ral, rbh, rbl;

    {
        const int src = b*Kk + ((k0 + srow - 4*dil + Kk) & (Kk - 1));
        const long long aw = (long long)src*64 + half*4;
        rah = *(const uint4*)&YH[aw]; ral = *(const uint4*)&YL[aw];
        const long long bw = (long long)srow*64 + half*4;
        rbh = *(const uint4*)&WH[bw]; rbl = *(const uint4*)&WL[bw];
    }
    stage8w(Ah[0], Al[0], srow, half, rah, ral);
    stage8w(Bh[0], Bl[0], srow, half, rbh, rbl);
    __syncthreads();

    for (int ch = 0; ch < 72; ch++) {
        const int s = ch & 1;
        if (ch + 1 < 72) {
            const int tn = (ch + 1) / 8, icb = (ch + 1) & 7;
            const int src = b*Kk + ((k0 + srow + (tn - 4)*dil + Kk) & (Kk - 1));
            const long long aw = (long long)src*64 + icb*8 + half*4;
            rah = *(const uint4*)&YH[aw]; ral = *(const uint4*)&YL[aw];
            const long long bw = (long long)tn*8192 + (long long)srow*64 + icb*8 + half*4;
            rbh = *(const uint4*)&WH[bw]; rbl = *(const uint4*)&WL[bw];
        }
        tile_compute(Ah[s], Al[s], Bh[s], Bl[s], c, qg, rg, wm, wn);
        if (ch + 1 < 72) {
            const int d = s ^ 1;
            stage8w(Ah[d], Al[d], srow, half, rah, ral);
            stage8w(Bh[d], Bl[d], srow, half, rbh, rbl);
        }
        __syncthreads();
    }

#pragma unroll
    for (int mt = 0; mt < 4; mt++) {
#pragma unroll
        for (int rh = 0; rh < 2; rh++) {
            const int pos = k0 + wm + mt*16 + qg + rh*8;
            const long long row = (long long)b*Kk + pos;
#pragma unroll
            for (int nt = 0; nt < 4; nt++) {
                const int n = wn + nt*8 + rg*2;
                float vx = c[mt][nt][rh*2]   + cbl[n];
                float vy = c[mt][nt][rh*2+1] + cbl[n+1];
                vx = fmaxf(vx, 0.f); vy = fmaxf(vy, 0.f);
                const long long sidx = row*1536 + 512 + (long long)layer*128 + n;
                if (layer > 0) {
                    float2 r = *(float2*)&state[sidx - 128];
                    vx += r.x; vy += r.y;
                }
                *(float2*)&state[sidx] = make_float2(vx, vy);
            }
        }
    }
}

// ---------------- transpose x ----------------
__global__ void __launch_bounds__(256) xtrans_k(const float* __restrict__ x, float* __restrict__ xr)
{
    __shared__ float t[32][33];
    const int c0 = blockIdx.x*32, k0 = blockIdx.y*32, b = blockIdx.z;
    const int tx = threadIdx.x & 31, ty = threadIdx.x >> 5;
#pragma unroll
    for (int i = 0; i < 4; i++)
        t[ty + i*8][tx] = x[(long long)b*65536 + (long long)(c0 + ty + i*8)*Kk + k0 + tx];
    __syncthreads();
#pragma unroll
    for (int i = 0; i < 4; i++)
        xr[((long long)(b*Kk + k0 + ty + i*8))*128 + c0 + tx] = t[tx][ty + i*8];
}

// ---------------- V transpose -> split planes ----------------
__global__ void __launch_bounds__(256) vtrans_k(const float* __restrict__ qkv,
                                                unsigned* __restrict__ VH, unsigned* __restrict__ VL)
{
    __shared__ float t[32][33];
    const int c0 = blockIdx.x*32, k0 = blockIdx.y*32, bh = blockIdx.z;
    const int b = bh >> 2, h = bh & 3;
    const int tx = threadIdx.x & 31, ty = threadIdx.x >> 5;
#pragma unroll
    for (int i = 0; i < 4; i++)
        t[ty + i*8][tx] = qkv[((long long)(b*Kk + k0 + ty + i*8))*768 + 256 + h*128 + c0 + tx];
    __syncthreads();
#pragma unroll
    for (int it = 0; it < 2; it++) {
        const int idx = threadIdx.x + it*256;
        const int cl = idx >> 4, kp = idx & 15;
        unsigned hw, lw;
        split2(t[kp*2][cl], t[kp*2 + 1][cl], hw, lw);
        const long long w = ((long long)bh << 15) + (long long)(c0 + cl)*256 + (k0 >> 1) + kp;
        VH[w] = hw; VL[w] = lw;
    }
}

// ---------------- layernorm stats ----------------
__global__ void __launch_bounds__(256) lnstat_k(
    const float* __restrict__ in, int lda, float* __restrict__ stat)
{
    const int row = blockIdx.x*8 + (threadIdx.x >> 5);
    const int lane = threadIdx.x & 31;
    const float* p = in + (long long)row*lda;
    float x[4];
#pragma unroll
    for (int q = 0; q < 4; q++) x[q] = p[lane + q*32];
    float s = x[0] + x[1] + x[2] + x[3];
#pragma unroll
    for (int off = 16; off; off >>= 1) s += __shfl_xor_sync(0xffffffffu, s, off);
    const float mu = s * (1.f/128.f);
    float v = 0.f;
#pragma unroll
    for (int q = 0; q < 4; q++) { float d = x[q] - mu; v = fmaf(d, d, v); }
#pragma unroll
    for (int off = 16; off; off >>= 1) v += __shfl_xor_sync(0xffffffffu, v, off);
    if (lane == 0) {
        stat[(long long)row*2]     = mu;
        stat[(long long)row*2 + 1] = rsqrtf(v * (1.f/128.f) + 1e-6f);
    }
}

// ---------------- prep kernels ----------------
__global__ void wtrans_k(const float* __restrict__ cw, float* __restrict__ wT)
{
    long long idx = (long long)blockIdx.x*256 + threadIdx.x;
    if (idx >= 8LL*9*128*128) return;
    int i = (int)(idx & 127); long long r = idx >> 7;
    int o = (int)(r & 127); r >>= 7;
    int t = (int)(r % 9); int l = (int)(r / 9);
    wT[idx] = cw[(((long long)l*128 + o)*128 + i)*9 + t];
}

__global__ void qkvpack_k(const float* __restrict__ Wq, const float* __restrict__ Wkm,
                          const float* __restrict__ Wv, float* __restrict__ W)
{
    long long idx = (long long)blockIdx.x*256 + threadIdx.x;
    if (idx >= 8LL*768*128) return;
    int cc = (int)(idx & 127); long long r = idx >> 7;
    int j = (int)(r % 768); int l = (int)(r / 768);
    float v;
    if (j < 128)      v = Wq[((long long)l*128 + cc)*128 + j];
    else if (j < 256) v = Wkm[((long long)l*128 + cc)*128 + (j - 128)];
    else              v = Wv[((long long)l*128 + cc)*512 + (j - 256)];
    W[idx] = v;
}

__global__ void wcT_k(const float* __restrict__ Wc, float* __restrict__ WcT)
{
    long long idx = (long long)blockIdx.x*256 + threadIdx.x;
    if (idx >= 8LL*128*512) return;
    int m = (int)(idx & 511); long long r = idx >> 9;
    int n = (int)(r & 127); int l = (int)(r >> 7);
    WcT[idx] = Wc[((long long)l*512 + m)*128 + n];
}

__global__ void waT_k(const float* __restrict__ Wa, float* __restrict__ WaT)
{
    long long idx = (long long)blockIdx.x*256 + threadIdx.x;
    if (idx >= 8LL*128*256) return;
    int i = (int)(idx & 255); long long r = idx >> 8;
    int o = (int)(r & 127); int l = (int)(r >> 7);
    WaT[idx] = Wa[((long long)l*256 + i)*128 + o];
}

__global__ void p2pad_k(const float* __restrict__ w, float* __restrict__ dst)
{
    int idx = blockIdx.x*256 + threadIdx.x;
    int k = idx & 255, n = idx >> 8;
    dst[idx] = (n < 64) ? w[n*256 + k] : 0.f;
}

__global__ void biaspad_k(const float* __restrict__ b, float* __restrict__ dst)
{
    int j = threadIdx.x;
    dst[j] = (j < 64) ? b[j] : 0.f;
}

// split fp32 matrix into bf16x2 hi/lo word planes
__global__ void wsplit_k(const float* __restrict__ src,
                         unsigned* __restrict__ H, unsigned* __restrict__ L, long long nwords)
{
    long long w = (long long)blockIdx.x*256 + threadIdx.x;
    if (w >= nwords) return;
    unsigned hw, lw;
    split2(src[w*2], src[w*2 + 1], hw, lw);
    H[w] = hw; L[w] = lw;
}

// ---------------- max over K (two-stage) + bias -> g ----------------
__global__ void __launch_bounds__(256) maxg1_k(
    const float* __restrict__ fus, float* __restrict__ pm)
{
    const int b = blockIdx.x, sl = blockIdx.y, f = threadIdx.x;
    const float* p = fus + (long long)b*Kk*256 + (long long)sl*64*256 + f;
    float mx = -3.0e38f;
    for (int k = 0; k < 64; k++) mx = fmaxf(mx, p[(long long)k*256]);
    pm[((long long)b*8 + sl)*256 + f] = mx;
}
__global__ void __launch_bounds__(256) maxg2_k(
    const float* __restrict__ pm, const float* __restrict__ fb, float* __restrict__ g)
{
    const int b = blockIdx.x, f = threadIdx.x;
    const float* p = pm + (long long)b*8*256 + f;
    float mx = -3.0e38f;
#pragma unroll
    for (int sl = 0; sl < 8; sl++) mx = fmaxf(mx, p[sl*256]);
    g[b*256 + f] = mx + fb[f];
}

__global__ void gfill_k(const float* __restrict__ g, float* __restrict__ state)
{
    long long idx = (long long)blockIdx.x*256 + threadIdx.x;
    int f = (int)(idx & 255); long long row = idx >> 8; int b = (int)(row >> 9);
    state[row*1536 + 256 + f] = g[b*256 + f];
}

// ---------------- LSTM elementwise ----------------
__device__ __forceinline__ float sigm(float x) { return 1.f / (1.f + __expf(-x)); }

__global__ void __launch_bounds__(256) lstm_k(
    const float* __restrict__ gates, const float* __restrict__ c0,
    float* __restrict__ state, float* __restrict__ ho, float* __restrict__ co)
{
    long long idx = (long long)blockIdx.x*256 + threadIdx.x;
    int j = (int)(idx & 255); long long row = idx >> 8;
    const float* gr = gates + row*1024;
    float gi = gr[j], gf = gr[256+j], gg = gr[512+j], go = gr[768+j];
    float c = sigm(gf)*c0[row*256 + j] + sigm(gi)*tanhf(gg);
    float h = sigm(go)*tanhf(c);
    state[row*1536 + j] = h;
    ho[idx] = h;
    co[idx] = c;
}

// ---------------- final p3 ----------------
__global__ void __launch_bounds__(256) p3_k(
    const float* __restrict__ p2, const float* __restrict__ w,
    const float* __restrict__ b3, float* __restrict__ out)
{
    const int row = blockIdx.x*8 + (threadIdx.x >> 5);
    const int lane = threadIdx.x & 31;
    const float* pr = p2 + (long long)row*128;
    float x0 = pr[lane], x1 = pr[lane + 32];
    float s0 = x0*w[lane]      + x1*w[lane + 32];
    float s1 = x0*w[64 + lane] + x1*w[96 + lane];
#pragma unroll
    for (int off = 16; off; off >>= 1) {
        s0 += __shfl_xor_sync(0xffffffffu, s0, off);
        s1 += __shfl_xor_sync(0xffffffffu, s1, off);
    }
    if (lane == 0) {
        int b = row >> 9, k = row & 511;
        out[(long long)b*1024 + k]       = s0 + b3[0];
        out[(long long)b*1024 + 512 + k] = s1 + b3[1];
    }
}

// ---------------- launch ----------------
extern "C" void kernel_launch(void* const* d_in, const int* in_sizes, int n_in,
                              void* d_out, int out_size)
{
    const float* x    = (const float*)d_in[0];
    const float* h0   = (const float*)d_in[1];
    const float* c0   = (const float*)d_in[2];
    const float* ln_g = (const float*)d_in[3];
    const float* ln_b = (const float*)d_in[4];
    const float* Wq   = (const float*)d_in[5];
    const float* Wkm  = (const float*)d_in[6];
    const float* Wv   = (const float*)d_in[7];
    const float* Ww   = (const float*)d_in[8];
    const float* Wa   = (const float*)d_in[9];
    const float* cw   = (const float*)d_in[10];
    const float* cb   = (const float*)d_in[11];
    const float* fus_w = (const float*)d_in[12];
    const float* fus_b = (const float*)d_in[13];
    const float* rs_w  = (const float*)d_in[14];
    const float* rs_b  = (const float*)d_in[15];
    const float* W_ih  = (const float*)d_in[16];
    const float* W_hh  = (const float*)d_in[17];
    const float* b_ih  = (const float*)d_in[18];
    const float* b_hh  = (const float*)d_in[19];
    const float* p1_w  = (const float*)d_in[20];
    const float* p1_b  = (const float*)d_in[21];
    const float* p2_w  = (const float*)d_in[22];
    const float* p2_b  = (const float*)d_in[23];
    const float* p3_w  = (const float*)d_in[24];
    const float* p3_b  = (const float*)d_in[25];
    float* out = (float*)d_out;

    void* sp = nullptr;
    cudaGetSymbolAddress(&sp, d_scratch);
    float* S = (float*)sp;
    unsigned* U = (unsigned*)sp;
    float* xrows = S + O_XROWS;
    float* lns   = S + O_LNS;
    float* qkv   = S + O_QKV;
    unsigned* QKH = U + O_QKH;  unsigned* QKL = U + O_QKL;
    float* rbuf  = S + O_R;
    unsigned* VH = U + O_VH;    unsigned* VL = U + O_VL;
    unsigned* YH = U + O_YH;    unsigned* YL = U + O_YL;
    float* state = S + O_STATE;
    float* fusb  = S + O_FUS;
    float* rnnb  = S + O_RNN;
    float* gates = S + O_GATES;
    float* p1b   = S + O_P1;
    float* p2bf  = S + O_P2;
    float* gbuf  = S + O_G;
    float* pmbuf = S + O_PM;
    float* wT    = S + O_WT;
    float* Wqkv  = S + O_WQKV;
    float* Wc    = S + O_WC;
    float* WcT   = S + O_WCT;
    float* WaT   = S + O_WAT;
    float* p2n   = S + O_P2N;
    float* p2bp  = S + O_P2B;
    unsigned* WQKVH = U + O_WQKVH; unsigned* WQKVL = U + O_WQKVL;
    unsigned* WCTH  = U + O_WCTH;  unsigned* WCTL  = U + O_WCTL;
    unsigned* WATH  = U + O_WATH;  unsigned* WATL  = U + O_WATL;
    unsigned* WTH   = U + O_WTH;   unsigned* WTL   = U + O_WTL;
    unsigned* FUSH  = U + O_FUSH;  unsigned* FUSL  = U + O_FUSL;
    unsigned* RSH   = U + O_RSH;   unsigned* RSL   = U + O_RSL;
    unsigned* WIHH  = U + O_WIHH;  unsigned* WIHL  = U + O_WIHL;
    unsigned* WHHH  = U + O_WHHH;  unsigned* WHHL  = U + O_WHHL;
    unsigned* P1H   = U + O_P1H;   unsigned* P1L   = U + O_P1L;
    unsigned* P2H   = U + O_P2H;   unsigned* P2L   = U + O_P2L;

    cudaFuncSetAttribute(flash_k, cudaFuncAttributeMaxDynamicSharedMemorySize, FLASH_SMEM);

    auto wsplit = [](const float* src, unsigned* H, unsigned* L, long long nwords) {
        wsplit_k<<<(int)((nwords + 255)/256), 256>>>(src, H, L, nwords);
    };

    // ---- prep ----
    xtrans_k<<<dim3(4,16,64), 256>>>(x, xrows);
    wtrans_k<<<(int)((8LL*9*128*128 + 255)/256), 256>>>(cw, wT);
    qkvpack_k<<<(int)((8LL*768*128 + 255)/256), 256>>>(Wq, Wkm, Wv, Wqkv);
    waT_k<<<(int)((8LL*128*256 + 255)/256), 256>>>(Wa, WaT);
    p2pad_k<<<128, 256>>>(p2_w, p2n);
    biaspad_k<<<1, 128>>>(p2_b, p2bp);
    wsplit(Wqkv, WQKVH, WQKVL, 8LL*768*64);
    wsplit(WaT, WATH, WATL, 8LL*128*128);
    wsplit(wT, WTH, WTL, 8LL*9*128*64);
    wsplit(fus_w, FUSH, FUSL, 256LL*512);
    wsplit(rs_w, RSH, RSL, 256LL*640);
    wsplit(W_ih, WIHH, WIHL, 1024LL*128);
    wsplit(W_hh, WHHH, WHHL, 1024LL*128);
    wsplit(p1_w, P1H, P1L, 256LL*768);
    wsplit(p2n, P2H, P2L, 128LL*128);
    // Wc[l] = Ww[l] @ WaT_top (B planes, batched over 8 layers)
    gemm_tc<false,false,false><<<dim3(4,1,8), 256>>>(
        Ww, 128, 65536,  WATH, WATL, 128, 16384,
        Wc, 128, 65536, nullptr, 128);
    wcT_k<<<(int)((8LL*128*512 + 255)/256), 256>>>(Wc, WcT);
    wsplit(WcT, WCTH, WCTL, 8LL*128*256);

    static const int DIL[8] = {1,1,1,1,2,2,4,4};
    for (int l = 0; l < 8; l++) {
        const float* inrows = (l == 0) ? xrows : (state + 512 + (l-1)*128);
        int lda = (l == 0) ? 128 : 1536;
        lnstat_k<<<BK/8, 256>>>(inrows, lda, lns);
        // qkv = LN(inrows) @ Wqkv[l]; Q/K emitted as split planes, V as fp32
        gemm_tc<false,true,true><<<dim3(256,6,1), 256>>>(
            inrows, lda, 0,  WQKVH + (long long)l*49152, WQKVL + (long long)l*49152, 64, 0,
            qkv, 768, 0, nullptr, 128,
            lns, ln_g + l*128, ln_b + l*128, QKH, QKL);
        vtrans_k<<<dim3(4,16,256), 256>>>(qkv, VH, VL);
        flash_k<<<dim3(4,4,64), 256, FLASH_SMEM>>>(QKH, QKL, VH, VL, rbuf);
        // y = r @ Wc[l] + inrows @ Wa_bot[l]  -> split planes
        gemm2_tc<<<dim3(256,1,1), 256>>>(
            rbuf, 512,  WCTH + (long long)l*32768, WCTL + (long long)l*32768, 256, 512,
            inrows, lda,  WATH + (long long)l*16384 + 64, WATL + (long long)l*16384 + 64, 128, 128,
            nullptr, 0, nullptr, nullptr, YH, YL);
        conv_tc<<<256, 256>>>(YH, YL, WTH + (long long)l*73728, WTL + (long long)l*73728,
                              cb + l*128, state, l, DIL[l]);
    }

    gemm_tc<false,false,false><<<dim3(256,2,1), 256>>>(
        state + 512, 1536, 0,  FUSH, FUSL, 512, 0,
        fusb, 256, 0, nullptr, 1024);
    maxg1_k<<<dim3(64,8), 256>>>(fusb, pmbuf);
    maxg2_k<<<64, 256>>>(pmbuf, fus_b, gbuf);
    gfill_k<<<BK, 256>>>(gbuf, state);
    gemm_tc<false,false,false><<<dim3(256,2,1), 256>>>(
        state + 256, 1536, 0,  RSH, RSL, 640, 0,
        rnnb, 256, 0, rs_b, 1280);
    gemm2_tc<<<dim3(256,8,1), 256>>>(
        rnnb, 256,  WIHH, WIHL, 128, 256,
        h0, 256,  WHHH, WHHL, 128, 256,
        gates, 1024, b_ih, b_hh, nullptr, nullptr);
    float* ho = out + 65536;
    float* co = out + 65536 + (long long)BK*256;
    lstm_k<<<BK, 256>>>(gates, c0, state, ho, co);
    gemm_tc<true,false,false><<<dim3(256,2,1), 256>>>(
        state, 1536, 0,  P1H, P1L, 768, 0,
        p1b, 256, 0, p1_b, 1536);
    gemm_tc<true,false,false><<<dim3(256,1,1), 256>>>(
        p1b, 256, 0,  P2H, P2L, 128, 0,
        p2bf, 128, 0, p2bp, 256);
    p3_k<<<BK/8, 256>>>(p2bf, p3_w, p3_b, out);
}

// round 12
// speedup vs baseline: 3.1391x; 1.1100x over previous
#include <cuda_runtime.h>

#define BK 32768
#define Kk 512

// ---------------- scratch offsets (4-byte units) ----------------
constexpr long long O_XROWS = 0,                      SZ_XROWS = (long long)BK*128;
constexpr long long O_LNS   = O_XROWS + SZ_XROWS,     SZ_LNS   = (long long)BK*2;
constexpr long long O_QKV   = O_LNS + SZ_LNS,         SZ_QKV   = (long long)BK*768;
constexpr long long O_QKH   = O_QKV + SZ_QKV,         SZ_QKH   = (long long)BK*128;
constexpr long long O_QKL   = O_QKH + SZ_QKH,         SZ_QKL   = (long long)BK*128;
constexpr long long O_R     = O_QKL + SZ_QKL,         SZ_R     = (long long)BK*512;
constexpr long long O_VH    = O_R + SZ_R,             SZ_VH    = (long long)BK*256;
constexpr long long O_VL    = O_VH + SZ_VH,           SZ_VL    = (long long)BK*256;
constexpr long long O_YH    = O_VL + SZ_VL,           SZ_YH    = (long long)BK*64;
constexpr long long O_YL    = O_YH + SZ_YH,           SZ_YL    = (long long)BK*64;
constexpr long long O_STATE = O_YL + SZ_YL,           SZ_STATE = (long long)BK*1536;
constexpr long long O_FUS   = O_STATE + SZ_STATE,     SZ_FUS   = (long long)BK*256;
constexpr long long O_RNN   = O_FUS + SZ_FUS,         SZ_RNN   = (long long)BK*256;
constexpr long long O_GATES = O_RNN + SZ_RNN,         SZ_GATES = (long long)BK*1024;
constexpr long long O_P1    = O_GATES + SZ_GATES,     SZ_P1    = (long long)BK*256;
constexpr long long O_P2    = O_P1 + SZ_P1,           SZ_P2    = (long long)BK*128;
constexpr long long O_G     = O_P2 + SZ_P2,           SZ_G     = 64*256;
constexpr long long O_PM    = O_G + SZ_G,             SZ_PM    = 64LL*8*256;
constexpr long long O_WT    = O_PM + SZ_PM,           SZ_WT    = 8LL*9*128*128;
constexpr long long O_WQKV  = O_WT + SZ_WT,           SZ_WQKV  = 8LL*768*128;
constexpr long long O_WC    = O_WQKV + SZ_WQKV,       SZ_WC    = 8LL*512*128;
constexpr long long O_WCT   = O_WC + SZ_WC,           SZ_WCT   = 8LL*128*512;
constexpr long long O_WAT   = O_WCT + SZ_WCT,         SZ_WAT   = 8LL*128*256;
constexpr long long O_P2N   = O_WAT + SZ_WAT,         SZ_P2N   = 128LL*256;
constexpr long long O_P2B   = O_P2N + SZ_P2N,         SZ_P2B   = 128;
constexpr long long O_WQKVH = O_P2B + SZ_P2B,         SZ_WQKVH = 8LL*768*64;
constexpr long long O_WQKVL = O_WQKVH + SZ_WQKVH;
constexpr long long O_WCTH  = O_WQKVL + SZ_WQKVH,     SZ_WCTH  = 8LL*128*256;
constexpr long long O_WCTL  = O_WCTH + SZ_WCTH;
constexpr long long O_WATH  = O_WCTL + SZ_WCTH,       SZ_WATH  = 8LL*128*128;
constexpr long long O_WATL  = O_WATH + SZ_WATH;
constexpr long long O_WTH   = O_WATL + SZ_WATH,       SZ_WTH   = 8LL*9*128*64;
constexpr long long O_WTL   = O_WTH + SZ_WTH;
constexpr long long O_FUSH  = O_WTL + SZ_WTH,         SZ_FUSH  = 256LL*512;
constexpr long long O_FUSL  = O_FUSH + SZ_FUSH;
constexpr long long O_RSH   = O_FUSL + SZ_FUSH,       SZ_RSH   = 256LL*640;
constexpr long long O_RSL   = O_RSH + SZ_RSH;
constexpr long long O_WIHH  = O_RSL + SZ_RSH,         SZ_WIHH  = 1024LL*128;
constexpr long long O_WIHL  = O_WIHH + SZ_WIHH;
constexpr long long O_WHHH  = O_WIHL + SZ_WIHH,       SZ_WHHH  = 1024LL*128;
constexpr long long O_WHHL  = O_WHHH + SZ_WHHH;
constexpr long long O_P1H   = O_WHHL + SZ_WHHH,       SZ_P1H   = 256LL*768;
constexpr long long O_P1L   = O_P1H + SZ_P1H;
constexpr long long O_P2H   = O_P1L + SZ_P1H,         SZ_P2H   = 128LL*128;
constexpr long long O_P2L   = O_P2H + SZ_P2H;
constexpr long long SCRATCH_TOTAL = O_P2L + SZ_P2H;

__device__ __align__(16) float d_scratch[SCRATCH_TOTAL];

// ---------------- bf16 split helpers ----------------
__device__ __forceinline__ int swz(int row, int kp) {
    return row*8 + (kp ^ (((row >> 2) & 1) << 2));
}
__device__ __forceinline__ void split2(float x, float y, unsigned& h, unsigned& l) {
    asm("cvt.rn.bf16x2.f32 %0, %1, %2;" : "=r"(h) : "f"(y), "f"(x));
    float hx = __uint_as_float(h << 16);
    float hy = __uint_as_float(h & 0xffff0000u);
    asm("cvt.rn.bf16x2.f32 %0, %1, %2;" : "=r"(l) : "f"(y - hy), "f"(x - hx));
}
__device__ __forceinline__ void mma16(float* c, const unsigned* a, const unsigned* b) {
    asm volatile(
        "mma.sync.aligned.m16n8k16.row.col.f32.bf16.bf16.f32 "
        "{%0,%1,%2,%3},{%4,%5,%6,%7},{%8,%9},{%0,%1,%2,%3};"
        : "+f"(c[0]), "+f"(c[1]), "+f"(c[2]), "+f"(c[3])
        : "r"(a[0]), "r"(a[1]), "r"(a[2]), "r"(a[3]), "r"(b[0]), "r"(b[1]));
}
// ldmatrix x4
__device__ __forceinline__ void ldm4(unsigned* r, unsigned addr) {
    asm volatile("ldmatrix.sync.aligned.m8n8.x4.shared.b16 {%0,%1,%2,%3}, [%4];"
        : "=r"(r[0]), "=r"(r[1]), "=r"(r[2]), "=r"(r[3]) : "r"(addr));
}
// shared address of 16B group (row, kw in {0,4})
__device__ __forceinline__ unsigned saddr(const unsigned* p, int row, int kw) {
    const int x = ((row >> 2) & 1) << 2;
    return (unsigned)__cvta_generic_to_shared(p + row*8 + (kw ^ x));
}

// stage 8 fp32 values (split on the fly)
__device__ __forceinline__ void stage8(unsigned* H, unsigned* L, int row, int half,
                                       float4 v0, float4 v1) {
    unsigned h0,l0,h1,l1,h2,l2,h3,l3;
    split2(v0.x, v0.y, h0, l0); split2(v0.z, v0.w, h1, l1);
    split2(v1.x, v1.y, h2, l2); split2(v1.z, v1.w, h3, l3);
    const int kpb = (half*4) ^ (((row >> 2) & 1) << 2);
    *(uint4*)&H[row*8 + kpb] = make_uint4(h0, h1, h2, h3);
    *(uint4*)&L[row*8 + kpb] = make_uint4(l0, l1, l2, l3);
}
// stage 8 pre-split words (no math)
__device__ __forceinline__ void stage8w(unsigned* H, unsigned* L, int row, int half,
                                        uint4 hv, uint4 lv) {
    const int kpb = (half*4) ^ (((row >> 2) & 1) << 2);
    *(uint4*)&H[row*8 + kpb] = hv;
    *(uint4*)&L[row*8 + kpb] = lv;
}

// tile_compute with ldmatrix fragment loads
__device__ __forceinline__ void tile_compute(
    const unsigned* __restrict__ Ah, const unsigned* __restrict__ Al,
    const unsigned* __restrict__ Bh, const unsigned* __restrict__ Bl,
    float c[4][4][4], int lane, int wm, int wn)
{
    const int sub = lane >> 3, e = lane & 7;
    const int arOff = (sub & 1)*8 + e, akw = (sub >> 1)*4;
    const int brOff = (sub >> 1)*8 + e, bkw = (sub & 1)*4;
    unsigned ah[4][4], al[4][4], bh[4][2], bl[4][2];
#pragma unroll
    for (int mt = 0; mt < 4; mt++) {
        const int row = wm + mt*16 + arOff;
        ldm4(ah[mt], saddr(Ah, row, akw));
        ldm4(al[mt], saddr(Al, row, akw));
    }
#pragma unroll
    for (int p = 0; p < 2; p++) {
        const int row = wn + p*16 + brOff;
        unsigned t4[4];
        ldm4(t4, saddr(Bh, row, bkw));
        bh[2*p][0] = t4[0]; bh[2*p][1] = t4[1]; bh[2*p+1][0] = t4[2]; bh[2*p+1][1] = t4[3];
        ldm4(t4, saddr(Bl, row, bkw));
        bl[2*p][0] = t4[0]; bl[2*p][1] = t4[1]; bl[2*p+1][0] = t4[2]; bl[2*p+1][1] = t4[3];
    }
#pragma unroll
    for (int mt = 0; mt < 4; mt++)
#pragma unroll
        for (int nt = 0; nt < 4; nt++) {
            mma16(c[mt][nt], ah[mt], bh[nt]);
            mma16(c[mt][nt], ah[mt], bl[nt]);
            mma16(c[mt][nt], al[mt], bh[nt]);
        }
}

// ---------------- tensor-core GEMM (bf16x3), B pre-split planes ----------------
template<bool RELU, bool LNA, bool QKP>
__global__ void __launch_bounds__(256) gemm_tc(
    const float* __restrict__ A, int lda, long long sA,
    const unsigned* __restrict__ BH, const unsigned* __restrict__ BL, int ldbw, long long sBw,
    float* __restrict__ C, int ldc, long long sC,
    const float* __restrict__ bias, int Kd,
    const float* __restrict__ lnstat = nullptr,
    const float* __restrict__ lg = nullptr,
    const float* __restrict__ lb = nullptr,
    unsigned* __restrict__ qkH = nullptr, unsigned* __restrict__ qkL = nullptr)
{
    const int bz = blockIdx.z;
    A  += (long long)bz*sA;
    BH += (long long)bz*sBw;  BL += (long long)bz*sBw;
    C  += (long long)bz*sC;
    const int m0 = blockIdx.x*128, n0 = blockIdx.y*128;
    __shared__ __align__(16) unsigned Ah[2][1024], Al[2][1024];
    __shared__ __align__(16) unsigned Bh[2][1024], Bl[2][1024];
    const int tid = threadIdx.x;
    const int lane = tid & 31, warp = tid >> 5;
    const int qg = lane >> 2, rg = lane & 3;
    const int wm = (warp & 1)*64, wn = (warp >> 1)*32;

    float c[4][4][4];
#pragma unroll
    for (int i = 0; i < 4; i++)
#pragma unroll
        for (int j = 0; j < 4; j++)
#pragma unroll
            for (int k = 0; k < 4; k++) c[i][j][k] = 0.f;

    const int srow = tid >> 1, half = tid & 1;
    const float* Ap = A + (long long)(m0 + srow)*lda + half*8;
    const long long bW = (long long)(n0 + srow)*ldbw + half*4;
    const int nc = Kd >> 4;

    float mu = 0.f, inv = 1.f;
    if (LNA) {
        mu  = lnstat[(long long)(m0 + srow)*2];
        inv = lnstat[(long long)(m0 + srow)*2 + 1];
    }

    float4 ra0, ra1; uint4 rbh, rbl;
    ra0 = *(const float4*)Ap;  ra1 = *(const float4*)(Ap + 4);
    rbh = *(const uint4*)&BH[bW];  rbl = *(const uint4*)&BL[bW];
    if (LNA) {
        float4 g0 = *(const float4*)(lg + half*8), g1 = *(const float4*)(lg + half*8 + 4);
        float4 b0 = *(const float4*)(lb + half*8), b1 = *(const float4*)(lb + half*8 + 4);
        ra0.x = (ra0.x - mu)*inv*g0.x + b0.x; ra0.y = (ra0.y - mu)*inv*g0.y + b0.y;
        ra0.z = (ra0.z - mu)*inv*g0.z + b0.z; ra0.w = (ra0.w - mu)*inv*g0.w + b0.w;
        ra1.x = (ra1.x - mu)*inv*g1.x + b1.x; ra1.y = (ra1.y - mu)*inv*g1.y + b1.y;
        ra1.z = (ra1.z - mu)*inv*g1.z + b1.z; ra1.w = (ra1.w - mu)*inv*g1.w + b1.w;
    }
    stage8(Ah[0], Al[0], srow, half, ra0, ra1);
    stage8w(Bh[0], Bl[0], srow, half, rbh, rbl);
    __syncthreads();

    for (int ch = 0; ch < nc; ch++) {
        const int s = ch & 1;
        if (ch + 1 < nc) {
            const int kb = (ch + 1) << 4;
            ra0 = *(const float4*)(Ap + kb); ra1 = *(const float4*)(Ap + kb + 4);
            rbh = *(const uint4*)&BH[bW + (ch + 1)*8];
            rbl = *(const uint4*)&BL[bW + (ch + 1)*8];
            if (LNA) {
                float4 g0 = *(const float4*)(lg + kb + half*8), g1 = *(const float4*)(lg + kb + half*8 + 4);
                float4 b0 = *(const float4*)(lb + kb + half*8), b1 = *(const float4*)(lb + kb + half*8 + 4);
                ra0.x = (ra0.x - mu)*inv*g0.x + b0.x; ra0.y = (ra0.y - mu)*inv*g0.y + b0.y;
                ra0.z = (ra0.z - mu)*inv*g0.z + b0.z; ra0.w = (ra0.w - mu)*inv*g0.w + b0.w;
                ra1.x = (ra1.x - mu)*inv*g1.x + b1.x; ra1.y = (ra1.y - mu)*inv*g1.y + b1.y;
                ra1.z = (ra1.z - mu)*inv*g1.z + b1.z; ra1.w = (ra1.w - mu)*inv*g1.w + b1.w;
            }
        }
        tile_compute(Ah[s], Al[s], Bh[s], Bl[s], c, lane, wm, wn);
        if (ch + 1 < nc) {
            const int d = s ^ 1;
            stage8(Ah[d], Al[d], srow, half, ra0, ra1);
            stage8w(Bh[d], Bl[d], srow, half, rbh, rbl);
        }
        __syncthreads();
    }

    const bool planeOut = QKP && (n0 < 256);
#pragma unroll
    for (int mt = 0; mt < 4; mt++) {
#pragma unroll
        for (int rh = 0; rh < 2; rh++) {
            const int m = m0 + wm + mt*16 + qg + rh*8;
#pragma unroll
            for (int nt = 0; nt < 4; nt++) {
                const int n = n0 + wn + nt*8 + rg*2;
                float vx = c[mt][nt][rh*2], vy = c[mt][nt][rh*2 + 1];
                if (bias) { float2 bb = *(const float2*)(bias + n); vx += bb.x; vy += bb.y; }
                if (RELU) { vx = fmaxf(vx, 0.f); vy = fmaxf(vy, 0.f); }
                if (planeOut) {
                    unsigned hw, lw; split2(vx, vy, hw, lw);
                    const long long w = (long long)m*128 + (n >> 1);
                    qkH[w] = hw; qkL[w] = lw;
                } else {
                    *(float2*)(C + (long long)m*ldc + n) = make_float2(vx, vy);
                }
            }
        }
    }
}

// ---------------- dual-source GEMM ----------------
__global__ void __launch_bounds__(256) gemm2_tc(
    const float* __restrict__ A1, int lda1,
    const unsigned* __restrict__ B1H, const unsigned* __restrict__ B1L, int ldb1w, int Kd1,
    const float* __restrict__ A2, int lda2,
    const unsigned* __restrict__ B2H, const unsigned* __restrict__ B2L, int ldb2w, int Kd2,
    float* __restrict__ C, int ldc,
    const float* __restrict__ bias1, const float* __restrict__ bias2,
    unsigned* __restrict__ YH, unsigned* __restrict__ YL)
{
    const int m0 = blockIdx.x*128, n0 = blockIdx.y*128;
    __shared__ __align__(16) unsigned Ah[2][1024], Al[2][1024];
    __shared__ __align__(16) unsigned Bh[2][1024], Bl[2][1024];
    const int tid = threadIdx.x;
    const int lane = tid & 31, warp = tid >> 5;
    const int qg = lane >> 2, rg = lane & 3;
    const int wm = (warp & 1)*64, wn = (warp >> 1)*32;

    float c[4][4][4];
#pragma unroll
    for (int i = 0; i < 4; i++)
#pragma unroll
        for (int j = 0; j < 4; j++)
#pragma unroll
            for (int k = 0; k < 4; k++) c[i][j][k] = 0.f;

    const int srow = tid >> 1, half = tid & 1;

    for (int pass = 0; pass < 2; pass++) {
        const float* Ap = (pass == 0 ? A1 : A2) + (long long)(m0 + srow)*(pass == 0 ? lda1 : lda2) + half*8;
        const unsigned* BHp = (pass == 0 ? B1H : B2H);
        const unsigned* BLp = (pass == 0 ? B1L : B2L);
        const int ldw = (pass == 0 ? ldb1w : ldb2w);
        const long long bW = (long long)(n0 + srow)*ldw + half*4;
        const int nc = (pass == 0 ? Kd1 : Kd2) >> 4;

        float4 ra0 = *(const float4*)Ap, ra1 = *(const float4*)(Ap + 4);
        uint4 rbh = *(const uint4*)&BHp[bW], rbl = *(const uint4*)&BLp[bW];
        stage8(Ah[0], Al[0], srow, half, ra0, ra1);
        stage8w(Bh[0], Bl[0], srow, half, rbh, rbl);
        __syncthreads();

        for (int ch = 0; ch < nc; ch++) {
            const int s = ch & 1;
            if (ch + 1 < nc) {
                const int kb = (ch + 1) << 4;
                ra0 = *(const float4*)(Ap + kb); ra1 = *(const float4*)(Ap + kb + 4);
                rbh = *(const uint4*)&BHp[bW + (ch + 1)*8];
                rbl = *(const uint4*)&BLp[bW + (ch + 1)*8];
            }
            tile_compute(Ah[s], Al[s], Bh[s], Bl[s], c, lane, wm, wn);
            if (ch + 1 < nc) {
                const int d = s ^ 1;
                stage8(Ah[d], Al[d], srow, half, ra0, ra1);
                stage8w(Bh[d], Bl[d], srow, half, rbh, rbl);
            }
            __syncthreads();
        }
    }

#pragma unroll
    for (int mt = 0; mt < 4; mt++) {
#pragma unroll
        for (int rh = 0; rh < 2; rh++) {
            const int m = m0 + wm + mt*16 + qg + rh*8;
#pragma unroll
            for (int nt = 0; nt < 4; nt++) {
                const int n = n0 + wn + nt*8 + rg*2;
                float vx = c[mt][nt][rh*2], vy = c[mt][nt][rh*2 + 1];
                if (bias1) { float2 bb = *(const float2*)(bias1 + n); vx += bb.x; vy += bb.y; }
                if (bias2) { float2 bb = *(const float2*)(bias2 + n); vx += bb.x; vy += bb.y; }
                if (YH) {
                    unsigned hw, lw; split2(vx, vy, hw, lw);
                    const long long w = (long long)m*64 + (n >> 1);
                    YH[w] = hw; YL[w] = lw;
                } else {
                    *(float2*)(C + (long long)m*ldc + n) = make_float2(vx, vy);
                }
            }
        }
    }
}

// ---------------- FA2 flash: ldmatrix fragments ----------------
constexpr int FLASH_SMEM = 98304;
__global__ void __launch_bounds__(256) flash_k(
    const unsigned* __restrict__ QKH, const unsigned* __restrict__ QKL,
    const unsigned* __restrict__ VH, const unsigned* __restrict__ VL,
    float* __restrict__ r)
{
    extern __shared__ __align__(16) unsigned sm_[];
    unsigned* Qh = sm_;
    unsigned* Ql = Qh + 2048;
    unsigned* Kh = Ql + 2048;
    unsigned* Kl = Kh + 2048;
    unsigned* Vh = Kl + 2048;
    unsigned* Vl = Vh + 8192;

    const int b = blockIdx.z, h = blockIdx.y, q0 = blockIdx.x*128;
    const int tid = threadIdx.x, lane = tid & 31, warp = tid >> 5;
    const int qg = lane >> 2, rg = lane & 3;
    const int wr = warp*16;
    const int srow = tid >> 1, half = tid & 1;
    const int bh = b*4 + h;
    const float sc = 0.17677669529663687f;

    const int sub = lane >> 3, e = lane & 7;
    const int arOff = (sub & 1)*8 + e, akw = (sub >> 1)*4;
    const int brOff = (sub >> 1)*8 + e, bkw = (sub & 1)*4;

    {   // Q: 128 rows x 32 ch = 16 words
        const long long qb = (long long)(b*Kk + q0 + srow)*128 + h*16 + half*4;
        stage8w(Qh, Ql, srow, half, *(const uint4*)&QKH[qb], *(const uint4*)&QKL[qb]);
        stage8w(Qh + 1024, Ql + 1024, srow, half, *(const uint4*)&QKH[qb + 8], *(const uint4*)&QKL[qb + 8]);
    }

    float co[16][4];
#pragma unroll
    for (int i = 0; i < 16; i++)
#pragma unroll
        for (int k = 0; k < 4; k++) co[i][k] = 0.f;
    float rM0 = -3.0e38f, rM1 = -3.0e38f, rL0 = 0.f, rL1 = 0.f;

    for (int kc = 0; kc < 4; kc++) {
        if (kc) __syncthreads();
        {   // K chunk
            const long long kb = (long long)(b*Kk + kc*128 + srow)*128 + 64 + h*16 + half*4;
            stage8w(Kh, Kl, srow, half, *(const uint4*)&QKH[kb], *(const uint4*)&QKL[kb]);
            stage8w(Kh + 1024, Kl + 1024, srow, half, *(const uint4*)&QKH[kb + 8], *(const uint4*)&QKL[kb + 8]);
        }
        {   // V chunk
            const long long vb = ((long long)bh << 15) + (long long)srow*256 + kc*64 + half*4;
#pragma unroll
            for (int j = 0; j < 8; j++)
                stage8w(Vh + j*1024, Vl + j*1024, srow, half,
                        *(const uint4*)&VH[vb + j*8], *(const uint4*)&VL[vb + j*8]);
        }
        __syncthreads();

        float cs[16][4];
#pragma unroll
        for (int i = 0; i < 16; i++)
#pragma unroll
            for (int k = 0; k < 4; k++) cs[i][k] = 0.f;
#pragma unroll
        for (int sb2 = 0; sb2 < 2; sb2++) {
            unsigned ah[4], al[4];
            ldm4(ah, saddr(Qh + sb2*1024, wr + arOff, akw));
            ldm4(al, saddr(Ql + sb2*1024, wr + arOff, akw));
#pragma unroll
            for (int p = 0; p < 8; p++) {
                unsigned th[4], tl[4];
                ldm4(th, saddr(Kh + sb2*1024, p*16 + brOff, bkw));
                ldm4(tl, saddr(Kl + sb2*1024, p*16 + brOff, bkw));
                mma16(cs[2*p],   ah, &th[0]);
                mma16(cs[2*p],   ah, &tl[0]);
                mma16(cs[2*p],   al, &th[0]);
                mma16(cs[2*p+1], ah, &th[2]);
                mma16(cs[2*p+1], ah, &tl[2]);
                mma16(cs[2*p+1], al, &th[2]);
            }
        }

        float m0 = -3.0e38f, m1 = -3.0e38f;
#pragma unroll
        for (int nt = 0; nt < 16; nt++) {
            m0 = fmaxf(m0, fmaxf(cs[nt][0], cs[nt][1]));
            m1 = fmaxf(m1, fmaxf(cs[nt][2], cs[nt][3]));
        }
        m0 *= sc; m1 *= sc;
        m0 = fmaxf(m0, __shfl_xor_sync(0xffffffffu, m0, 1));
        m0 = fmaxf(m0, __shfl_xor_sync(0xffffffffu, m0, 2));
        m1 = fmaxf(m1, __shfl_xor_sync(0xffffffffu, m1, 1));
        m1 = fmaxf(m1, __shfl_xor_sync(0xffffffffu, m1, 2));
        const float nm0 = fmaxf(rM0, m0), nm1 = fmaxf(rM1, m1);
        const float a0 = __expf(rM0 - nm0), a1 = __expf(rM1 - nm1);
        float s0 = 0.f, s1 = 0.f;
        unsigned pfh[8][4], pfl[8][4];
#pragma unroll
        for (int nt = 0; nt < 16; nt++) {
            float p0 = __expf(cs[nt][0]*sc - nm0), p1 = __expf(cs[nt][1]*sc - nm0);
            float p2 = __expf(cs[nt][2]*sc - nm1), p3 = __expf(cs[nt][3]*sc - nm1);
            s0 += p0 + p1; s1 += p2 + p3;
            const int j = nt >> 1, o = (nt & 1)*2;
            split2(p0, p1, pfh[j][o],   pfl[j][o]);
            split2(p2, p3, pfh[j][o+1], pfl[j][o+1]);
        }
        s0 += __shfl_xor_sync(0xffffffffu, s0, 1);
        s0 += __shfl_xor_sync(0xffffffffu, s0, 2);
        s1 += __shfl_xor_sync(0xffffffffu, s1, 1);
        s1 += __shfl_xor_sync(0xffffffffu, s1, 2);
        rL0 = rL0*a0 + s0; rL1 = rL1*a1 + s1;
        rM0 = nm0; rM1 = nm1;
#pragma unroll
        for (int nt = 0; nt < 16; nt++) {
            co[nt][0] *= a0; co[nt][1] *= a0;
            co[nt][2] *= a1; co[nt][3] *= a1;
        }
#pragma unroll
        for (int j = 0; j < 8; j++) {
#pragma unroll
            for (int p = 0; p < 8; p++) {
                unsigned th[4], tl[4];
                ldm4(th, saddr(Vh + j*1024, p*16 + brOff, bkw));
                ldm4(tl, saddr(Vl + j*1024, p*16 + brOff, bkw));
                mma16(co[2*p],   pfh[j], &th[0]);
                mma16(co[2*p],   pfh[j], &tl[0]);
                mma16(co[2*p],   pfl[j], &th[0]);
                mma16(co[2*p+1], pfh[j], &th[2]);
                mma16(co[2*p+1], pfh[j], &tl[2]);
                mma16(co[2*p+1], pfl[j], &th[2]);
            }
        }
    }

    const float inv0 = 1.f / rL0, inv1 = 1.f / rL1;
    float* rp0 = r + ((long long)(b*Kk + q0 + wr + qg))*512 + h*128;
    float* rp1 = r + ((long long)(b*Kk + q0 + wr + qg + 8))*512 + h*128;
#pragma unroll
    for (int nt = 0; nt < 16; nt++) {
        const int col = nt*8 + rg*2;
        *(float2*)(rp0 + col) = make_float2(co[nt][0]*inv0, co[nt][1]*inv0);
        *(float2*)(rp1 + col) = make_float2(co[nt][2]*inv1, co[nt][3]*inv1);
    }
}

// ---------------- conv ----------------
__global__ void __launch_bounds__(256) conv_tc(
    const unsigned* __restrict__ YH, const unsigned* __restrict__ YL,
    const unsigned* __restrict__ WH, const unsigned* __restrict__ WL,
    const float* __restrict__ cbl, float* __restrict__ state,
    int layer, int dil)
{
    const int tile = blockIdx.x;
    const int b = tile >> 2, k0 = (tile & 3) << 7;
    __shared__ __align__(16) unsigned Ah[2][1024], Al[2][1024];
    __shared__ __align__(16) unsigned Bh[2][1024], Bl[2][1024];
    const int tid = threadIdx.x;
    const int lane = tid & 31, warp = tid >> 5;
    const int qg = lane >> 2, rg = lane & 3;
    const int wm = (warp & 1)*64, wn = (warp >> 1)*32;

    float c[4][4][4];
#pragma unroll
    for (int i = 0; i < 4; i++)
#pragma unroll
        for (int j = 0; j < 4; j++)
#pragma unroll
            for (int k = 0; k < 4; k++) c[i][j][k] = 0.f;

    const int srow = tid >> 1, half = tid & 1;
    uint4 rah, ral, rbh, rbl;

    {
        const int src = b*Kk + ((k0 + srow - 4*dil + Kk) & (Kk - 1));
        const long long aw = (long long)src*64 + half*4;
        rah = *(const uint4*)&YH[aw]; ral = *(const uint4*)&YL[aw];
        const long long bw = (long long)srow*64 + half*4;
        rbh = *(const uint4*)&WH[bw]; rbl = *(const uint4*)&WL[bw];
    }
    stage8w(Ah[0], Al[0], srow, half, rah, ral);
    stage8w(Bh[0], Bl[0], srow, half, rbh, rbl);
    __syncthreads();

    for (int ch = 0; ch < 72; ch++) {
        const int s = ch & 1;
        if (ch + 1 < 72) {
            const int tn = (ch + 1) / 8, icb = (ch + 1) & 7;
            const int src = b*Kk + ((k0 + srow + (tn - 4)*dil + Kk) & (Kk - 1));
            const long long aw = (long long)src*64 + icb*8 + half*4;
            rah = *(const uint4*)&YH[aw]; ral = *(const uint4*)&YL[aw];
            const long long bw = (long long)tn*8192 + (long long)srow*64 + icb*8 + half*4;
            rbh = *(const uint4*)&WH[bw]; rbl = *(const uint4*)&WL[bw];
        }
        tile_compute(Ah[s], Al[s], Bh[s], Bl[s], c, lane, wm, wn);
        if (ch + 1 < 72) {
            const int d = s ^ 1;
            stage8w(Ah[d], Al[d], srow, half, rah, ral);
            stage8w(Bh[d], Bl[d], srow, half, rbh, rbl);
        }
        __syncthreads();
    }

#pragma unroll
    for (int mt = 0; mt < 4; mt++) {
#pragma unroll
        for (int rh = 0; rh < 2; rh++) {
            const int pos = k0 + wm + mt*16 + qg + rh*8;
            const long long row = (long long)b*Kk + pos;
#pragma unroll
            for (int nt = 0; nt < 4; nt++) {
                const int n = wn + nt*8 + rg*2;
                float vx = c[mt][nt][rh*2]   + cbl[n];
                float vy = c[mt][nt][rh*2+1] + cbl[n+1];
                vx = fmaxf(vx, 0.f); vy = fmaxf(vy, 0.f);
                const long long sidx = row*1536 + 512 + (long long)layer*128 + n;
                if (layer > 0) {
                    float2 r = *(float2*)&state[sidx - 128];
                    vx += r.x; vy += r.y;
                }
                *(float2*)&state[sidx] = make_float2(vx, vy);
            }
        }
    }
}

// ---------------- transpose x ----------------
__global__ void __launch_bounds__(256) xtrans_k(const float* __restrict__ x, float* __restrict__ xr)
{
    __shared__ float t[32][33];
    const int c0 = blockIdx.x*32, k0 = blockIdx.y*32, b = blockIdx.z;
    const int tx = threadIdx.x & 31, ty = threadIdx.x >> 5;
#pragma unroll
    for (int i = 0; i < 4; i++)
        t[ty + i*8][tx] = x[(long long)b*65536 + (long long)(c0 + ty + i*8)*Kk + k0 + tx];
    __syncthreads();
#pragma unroll
    for (int i = 0; i < 4; i++)
        xr[((long long)(b*Kk + k0 + ty + i*8))*128 + c0 + tx] = t[tx][ty + i*8];
}

// ---------------- V transpose -> split planes ----------------
__global__ void __launch_bounds__(256) vtrans_k(const float* __restrict__ qkv,
                                                unsigned* __restrict__ VH, unsigned* __restrict__ VL)
{
    __shared__ float t[32][33];
    const int c0 = blockIdx.x*32, k0 = blockIdx.y*32, bh = blockIdx.z;
    const int b = bh >> 2, h = bh & 3;
    const int tx = threadIdx.x & 31, ty = threadIdx.x >> 5;
#pragma unroll
    for (int i = 0; i < 4; i++)
        t[ty + i*8][tx] = qkv[((long long)(b*Kk + k0 + ty + i*8))*768 + 256 + h*128 + c0 + tx];
    __syncthreads();
#pragma unroll
    for (int it = 0; it < 2; it++) {
        const int idx = threadIdx.x + it*256;
        const int cl = idx >> 4, kp = idx & 15;
        unsigned hw, lw;
        split2(t[kp*2][cl], t[kp*2 + 1][cl], hw, lw);
        const long long w = ((long long)bh << 15) + (long long)(c0 + cl)*256 + (k0 >> 1) + kp;
        VH[w] = hw; VL[w] = lw;
    }
}

// ---------------- layernorm stats ----------------
__global__ void __launch_bounds__(256) lnstat_k(
    const float* __restrict__ in, int lda, float* __restrict__ stat)
{
    const int row = blockIdx.x*8 + (threadIdx.x >> 5);
    const int lane = threadIdx.x & 31;
    const float* p = in + (long long)row*lda;
    float x[4];
#pragma unroll
    for (int q = 0; q < 4; q++) x[q] = p[lane + q*32];
    float s = x[0] + x[1] + x[2] + x[3];
#pragma unroll
    for (int off = 16; off; off >>= 1) s += __shfl_xor_sync(0xffffffffu, s, off);
    const float mu = s * (1.f/128.f);
    float v = 0.f;
#pragma unroll
    for (int q = 0; q < 4; q++) { float d = x[q] - mu; v = fmaf(d, d, v); }
#pragma unroll
    for (int off = 16; off; off >>= 1) v += __shfl_xor_sync(0xffffffffu, v, off);
    if (lane == 0) {
        stat[(long long)row*2]     = mu;
        stat[(long long)row*2 + 1] = rsqrtf(v * (1.f/128.f) + 1e-6f);
    }
}

// ---------------- prep kernels ----------------
__global__ void wtrans_k(const float* __restrict__ cw, float* __restrict__ wT)
{
    long long idx = (long long)blockIdx.x*256 + threadIdx.x;
    if (idx >= 8LL*9*128*128) return;
    int i = (int)(idx & 127); long long r = idx >> 7;
    int o = (int)(r & 127); r >>= 7;
    int t = (int)(r % 9); int l = (int)(r / 9);
    wT[idx] = cw[(((long long)l*128 + o)*128 + i)*9 + t];
}

__global__ void qkvpack_k(const float* __restrict__ Wq, const float* __restrict__ Wkm,
                          const float* __restrict__ Wv, float* __restrict__ W)
{
    long long idx = (long long)blockIdx.x*256 + threadIdx.x;
    if (idx >= 8LL*768*128) return;
    int cc = (int)(idx & 127); long long r = idx >> 7;
    int j = (int)(r % 768); int l = (int)(r / 768);
    float v;
    if (j < 128)      v = Wq[((long long)l*128 + cc)*128 + j];
    else if (j < 256) v = Wkm[((long long)l*128 + cc)*128 + (j - 128)];
    else              v = Wv[((long long)l*128 + cc)*512 + (j - 256)];
    W[idx] = v;
}

__global__ void wcT_k(const float* __restrict__ Wc, float* __restrict__ WcT)
{
    long long idx = (long long)blockIdx.x*256 + threadIdx.x;
    if (idx >= 8LL*128*512) return;
    int m = (int)(idx & 511); long long r = idx >> 9;
    int n = (int)(r & 127); int l = (int)(r >> 7);
    WcT[idx] = Wc[((long long)l*512 + m)*128 + n];
}

__global__ void waT_k(const float* __restrict__ Wa, float* __restrict__ WaT)
{
    long long idx = (long long)blockIdx.x*256 + threadIdx.x;
    if (idx >= 8LL*128*256) return;
    int i = (int)(idx & 255); long long r = idx >> 8;
    int o = (int)(r & 127); int l = (int)(r >> 7);
    WaT[idx] = Wa[((long long)l*256 + i)*128 + o];
}

__global__ void p2pad_k(const float* __restrict__ w, float* __restrict__ dst)
{
    int idx = blockIdx.x*256 + threadIdx.x;
    int k = idx & 255, n = idx >> 8;
    dst[idx] = (n < 64) ? w[n*256 + k] : 0.f;
}

__global__ void biaspad_k(const float* __restrict__ b, float* __restrict__ dst)
{
    int j = threadIdx.x;
    dst[j] = (j < 64) ? b[j] : 0.f;
}

__global__ void wsplit_k(const float* __restrict__ src,
                         unsigned* __restrict__ H, unsigned* __restrict__ L, long long nwords)
{
    long long w = (long long)blockIdx.x*256 + threadIdx.x;
    if (w >= nwords) return;
    unsigned hw, lw;
    split2(src[w*2], src[w*2 + 1], hw, lw);
    H[w] = hw; L[w] = lw;
}

// ---------------- max over K (two-stage) + bias -> g ----------------
__global__ void __launch_bounds__(256) maxg1_k(
    const float* __restrict__ fus, float* __restrict__ pm)
{
    const int b = blockIdx.x, sl = blockIdx.y, f = threadIdx.x;
    const float* p = fus + (long long)b*Kk*256 + (long long)sl*64*256 + f;
    float mx = -3.0e38f;
    for (int k = 0; k < 64; k++) mx = fmaxf(mx, p[(long long)k*256]);
    pm[((long long)b*8 + sl)*256 + f] = mx;
}
__global__ void __launch_bounds__(256) maxg2_k(
    const float* __restrict__ pm, const float* __restrict__ fb, float* __restrict__ g)
{
    const int b = blockIdx.x, f = threadIdx.x;
    const float* p = pm + (long long)b*8*256 + f;
    float mx = -3.0e38f;
#pragma unroll
    for (int sl = 0; sl < 8; sl++) mx = fmaxf(mx, p[sl*256]);
    g[b*256 + f] = mx + fb[f];
}

__global__ void gfill_k(const float* __restrict__ g, float* __restrict__ state)
{
    long long idx = (long long)blockIdx.x*256 + threadIdx.x;
    int f = (int)(idx & 255); long long row = idx >> 8; int b = (int)(row >> 9);
    state[row*1536 + 256 + f] = g[b*256 + f];
}

// ---------------- LSTM elementwise ----------------
__device__ __forceinline__ float sigm(float x) { return 1.f / (1.f + __expf(-x)); }

__global__ void __launch_bounds__(256) lstm_k(
    const float* __restrict__ gates, const float* __restrict__ c0,
    float* __restrict__ state, float* __restrict__ ho, float* __restrict__ co)
{
    long long idx = (long long)blockIdx.x*256 + threadIdx.x;
    int j = (int)(idx & 255); long long row = idx >> 8;
    const float* gr = gates + row*1024;
    float gi = gr[j], gf = gr[256+j], gg = gr[512+j], go = gr[768+j];
    float c = sigm(gf)*c0[row*256 + j] + sigm(gi)*tanhf(gg);
    float h = sigm(go)*tanhf(c);
    state[row*1536 + j] = h;
    ho[idx] = h;
    co[idx] = c;
}

// ---------------- final p3 ----------------
__global__ void __launch_bounds__(256) p3_k(
    const float* __restrict__ p2, const float* __restrict__ w,
    const float* __restrict__ b3, float* __restrict__ out)
{
    const int row = blockIdx.x*8 + (threadIdx.x >> 5);
    const int lane = threadIdx.x & 31;
    const float* pr = p2 + (long long)row*128;
    float x0 = pr[lane], x1 = pr[lane + 32];
    float s0 = x0*w[lane]      + x1*w[lane + 32];
    float s1 = x0*w[64 + lane] + x1*w[96 + lane];
#pragma unroll
    for (int off = 16; off; off >>= 1) {
        s0 += __shfl_xor_sync(0xffffffffu, s0, off);
        s1 += __shfl_xor_sync(0xffffffffu, s1, off);
    }
    if (lane == 0) {
        int b = row >> 9, k = row & 511;
        out[(long long)b*1024 + k]       = s0 + b3[0];
        out[(long long)b*1024 + 512 + k] = s1 + b3[1];
    }
}

// ---------------- launch ----------------
extern "C" void kernel_launch(void* const* d_in, const int* in_sizes, int n_in,
                              void* d_out, int out_size)
{
    const float* x    = (const float*)d_in[0];
    const float* h0   = (const float*)d_in[1];
    const float* c0   = (const float*)d_in[2];
    const float* ln_g = (const float*)d_in[3];
    const float* ln_b = (const float*)d_in[4];
    const float* Wq   = (const float*)d_in[5];
    const float* Wkm  = (const float*)d_in[6];
    const float* Wv   = (const float*)d_in[7];
    const float* Ww   = (const float*)d_in[8];
    const float* Wa   = (const float*)d_in[9];
    const float* cw   = (const float*)d_in[10];
    const float* cb   = (const float*)d_in[11];
    const float* fus_w = (const float*)d_in[12];
    const float* fus_b = (const float*)d_in[13];
    const float* rs_w  = (const float*)d_in[14];
    const float* rs_b  = (const float*)d_in[15];
    const float* W_ih  = (const float*)d_in[16];
    const float* W_hh  = (const float*)d_in[17];
    const float* b_ih  = (const float*)d_in[18];
    const float* b_hh  = (const float*)d_in[19];
    const float* p1_w  = (const float*)d_in[20];
    const float* p1_b  = (const float*)d_in[21];
    const float* p2_w  = (const float*)d_in[22];
    const float* p2_b  = (const float*)d_in[23];
    const float* p3_w  = (const float*)d_in[24];
    const float* p3_b  = (const float*)d_in[25];
    float* out = (float*)d_out;

    void* sp = nullptr;
    cudaGetSymbolAddress(&sp, d_scratch);
    float* S = (float*)sp;
    unsigned* U = (unsigned*)sp;
    float* xrows = S + O_XROWS;
    float* lns   = S + O_LNS;
    float* qkv   = S + O_QKV;
    unsigned* QKH = U + O_QKH;  unsigned* QKL = U + O_QKL;
    float* rbuf  = S + O_R;
    unsigned* VH = U + O_VH;    unsigned* VL = U + O_VL;
    unsigned* YH = U + O_YH;    unsigned* YL = U + O_YL;
    float* state = S + O_STATE;
    float* fusb  = S + O_FUS;
    float* rnnb  = S + O_RNN;
    float* gates = S + O_GATES;
    float* p1b   = S + O_P1;
    float* p2bf  = S + O_P2;
    float* gbuf  = S + O_G;
    float* pmbuf = S + O_PM;
    float* wT    = S + O_WT;
    float* Wqkv  = S + O_WQKV;
    float* Wc    = S + O_WC;
    float* WcT   = S + O_WCT;
    float* WaT   = S + O_WAT;
    float* p2n   = S + O_P2N;
    float* p2bp  = S + O_P2B;
    unsigned* WQKVH = U + O_WQKVH; unsigned* WQKVL = U + O_WQKVL;
    unsigned* WCTH  = U + O_WCTH;  unsigned* WCTL  = U + O_WCTL;
    unsigned* WATH  = U + O_WATH;  unsigned* WATL  = U + O_WATL;
    unsigned* WTH   = U + O_WTH;   unsigned* WTL   = U + O_WTL;
    unsigned* FUSH  = U + O_FUSH;  unsigned* FUSL  = U + O_FUSL;
    unsigned* RSH   = U + O_RSH;   unsigned* RSL   = U + O_RSL;
    unsigned* WIHH  = U + O_WIHH;  unsigned* WIHL  = U + O_WIHL;
    unsigned* WHHH  = U + O_WHHH;  unsigned* WHHL  = U + O_WHHL;
    unsigned* P1H   = U + O_P1H;   unsigned* P1L   = U + O_P1L;
    unsigned* P2H   = U + O_P2H;   unsigned* P2L   = U + O_P2L;

    cudaFuncSetAttribute(flash_k, cudaFuncAttributeMaxDynamicSharedMemorySize, FLASH_SMEM);

    auto wsplit = [](const float* src, unsigned* H, unsigned* L, long long nwords) {
        wsplit_k<<<(int)((nwords + 255)/256), 256>>>(src, H, L, nwords);
    };

    // ---- prep ----
    xtrans_k<<<dim3(4,16,64), 256>>>(x, xrows);
    wtrans_k<<<(int)((8LL*9*128*128 + 255)/256), 256>>>(cw, wT);
    qkvpack_k<<<(int)((8LL*768*128 + 255)/256), 256>>>(Wq, Wkm, Wv, Wqkv);
    waT_k<<<(int)((8LL*128*256 + 255)/256), 256>>>(Wa, WaT);
    p2pad_k<<<128, 256>>>(p2_w, p2n);
    biaspad_k<<<1, 128>>>(p2_b, p2bp);
    wsplit(Wqkv, WQKVH, WQKVL, 8LL*768*64);
    wsplit(WaT, WATH, WATL, 8LL*128*128);
    wsplit(wT, WTH, WTL, 8LL*9*128*64);
    wsplit(fus_w, FUSH, FUSL, 256LL*512);
    wsplit(rs_w, RSH, RSL, 256LL*640);
    wsplit(W_ih, WIHH, WIHL, 1024LL*128);
    wsplit(W_hh, WHHH, WHHL, 1024LL*128);
    wsplit(p1_w, P1H, P1L, 256LL*768);
    wsplit(p2n, P2H, P2L, 128LL*128);
    gemm_tc<false,false,false><<<dim3(4,1,8), 256>>>(
        Ww, 128, 65536,  WATH, WATL, 128, 16384,
        Wc, 128, 65536, nullptr, 128);
    wcT_k<<<(int)((8LL*128*512 + 255)/256), 256>>>(Wc, WcT);
    wsplit(WcT, WCTH, WCTL, 8LL*128*256);

    static const int DIL[8] = {1,1,1,1,2,2,4,4};
    for (int l = 0; l < 8; l++) {
        const float* inrows = (l == 0) ? xrows : (state + 512 + (l-1)*128);
        int lda = (l == 0) ? 128 : 1536;
        lnstat_k<<<BK/8, 256>>>(inrows, lda, lns);
        gemm_tc<false,true,true><<<dim3(256,6,1), 256>>>(
            inrows, lda, 0,  WQKVH + (long long)l*49152, WQKVL + (long long)l*49152, 64, 0,
            qkv, 768, 0, nullptr, 128,
            lns, ln_g + l*128, ln_b + l*128, QKH, QKL);
        vtrans_k<<<dim3(4,16,256), 256>>>(qkv, VH, VL);
        flash_k<<<dim3(4,4,64), 256, FLASH_SMEM>>>(QKH, QKL, VH, VL, rbuf);
        gemm2_tc<<<dim3(256,1,1), 256>>>(
            rbuf, 512,  WCTH + (long long)l*32768, WCTL + (long long)l*32768, 256, 512,
            inrows, lda,  WATH + (long long)l*16384 + 64, WATL + (long long)l*16384 + 64, 128, 128,
            nullptr, 0, nullptr, nullptr, YH, YL);
        conv_tc<<<256, 256>>>(YH, YL, WTH + (long long)l*73728, WTL + (long long)l*73728,
                              cb + l*128, state, l, DIL[l]);
    }

    gemm_tc<false,false,false><<<dim3(256,2,1), 256>>>(
        state + 512, 1536, 0,  FUSH, FUSL, 512, 0,
        fusb, 256, 0, nullptr, 1024);
    maxg1_k<<<dim3(64,8), 256>>>(fusb, pmbuf);
    maxg2_k<<<64, 256>>>(pmbuf, fus_b, gbuf);
    gfill_k<<<BK, 256>>>(gbuf, state);
    gemm_tc<false,false,false><<<dim3(256,2,1), 256>>>(
        state + 256, 1536, 0,  RSH, RSL, 640, 0,
        rnnb, 256, 0, rs_b, 1280);
    gemm2_tc<<<dim3(256,8,1), 256>>>(
        rnnb, 256,  WIHH, WIHL, 128, 256,
        h0, 256,  WHHH, WHHL, 128, 256,
        gates, 1024, b_ih, b_hh, nullptr, nullptr);
    float* ho = out + 65536;
    float* co = out + 65536 + (long long)BK*256;
    lstm_k<<<BK, 256>>>(gates, c0, state, ho, co);
    gemm_tc<true,false,false><<<dim3(256,2,1), 256>>>(
        state, 1536, 0,  P1H, P1L, 768, 0,
        p1b, 256, 0, p1_b, 1536);
    gemm_tc<true,false,false><<<dim3(256,1,1), 256>>>(
        p1b, 256, 0,  P2H, P2L, 128, 0,
        p2bf, 128, 0, p2bp, 256);
    p3_k<<<BK/8, 256>>>(p2bf, p3_w, p3_b, out);
}